// round 6
// baseline (speedup 1.0000x reference)
#include <cuda_runtime.h>
#include <cuda_bf16.h>
#include <math.h>
#include <stdint.h>

#define B_ 2
#define T_ 2048
#define C_ 2048
#define H_ 16
#define D_ 128
#define M_ (B_*T_)   // 4096 rows

// ---------------- scratch (device globals; no allocation allowed) -------------
__device__ float g_gate[M_*H_];
__device__ __nv_bfloat16 g_xh[M_*C_],  g_xl[M_*C_];
__device__ __nv_bfloat16 g_yh[M_*C_],  g_yl[M_*C_];
__device__ __nv_bfloat16 g_qh[M_*C_],  g_ql[M_*C_];   // [b][h][t][d]
__device__ __nv_bfloat16 g_kh[M_*C_],  g_kl[M_*C_];   // [b][h][t][d]
__device__ __nv_bfloat16 g_vh[M_*C_],  g_vl[M_*C_];   // [b][h][t][d]
__device__ __nv_bfloat16 g_wqh[C_*C_], g_wql[C_*C_];
__device__ __nv_bfloat16 g_wkh[C_*C_], g_wkl[C_*C_];
__device__ __nv_bfloat16 g_wvh[C_*C_], g_wvl[C_*C_];
__device__ __nv_bfloat16 g_wph[C_*C_], g_wpl[C_*C_];

// ================= PTX helpers =================
__device__ __forceinline__ uint32_t smem_u32(const void* p) {
    uint32_t a;
    asm("{ .reg .u64 t; cvta.to.shared.u64 t, %1; cvt.u32.u64 %0, t; }" : "=r"(a) : "l"(p));
    return a;
}
__device__ __forceinline__ void cpasync16(uint32_t saddr, const void* gaddr) {
    asm volatile("cp.async.cg.shared.global [%0], [%1], 16;" :: "r"(saddr), "l"(gaddr) : "memory");
}
__device__ __forceinline__ void ldsm4(uint32_t addr, uint32_t* r) {
    asm volatile("ldmatrix.sync.aligned.m8n8.x4.shared.b16 {%0,%1,%2,%3}, [%4];"
                 : "=r"(r[0]), "=r"(r[1]), "=r"(r[2]), "=r"(r[3]) : "r"(addr));
}
__device__ __forceinline__ void ldsm4t(uint32_t addr, uint32_t* r) {
    asm volatile("ldmatrix.sync.aligned.m8n8.x4.trans.shared.b16 {%0,%1,%2,%3}, [%4];"
                 : "=r"(r[0]), "=r"(r[1]), "=r"(r[2]), "=r"(r[3]) : "r"(addr));
}
__device__ __forceinline__ float ex2f(float x) {
    float y; asm("ex2.approx.f32 %0, %1;" : "=f"(y) : "f"(x)); return y;
}
#define MMA_BF16(Cf, Af, B0, B1)                                              \
    asm volatile("mma.sync.aligned.m16n8k16.row.col.f32.bf16.bf16.f32 "        \
        "{%0,%1,%2,%3},{%4,%5,%6,%7},{%8,%9},{%0,%1,%2,%3};"                   \
        : "+f"((Cf)[0]), "+f"((Cf)[1]), "+f"((Cf)[2]), "+f"((Cf)[3])           \
        : "r"((Af)[0]), "r"((Af)[1]), "r"((Af)[2]), "r"((Af)[3]),              \
          "r"(B0), "r"(B1))

__device__ __forceinline__ void store_hl(__nv_bfloat16* ph, __nv_bfloat16* pl,
                                         float a, float b) {
    __nv_bfloat16 ha = __float2bfloat16(a), hb = __float2bfloat16(b);
    *reinterpret_cast<__nv_bfloat162*>(ph) = __nv_bfloat162(ha, hb);
    *reinterpret_cast<__nv_bfloat162*>(pl) = __nv_bfloat162(
        __float2bfloat16(a - __bfloat162float(ha)),
        __float2bfloat16(b - __bfloat162float(hb)));
}
__device__ __forceinline__ void packhl(float a, float b, uint32_t& hi, uint32_t& lo) {
    __nv_bfloat16 ha = __float2bfloat16(a), hb = __float2bfloat16(b);
    __nv_bfloat162 hv(ha, hb);
    hi = *reinterpret_cast<uint32_t*>(&hv);
    __nv_bfloat162 lv(__float2bfloat16(a - __bfloat162float(ha)),
                      __float2bfloat16(b - __bfloat162float(hb)));
    lo = *reinterpret_cast<uint32_t*>(&lv);
}

// ---------------- fp32 -> bf16 hi/lo split ------------------------------------
__global__ void split_kernel(const float* __restrict__ src,
                             __nv_bfloat16* __restrict__ hi,
                             __nv_bfloat16* __restrict__ lo, int n) {
    int i = (blockIdx.x * blockDim.x + threadIdx.x) * 4;
    if (i >= n) return;
    float4 v = *(const float4*)(src + i);
    __nv_bfloat16 h0 = __float2bfloat16(v.x), h1 = __float2bfloat16(v.y);
    __nv_bfloat16 h2 = __float2bfloat16(v.z), h3 = __float2bfloat16(v.w);
    ((__nv_bfloat162*)(hi + i))[0] = __nv_bfloat162(h0, h1);
    ((__nv_bfloat162*)(hi + i))[1] = __nv_bfloat162(h2, h3);
    ((__nv_bfloat162*)(lo + i))[0] = __nv_bfloat162(
        __float2bfloat16(v.x - __bfloat162float(h0)),
        __float2bfloat16(v.y - __bfloat162float(h1)));
    ((__nv_bfloat162*)(lo + i))[1] = __nv_bfloat162(
        __float2bfloat16(v.z - __bfloat162float(h2)),
        __float2bfloat16(v.w - __bfloat162float(h3)));
}

// batched weight split
__global__ void wsplit_kernel(const float* __restrict__ w0, const float* __restrict__ w1,
                              const float* __restrict__ w2, const float* __restrict__ w3,
                              __nv_bfloat16* __restrict__ h0, __nv_bfloat16* __restrict__ l0,
                              __nv_bfloat16* __restrict__ h1, __nv_bfloat16* __restrict__ l1,
                              __nv_bfloat16* __restrict__ h2, __nv_bfloat16* __restrict__ l2,
                              __nv_bfloat16* __restrict__ h3, __nv_bfloat16* __restrict__ l3) {
    const float* src; __nv_bfloat16 *hi, *lo;
    switch (blockIdx.y) {
        case 0: src = w0; hi = h0; lo = l0; break;
        case 1: src = w1; hi = h1; lo = l1; break;
        case 2: src = w2; hi = h2; lo = l2; break;
        default: src = w3; hi = h3; lo = l3; break;
    }
    int i = (blockIdx.x * blockDim.x + threadIdx.x) * 4;
    float4 v = *(const float4*)(src + i);
    __nv_bfloat16 a0 = __float2bfloat16(v.x), a1 = __float2bfloat16(v.y);
    __nv_bfloat16 a2 = __float2bfloat16(v.z), a3 = __float2bfloat16(v.w);
    ((__nv_bfloat162*)(hi + i))[0] = __nv_bfloat162(a0, a1);
    ((__nv_bfloat162*)(hi + i))[1] = __nv_bfloat162(a2, a3);
    ((__nv_bfloat162*)(lo + i))[0] = __nv_bfloat162(
        __float2bfloat16(v.x - __bfloat162float(a0)),
        __float2bfloat16(v.y - __bfloat162float(a1)));
    ((__nv_bfloat162*)(lo + i))[1] = __nv_bfloat162(
        __float2bfloat16(v.z - __bfloat162float(a2)),
        __float2bfloat16(v.w - __bfloat162float(a3)));
}

// ---------------- gate = 3*sigmoid(x[:, :12] @ Wg^T) --------------------------
__global__ void gate_kernel(const float* __restrict__ x, const float* __restrict__ Wg,
                            float* __restrict__ gate) {
    int idx = blockIdx.x * blockDim.x + threadIdx.x;
    if (idx >= M_ * H_) return;
    int m = idx >> 4, h = idx & 15;
    float s = 0.f;
#pragma unroll
    for (int j = 0; j < 12; j++) s += x[(size_t)m * C_ + j] * Wg[h * 12 + j];
    gate[idx] = 3.f / (1.f + __expf(-s));
}

// ---------------- mma.sync bf16 split GEMM ------------------------------------
// 512 threads, 4x4 warps (warp tile 32x32), BK=32, 3-stage, prefetch depth 2.
#define RS_B 80
#define ARR_B (128 * RS_B)
#define STG_B (4 * ARR_B)           // 40960
#define NSTAGE 3
#define NCHUNK 64
#define GEMM_SMEM (NSTAGE * STG_B)  // 122880

template<int EPI>
__global__ __launch_bounds__(512, 1) void gemm_mma(
    const __nv_bfloat16* __restrict__ Ah, const __nv_bfloat16* __restrict__ Al,
    const __nv_bfloat16* __restrict__ Bh, const __nv_bfloat16* __restrict__ Bl,
    float* __restrict__ Cout,
    __nv_bfloat16* __restrict__ Oh, __nv_bfloat16* __restrict__ Ol,
    const float* __restrict__ ve, const float* __restrict__ gate,
    const float* __restrict__ cosp, const float* __restrict__ sinp) {
    extern __shared__ char smc[];
    const uint32_t sb = smem_u32(smc);
    const int tid = threadIdx.x;
    const int wid = tid >> 5, lane = tid & 31;
    const int warp_m = wid & 3, warp_n = wid >> 2;   // 4 x 4
    const int arow0 = blockIdx.y * 128, brow0 = blockIdx.x * 128;

    auto load_chunk = [&](int stage, int chunk) {
        const int k0 = chunk * 32;
        uint32_t stg = sb + stage * STG_B;
#pragma unroll
        for (int j = 0; j < 4; j++) {
            int u = tid + j * 512;           // 0..2047
            int arr = u >> 9;
            int rc = u & 511;
            int r = rc >> 2, c = rc & 3;
            uint32_t sa = stg + arr * ARR_B + r * RS_B + c * 16;
            const __nv_bfloat16* src;
            size_t off;
            if (arr < 2) {
                src = (arr == 0) ? Ah : Al;
                off = (size_t)(arow0 + r) * C_ + k0 + c * 8;
            } else {
                src = (arr == 2) ? Bh : Bl;
                off = (size_t)(brow0 + r) * C_ + k0 + c * 8;
            }
            cpasync16(sa, src + off);
        }
        asm volatile("cp.async.commit_group;" ::: "memory");
    };

    float acc[2][4][4];
#pragma unroll
    for (int mi = 0; mi < 2; mi++)
#pragma unroll
        for (int nf = 0; nf < 4; nf++)
#pragma unroll
            for (int q = 0; q < 4; q++) acc[mi][nf][q] = 0.f;

    load_chunk(0, 0);
    load_chunk(1, 1);

    const uint32_t a_lane_off = (uint32_t)((warp_m * 32 + (lane & 15)) * RS_B + (lane >> 4) * 16);
    const uint32_t b_lane_off = (uint32_t)((warp_n * 32 + (lane & 15)) * RS_B + (lane >> 4) * 16);

    for (int i = 0; i < NCHUNK; i++) {
        if (i < NCHUNK - 1) asm volatile("cp.async.wait_group 1;" ::: "memory");
        else                asm volatile("cp.async.wait_group 0;" ::: "memory");
        __syncthreads();
        if (i + 2 < NCHUNK) load_chunk((i + 2) % NSTAGE, i + 2);

        uint32_t stg = sb + (i % NSTAGE) * STG_B;
#pragma unroll
        for (int ks = 0; ks < 2; ks++) {
            uint32_t a_h[2][4], a_l[2][4];
            uint32_t b_h[4][2], b_l[4][2];
            uint32_t koff = ks * 32;
#pragma unroll
            for (int mi = 0; mi < 2; mi++) {
                ldsm4(stg + 0 * ARR_B + a_lane_off + mi * 16 * RS_B + koff, a_h[mi]);
                ldsm4(stg + 1 * ARR_B + a_lane_off + mi * 16 * RS_B + koff, a_l[mi]);
            }
#pragma unroll
            for (int nf4 = 0; nf4 < 2; nf4++) {
                uint32_t t[4];
                ldsm4(stg + 2 * ARR_B + b_lane_off + nf4 * 16 * RS_B + koff, t);
                b_h[nf4 * 2][0] = t[0]; b_h[nf4 * 2][1] = t[2];
                b_h[nf4 * 2 + 1][0] = t[1]; b_h[nf4 * 2 + 1][1] = t[3];
                ldsm4(stg + 3 * ARR_B + b_lane_off + nf4 * 16 * RS_B + koff, t);
                b_l[nf4 * 2][0] = t[0]; b_l[nf4 * 2][1] = t[2];
                b_l[nf4 * 2 + 1][0] = t[1]; b_l[nf4 * 2 + 1][1] = t[3];
            }
            // product-major: same-acc reuse distance = 8
#pragma unroll
            for (int mi = 0; mi < 2; mi++)
#pragma unroll
                for (int nf = 0; nf < 4; nf++) MMA_BF16(acc[mi][nf], a_h[mi], b_h[nf][0], b_h[nf][1]);
#pragma unroll
            for (int mi = 0; mi < 2; mi++)
#pragma unroll
                for (int nf = 0; nf < 4; nf++) MMA_BF16(acc[mi][nf], a_h[mi], b_l[nf][0], b_l[nf][1]);
#pragma unroll
            for (int mi = 0; mi < 2; mi++)
#pragma unroll
                for (int nf = 0; nf < 4; nf++) MMA_BF16(acc[mi][nf], a_l[mi], b_h[nf][0], b_h[nf][1]);
        }
    }

    if (EPI == 1) {
        // stage acc tile to smem, then rope+rms+split per row
        __syncthreads();
        float* S = (float*)smc;      // 128 x 132
        const int rbase = warp_m * 32 + (lane >> 2);
        const int cbase = warp_n * 32 + (lane & 3) * 2;
#pragma unroll
        for (int mi = 0; mi < 2; mi++)
#pragma unroll
            for (int nf = 0; nf < 4; nf++) {
                int r = rbase + mi * 16, c = cbase + nf * 8;
                S[r * 132 + c] = acc[mi][nf][0];
                S[r * 132 + c + 1] = acc[mi][nf][1];
                S[(r + 8) * 132 + c] = acc[mi][nf][2];
                S[(r + 8) * 132 + c + 1] = acc[mi][nf][3];
            }
        __syncthreads();
        const int hh = brow0 >> 7;
        const int d0 = lane * 2;
#pragma unroll 4
        for (int rr = wid * 8; rr < wid * 8 + 8; rr++) {
            int m = arow0 + rr, b = m >> 11, t = m & 2047;
            float xa0 = S[rr * 132 + d0],      xa1 = S[rr * 132 + d0 + 1];
            float xb0 = S[rr * 132 + d0 + 64], xb1 = S[rr * 132 + d0 + 65];
            float2 cc = *(const float2*)(cosp + t * 64 + d0);
            float2 sn = *(const float2*)(sinp + t * 64 + d0);
            float y1a = xa0 * cc.x + xb0 * sn.x;
            float y1b = xa1 * cc.y + xb1 * sn.y;
            float y2a = xb0 * cc.x - xa0 * sn.x;
            float y2b = xb1 * cc.y - xa1 * sn.y;
            float ss = y1a * y1a + y1b * y1b + y2a * y2a + y2b * y2b;
#pragma unroll
            for (int off = 16; off; off >>= 1) ss += __shfl_xor_sync(0xffffffffu, ss, off);
            float r = rsqrtf(ss * (1.f / 128.f) + 1e-6f) * 1.2f;
            size_t ob = ((size_t)(b * H_ + hh) * T_ + t) * D_;
            store_hl(Oh + ob + d0, Ol + ob + d0, y1a * r, y1b * r);
            store_hl(Oh + ob + d0 + 64, Ol + ob + d0 + 64, y2a * r, y2b * r);
        }
        return;
    }

    const int r0w = arow0 + warp_m * 32 + (lane >> 2);
    const int c0w = brow0 + warp_n * 32 + (lane & 3) * 2;
#pragma unroll
    for (int mi = 0; mi < 2; mi++) {
#pragma unroll
        for (int nf = 0; nf < 4; nf++) {
            int n = c0w + nf * 8;
            int m0 = r0w + mi * 16;
            int m1 = m0 + 8;
            float v0 = acc[mi][nf][0], v1 = acc[mi][nf][1];
            float v2 = acc[mi][nf][2], v3 = acc[mi][nf][3];
            if (EPI == 2) {
                float g0 = gate[m0 * H_ + (n >> 7)];
                float g1 = gate[m1 * H_ + (n >> 7)];
                const float* ve0 = ve + (size_t)m0 * C_ + n;
                const float* ve1 = ve + (size_t)m1 * C_ + n;
                v0 += g0 * ve0[0]; v1 += g0 * ve0[1];
                v2 += g1 * ve1[0]; v3 += g1 * ve1[1];
                int hh = n >> 7, dd = n & 127;
                size_t o0 = ((size_t)((m0 >> 11) * H_ + hh) * T_ + (m0 & 2047)) * D_ + dd;
                size_t o1 = ((size_t)((m1 >> 11) * H_ + hh) * T_ + (m1 & 2047)) * D_ + dd;
                store_hl(Oh + o0, Ol + o0, v0, v1);
                store_hl(Oh + o1, Ol + o1, v2, v3);
            } else {
                *(float2*)(Cout + (size_t)m0 * C_ + n) = make_float2(v0, v1);
                *(float2*)(Cout + (size_t)m1 * C_ + n) = make_float2(v2, v3);
            }
        }
    }
}

// ---------------- tensor-core flash attention (bf16 hi/lo split) -------------
// 256 threads (8 warps), q-tile 128 rows (16 per warp), KV tile 64, 2 stages.
#define QTB (128 * 272)              // 34816
#define KTB (64 * 272)               // 17408
#define KV_OFF (2 * QTB)             // 69632
#define STG (4 * KTB)                // 69632
#define ATT_SMEM (2 * QTB + 2 * STG) // 208896

__global__ __launch_bounds__(256, 1) void attn_mma(
    const __nv_bfloat16* __restrict__ qh, const __nv_bfloat16* __restrict__ ql,
    const __nv_bfloat16* __restrict__ kh, const __nv_bfloat16* __restrict__ kl,
    const __nv_bfloat16* __restrict__ vh, const __nv_bfloat16* __restrict__ vl,
    __nv_bfloat16* __restrict__ yh, __nv_bfloat16* __restrict__ yl,
    const int* __restrict__ winp) {
    extern __shared__ char smc[];
    const uint32_t sb = smem_u32(smc);
    const int tid = threadIdx.x, w = tid >> 5, l = tid & 31;
    const int t0 = blockIdx.x * 128, h = blockIdx.y, b = blockIdx.z;
    int win = *winp;
    if (win <= 0 || win >= T_) win = T_;
    const size_t hb = (size_t)(b * H_ + h) * ((size_t)T_ * D_);

    // Q hi/lo tiles (128 rows)
#pragma unroll
    for (int j = 0; j < 8; j++) {
        int u = tid + j * 256;
        int r = u >> 4, c = u & 15;
        uint32_t so = (uint32_t)(r * 272 + c * 16);
        size_t go = hb + (size_t)(t0 + r) * D_ + c * 8;
        cpasync16(sb + so, qh + go);
        cpasync16(sb + QTB + so, ql + go);
    }
    asm volatile("cp.async.commit_group;" ::: "memory");

    int start = t0 - win;
    if (start < 0) start = 0;
    start &= ~63;
    const int ntile = ((t0 + 64 - start) >> 6) + 1;

    auto loadKV = [&](int stg, int k0) {
        uint32_t bs = sb + KV_OFF + stg * STG;
#pragma unroll
        for (int j = 0; j < 16; j++) {
            int u = tid + j * 256;          // 0..4095
            int arr = u >> 10;
            int rc = u & 1023;
            int r = rc >> 4, c = rc & 15;
            uint32_t so = (uint32_t)(arr * KTB + r * 272 + c * 16);
            size_t go = hb + (size_t)(k0 + r) * D_ + c * 8;
            const __nv_bfloat16* src = (arr == 0) ? kh : (arr == 1) ? kl : (arr == 2) ? vh : vl;
            cpasync16(bs + so, src + go);
        }
        asm volatile("cp.async.commit_group;" ::: "memory");
    };
    loadKV(0, start);
    if (ntile > 1) loadKV(1, start + 64);

    float o[16][4];
#pragma unroll
    for (int f = 0; f < 16; f++)
#pragma unroll
        for (int q = 0; q < 4; q++) o[f][q] = 0.f;
    float rm0 = -1e4f, rm1 = -1e4f, rl0 = 0.f, rl1 = 0.f;
    const float SC2 = 0.1275187989f;   // 1/sqrt(128) * log2(e)

    const uint32_t aoff = (uint32_t)((w * 16 + (l & 15)) * 272 + (l >> 4) * 16);
    const uint32_t boff = (uint32_t)((l & 15) * 272 + (l >> 4) * 16);
    const int r0 = t0 + w * 16 + (l >> 2), r1 = r0 + 8;
    const int wr_min = t0 + w * 16, wr_max = t0 + w * 16 + 15;

    for (int i = 0; i < ntile; i++) {
        int k0 = start + i * 64;
        if (i + 1 < ntile) asm volatile("cp.async.wait_group 1;" ::: "memory");
        else               asm volatile("cp.async.wait_group 0;" ::: "memory");
        __syncthreads();
        uint32_t bs = sb + KV_OFF + (i & 1) * STG;

        // per-warp tile skip: fully-future or fully-out-of-window
        bool active = (k0 <= wr_max) && (k0 + 63 >= wr_min - win);
        if (active) {
            // ---- S = Qh*Kh + Qh*Kl + Ql*Kh (product-major) ----
            float s[8][4];
#pragma unroll
            for (int f = 0; f < 8; f++)
#pragma unroll
                for (int q = 0; q < 4; q++) s[f][q] = 0.f;
#pragma unroll
            for (int ks = 0; ks < 8; ks++) {
                uint32_t aq[4], al4[4];
                uint32_t tk[4][4], uk[4][4];
                ldsm4(sb + aoff + ks * 32, aq);
                ldsm4(sb + QTB + aoff + ks * 32, al4);
#pragma unroll
                for (int ng = 0; ng < 4; ng++) {
                    ldsm4(bs + boff + ng * 16 * 272 + ks * 32, tk[ng]);
                    ldsm4(bs + KTB + boff + ng * 16 * 272 + ks * 32, uk[ng]);
                }
#pragma unroll
                for (int ng = 0; ng < 4; ng++) {
                    MMA_BF16(s[ng * 2], aq, tk[ng][0], tk[ng][2]);
                    MMA_BF16(s[ng * 2 + 1], aq, tk[ng][1], tk[ng][3]);
                }
#pragma unroll
                for (int ng = 0; ng < 4; ng++) {
                    MMA_BF16(s[ng * 2], aq, uk[ng][0], uk[ng][2]);
                    MMA_BF16(s[ng * 2 + 1], aq, uk[ng][1], uk[ng][3]);
                }
#pragma unroll
                for (int ng = 0; ng < 4; ng++) {
                    MMA_BF16(s[ng * 2], al4, tk[ng][0], tk[ng][2]);
                    MMA_BF16(s[ng * 2 + 1], al4, tk[ng][1], tk[ng][3]);
                }
            }

            // ---- masked online softmax (exp2 domain) ----
            float mx0 = -1e30f, mx1 = -1e30f;
#pragma unroll
            for (int nf = 0; nf < 8; nf++) {
                int c0 = k0 + nf * 8 + (l & 3) * 2, c1 = c0 + 1;
                float x0 = (c0 <= r0 && r0 - c0 <= win) ? s[nf][0] * SC2 : -1e30f;
                float x1 = (c1 <= r0 && r0 - c1 <= win) ? s[nf][1] * SC2 : -1e30f;
                float x2 = (c0 <= r1 && r1 - c0 <= win) ? s[nf][2] * SC2 : -1e30f;
                float x3 = (c1 <= r1 && r1 - c1 <= win) ? s[nf][3] * SC2 : -1e30f;
                s[nf][0] = x0; s[nf][1] = x1; s[nf][2] = x2; s[nf][3] = x3;
                mx0 = fmaxf(mx0, fmaxf(x0, x1));
                mx1 = fmaxf(mx1, fmaxf(x2, x3));
            }
            mx0 = fmaxf(mx0, __shfl_xor_sync(0xffffffffu, mx0, 1));
            mx0 = fmaxf(mx0, __shfl_xor_sync(0xffffffffu, mx0, 2));
            mx1 = fmaxf(mx1, __shfl_xor_sync(0xffffffffu, mx1, 1));
            mx1 = fmaxf(mx1, __shfl_xor_sync(0xffffffffu, mx1, 2));
            float mn0 = fmaxf(rm0, fmaxf(mx0, -1e4f));
            float mn1 = fmaxf(rm1, fmaxf(mx1, -1e4f));
            float corr0 = ex2f(rm0 - mn0), corr1 = ex2f(rm1 - mn1);
            float ls0 = 0.f, ls1 = 0.f;
#pragma unroll
            for (int nf = 0; nf < 8; nf++) {
                float p0 = ex2f(s[nf][0] - mn0);
                float p1 = ex2f(s[nf][1] - mn0);
                float p2 = ex2f(s[nf][2] - mn1);
                float p3 = ex2f(s[nf][3] - mn1);
                s[nf][0] = p0; s[nf][1] = p1; s[nf][2] = p2; s[nf][3] = p3;
                ls0 += p0 + p1; ls1 += p2 + p3;
            }
            ls0 += __shfl_xor_sync(0xffffffffu, ls0, 1);
            ls0 += __shfl_xor_sync(0xffffffffu, ls0, 2);
            ls1 += __shfl_xor_sync(0xffffffffu, ls1, 1);
            ls1 += __shfl_xor_sync(0xffffffffu, ls1, 2);
            rl0 = rl0 * corr0 + ls0;
            rl1 = rl1 * corr1 + ls1;
            rm0 = mn0; rm1 = mn1;
#pragma unroll
            for (int f = 0; f < 16; f++) {
                o[f][0] *= corr0; o[f][1] *= corr0;
                o[f][2] *= corr1; o[f][3] *= corr1;
            }

            // ---- O += Ph*Vh + Ph*Vl + Pl*Vh (product-major per ks) ----
#pragma unroll
            for (int ks = 0; ks < 4; ks++) {
                uint32_t ph[4], pl4[4];
                packhl(s[2 * ks][0], s[2 * ks][1], ph[0], pl4[0]);
                packhl(s[2 * ks][2], s[2 * ks][3], ph[1], pl4[1]);
                packhl(s[2 * ks + 1][0], s[2 * ks + 1][1], ph[2], pl4[2]);
                packhl(s[2 * ks + 1][2], s[2 * ks + 1][3], ph[3], pl4[3]);
                uint32_t voff = (uint32_t)((ks * 16 + (l & 15)) * 272 + (l >> 4) * 16);
                uint32_t tv[8][4], uv[8][4];
#pragma unroll
                for (int dg = 0; dg < 8; dg++) {
                    ldsm4t(bs + 2 * KTB + voff + dg * 32, tv[dg]);
                    ldsm4t(bs + 3 * KTB + voff + dg * 32, uv[dg]);
                }
#pragma unroll
                for (int dg = 0; dg < 8; dg++) {
                    MMA_BF16(o[dg * 2], ph, tv[dg][0], tv[dg][1]);
                    MMA_BF16(o[dg * 2 + 1], ph, tv[dg][2], tv[dg][3]);
                }
#pragma unroll
                for (int dg = 0; dg < 8; dg++) {
                    MMA_BF16(o[dg * 2], ph, uv[dg][0], uv[dg][1]);
                    MMA_BF16(o[dg * 2 + 1], ph, uv[dg][2], uv[dg][3]);
                }
#pragma unroll
                for (int dg = 0; dg < 8; dg++) {
                    MMA_BF16(o[dg * 2], pl4, tv[dg][0], tv[dg][1]);
                    MMA_BF16(o[dg * 2 + 1], pl4, tv[dg][2], tv[dg][3]);
                }
            }
        }
        __syncthreads();
        if (i + 2 < ntile) loadKV(i & 1, k0 + 128);
    }

    float i0 = 1.f / rl0, i1 = 1.f / rl1;
    int m0r = t0 + w * 16 + (l >> 2);
#pragma unroll
    for (int f = 0; f < 16; f++) {
        int col = h * 128 + (f >> 1) * 16 + (f & 1) * 8 + (l & 3) * 2;
        size_t a0 = ((size_t)(b * T_ + m0r)) * C_ + col;
        size_t a1 = a0 + (size_t)8 * C_;
        store_hl(yh + a0, yl + a0, o[f][0] * i0, o[f][1] * i0);
        store_hl(yh + a1, yl + a1, o[f][2] * i1, o[f][3] * i1);
    }
}

// ---------------- launch ------------------------------------------------------
extern "C" void kernel_launch(void* const* d_in, const int* in_sizes, int n_in,
                              void* d_out, int out_size) {
    const float* x     = (const float*)d_in[0];
    const float* ve    = (const float*)d_in[1];
    const float* Wq    = (const float*)d_in[2];
    const float* Wk    = (const float*)d_in[3];
    const float* Wv    = (const float*)d_in[4];
    const float* Wproj = (const float*)d_in[5];
    const float* Wg    = (const float*)d_in[6];
    const float* cosp  = (const float*)d_in[7];
    const float* sinp  = (const float*)d_in[8];
    const int*   winp  = (const int*)d_in[9];
    float* out = (float*)d_out;

    void *pg, *pxh, *pxl, *pyh, *pyl;
    void *pqh, *pql, *pkh, *pkl, *pvh, *pvl;
    void *pwqh, *pwql, *pwkh, *pwkl, *pwvh, *pwvl, *pwph, *pwpl;
    cudaGetSymbolAddress(&pg,  g_gate);
    cudaGetSymbolAddress(&pxh, g_xh);  cudaGetSymbolAddress(&pxl, g_xl);
    cudaGetSymbolAddress(&pyh, g_yh);  cudaGetSymbolAddress(&pyl, g_yl);
    cudaGetSymbolAddress(&pqh, g_qh);  cudaGetSymbolAddress(&pql, g_ql);
    cudaGetSymbolAddress(&pkh, g_kh);  cudaGetSymbolAddress(&pkl, g_kl);
    cudaGetSymbolAddress(&pvh, g_vh);  cudaGetSymbolAddress(&pvl, g_vl);
    cudaGetSymbolAddress(&pwqh, g_wqh); cudaGetSymbolAddress(&pwql, g_wql);
    cudaGetSymbolAddress(&pwkh, g_wkh); cudaGetSymbolAddress(&pwkl, g_wkl);
    cudaGetSymbolAddress(&pwvh, g_wvh); cudaGetSymbolAddress(&pwvl, g_wvl);
    cudaGetSymbolAddress(&pwph, g_wph); cudaGetSymbolAddress(&pwpl, g_wpl);

    cudaFuncSetAttribute(gemm_mma<0>, cudaFuncAttributeMaxDynamicSharedMemorySize, GEMM_SMEM);
    cudaFuncSetAttribute(gemm_mma<1>, cudaFuncAttributeMaxDynamicSharedMemorySize, GEMM_SMEM);
    cudaFuncSetAttribute(gemm_mma<2>, cudaFuncAttributeMaxDynamicSharedMemorySize, GEMM_SMEM);
    cudaFuncSetAttribute(attn_mma, cudaFuncAttributeMaxDynamicSharedMemorySize, ATT_SMEM);

    // 0) splits
    split_kernel<<<M_*C_/1024, 256>>>(x, (__nv_bfloat16*)pxh, (__nv_bfloat16*)pxl, M_*C_);
    wsplit_kernel<<<dim3(C_*C_/1024, 4), 256>>>(
        Wq, Wk, Wv, Wproj,
        (__nv_bfloat16*)pwqh, (__nv_bfloat16*)pwql,
        (__nv_bfloat16*)pwkh, (__nv_bfloat16*)pwkl,
        (__nv_bfloat16*)pwvh, (__nv_bfloat16*)pwvl,
        (__nv_bfloat16*)pwph, (__nv_bfloat16*)pwpl);

    // 1) gate
    gate_kernel<<<(M_ * H_ + 255) / 256, 256>>>(x, Wg, (float*)pg);

    // 2) q, k projections (fused rope+rms+split), v projection (fused gate+split)
    dim3 ggrid(C_ / 128, M_ / 128);
    gemm_mma<1><<<ggrid, 512, GEMM_SMEM>>>((const __nv_bfloat16*)pxh, (const __nv_bfloat16*)pxl,
                                           (const __nv_bfloat16*)pwqh, (const __nv_bfloat16*)pwql,
                                           nullptr, (__nv_bfloat16*)pqh, (__nv_bfloat16*)pql,
                                           nullptr, nullptr, cosp, sinp);
    gemm_mma<1><<<ggrid, 512, GEMM_SMEM>>>((const __nv_bfloat16*)pxh, (const __nv_bfloat16*)pxl,
                                           (const __nv_bfloat16*)pwkh, (const __nv_bfloat16*)pwkl,
                                           nullptr, (__nv_bfloat16*)pkh, (__nv_bfloat16*)pkl,
                                           nullptr, nullptr, cosp, sinp);
    gemm_mma<2><<<ggrid, 512, GEMM_SMEM>>>((const __nv_bfloat16*)pxh, (const __nv_bfloat16*)pxl,
                                           (const __nv_bfloat16*)pwvh, (const __nv_bfloat16*)pwvl,
                                           nullptr, (__nv_bfloat16*)pvh, (__nv_bfloat16*)pvl,
                                           ve, (const float*)pg, nullptr, nullptr);

    // 3) tensor-core attention -> bf16 hi/lo y
    attn_mma<<<dim3(T_ / 128, H_, B_), 256, ATT_SMEM>>>(
        (const __nv_bfloat16*)pqh, (const __nv_bfloat16*)pql,
        (const __nv_bfloat16*)pkh, (const __nv_bfloat16*)pkl,
        (const __nv_bfloat16*)pvh, (const __nv_bfloat16*)pvl,
        (__nv_bfloat16*)pyh, (__nv_bfloat16*)pyl, winp);

    // 4) output projection
    gemm_mma<0><<<ggrid, 512, GEMM_SMEM>>>((const __nv_bfloat16*)pyh, (const __nv_bfloat16*)pyl,
                                           (const __nv_bfloat16*)pwph, (const __nv_bfloat16*)pwpl,
                                           out, nullptr, nullptr, nullptr, nullptr,
                                           nullptr, nullptr);
}

// round 8
// speedup vs baseline: 1.0461x; 1.0461x over previous
#include <cuda_runtime.h>
#include <cuda_bf16.h>
#include <math.h>
#include <stdint.h>

#define B_ 2
#define T_ 2048
#define C_ 2048
#define H_ 16
#define D_ 128
#define M_ (B_*T_)   // 4096 rows

// ---------------- scratch (device globals; no allocation allowed) -------------
__device__ float g_gate[M_*H_];
__device__ __nv_bfloat16 g_xh[M_*C_],  g_xl[M_*C_];
__device__ __nv_bfloat16 g_yh[M_*C_],  g_yl[M_*C_];
__device__ __nv_bfloat16 g_qh[M_*C_],  g_ql[M_*C_];   // [b][h][t][d]
__device__ __nv_bfloat16 g_kh[M_*C_],  g_kl[M_*C_];   // [b][h][t][d]
__device__ __nv_bfloat16 g_vh[M_*C_],  g_vl[M_*C_];   // [b][h][t][d]
__device__ __nv_bfloat16 g_wqh[C_*C_], g_wql[C_*C_];
__device__ __nv_bfloat16 g_wkh[C_*C_], g_wkl[C_*C_];
__device__ __nv_bfloat16 g_wvh[C_*C_], g_wvl[C_*C_];
__device__ __nv_bfloat16 g_wph[C_*C_], g_wpl[C_*C_];

// ================= PTX helpers =================
__device__ __forceinline__ uint32_t smem_u32(const void* p) {
    uint32_t a;
    asm("{ .reg .u64 t; cvta.to.shared.u64 t, %1; cvt.u32.u64 %0, t; }" : "=r"(a) : "l"(p));
    return a;
}
__device__ __forceinline__ void cpasync16(uint32_t saddr, const void* gaddr) {
    asm volatile("cp.async.cg.shared.global [%0], [%1], 16;" :: "r"(saddr), "l"(gaddr) : "memory");
}
__device__ __forceinline__ void ldsm4(uint32_t addr, uint32_t* r) {
    asm volatile("ldmatrix.sync.aligned.m8n8.x4.shared.b16 {%0,%1,%2,%3}, [%4];"
                 : "=r"(r[0]), "=r"(r[1]), "=r"(r[2]), "=r"(r[3]) : "r"(addr));
}
__device__ __forceinline__ void ldsm4t(uint32_t addr, uint32_t* r) {
    asm volatile("ldmatrix.sync.aligned.m8n8.x4.trans.shared.b16 {%0,%1,%2,%3}, [%4];"
                 : "=r"(r[0]), "=r"(r[1]), "=r"(r[2]), "=r"(r[3]) : "r"(addr));
}
__device__ __forceinline__ float ex2f(float x) {
    float y; asm("ex2.approx.f32 %0, %1;" : "=f"(y) : "f"(x)); return y;
}
#define MMA_BF16(Cf, Af, B0, B1)                                              \
    asm volatile("mma.sync.aligned.m16n8k16.row.col.f32.bf16.bf16.f32 "        \
        "{%0,%1,%2,%3},{%4,%5,%6,%7},{%8,%9},{%0,%1,%2,%3};"                   \
        : "+f"((Cf)[0]), "+f"((Cf)[1]), "+f"((Cf)[2]), "+f"((Cf)[3])           \
        : "r"((Af)[0]), "r"((Af)[1]), "r"((Af)[2]), "r"((Af)[3]),              \
          "r"(B0), "r"(B1))

__device__ __forceinline__ void store_hl(__nv_bfloat16* ph, __nv_bfloat16* pl,
                                         float a, float b) {
    __nv_bfloat16 ha = __float2bfloat16(a), hb = __float2bfloat16(b);
    *reinterpret_cast<__nv_bfloat162*>(ph) = __nv_bfloat162(ha, hb);
    *reinterpret_cast<__nv_bfloat162*>(pl) = __nv_bfloat162(
        __float2bfloat16(a - __bfloat162float(ha)),
        __float2bfloat16(b - __bfloat162float(hb)));
}
__device__ __forceinline__ void packhl(float a, float b, uint32_t& hi, uint32_t& lo) {
    __nv_bfloat16 ha = __float2bfloat16(a), hb = __float2bfloat16(b);
    __nv_bfloat162 hv(ha, hb);
    hi = *reinterpret_cast<uint32_t*>(&hv);
    __nv_bfloat162 lv(__float2bfloat16(a - __bfloat162float(ha)),
                      __float2bfloat16(b - __bfloat162float(hb)));
    lo = *reinterpret_cast<uint32_t*>(&lv);
}

// ---------------- fp32 -> bf16 hi/lo split ------------------------------------
__global__ void split_kernel(const float* __restrict__ src,
                             __nv_bfloat16* __restrict__ hi,
                             __nv_bfloat16* __restrict__ lo, int n) {
    int i = (blockIdx.x * blockDim.x + threadIdx.x) * 4;
    if (i >= n) return;
    float4 v = *(const float4*)(src + i);
    __nv_bfloat16 h0 = __float2bfloat16(v.x), h1 = __float2bfloat16(v.y);
    __nv_bfloat16 h2 = __float2bfloat16(v.z), h3 = __float2bfloat16(v.w);
    ((__nv_bfloat162*)(hi + i))[0] = __nv_bfloat162(h0, h1);
    ((__nv_bfloat162*)(hi + i))[1] = __nv_bfloat162(h2, h3);
    ((__nv_bfloat162*)(lo + i))[0] = __nv_bfloat162(
        __float2bfloat16(v.x - __bfloat162float(h0)),
        __float2bfloat16(v.y - __bfloat162float(h1)));
    ((__nv_bfloat162*)(lo + i))[1] = __nv_bfloat162(
        __float2bfloat16(v.z - __bfloat162float(h2)),
        __float2bfloat16(v.w - __bfloat162float(h3)));
}

// batched weight split
__global__ void wsplit_kernel(const float* __restrict__ w0, const float* __restrict__ w1,
                              const float* __restrict__ w2, const float* __restrict__ w3,
                              __nv_bfloat16* __restrict__ h0, __nv_bfloat16* __restrict__ l0,
                              __nv_bfloat16* __restrict__ h1, __nv_bfloat16* __restrict__ l1,
                              __nv_bfloat16* __restrict__ h2, __nv_bfloat16* __restrict__ l2,
                              __nv_bfloat16* __restrict__ h3, __nv_bfloat16* __restrict__ l3) {
    const float* src; __nv_bfloat16 *hi, *lo;
    switch (blockIdx.y) {
        case 0: src = w0; hi = h0; lo = l0; break;
        case 1: src = w1; hi = h1; lo = l1; break;
        case 2: src = w2; hi = h2; lo = l2; break;
        default: src = w3; hi = h3; lo = l3; break;
    }
    int i = (blockIdx.x * blockDim.x + threadIdx.x) * 4;
    float4 v = *(const float4*)(src + i);
    __nv_bfloat16 a0 = __float2bfloat16(v.x), a1 = __float2bfloat16(v.y);
    __nv_bfloat16 a2 = __float2bfloat16(v.z), a3 = __float2bfloat16(v.w);
    ((__nv_bfloat162*)(hi + i))[0] = __nv_bfloat162(a0, a1);
    ((__nv_bfloat162*)(hi + i))[1] = __nv_bfloat162(a2, a3);
    ((__nv_bfloat162*)(lo + i))[0] = __nv_bfloat162(
        __float2bfloat16(v.x - __bfloat162float(a0)),
        __float2bfloat16(v.y - __bfloat162float(a1)));
    ((__nv_bfloat162*)(lo + i))[1] = __nv_bfloat162(
        __float2bfloat16(v.z - __bfloat162float(a2)),
        __float2bfloat16(v.w - __bfloat162float(a3)));
}

// ---------------- gate = 3*sigmoid(x[:, :12] @ Wg^T) --------------------------
__global__ void gate_kernel(const float* __restrict__ x, const float* __restrict__ Wg,
                            float* __restrict__ gate) {
    int idx = blockIdx.x * blockDim.x + threadIdx.x;
    if (idx >= M_ * H_) return;
    int m = idx >> 4, h = idx & 15;
    float s = 0.f;
#pragma unroll
    for (int j = 0; j < 12; j++) s += x[(size_t)m * C_ + j] * Wg[h * 12 + j];
    gate[idx] = 3.f / (1.f + __expf(-s));
}

// ---------------- mma.sync bf16 split GEMM ------------------------------------
// 256 threads, 4x2 warps (warp tile 32x64), BK=32, 3 stages,
// fragment double-buffering + cross-chunk register prefetch.
// Barrier placed mid-iteration: publishes chunk i+1 AND fences stage(i) reuse.
#define RS_B 80
#define ARR_B (128 * RS_B)
#define STG_B (4 * ARR_B)           // 40960
#define NSTAGE 3
#define NCHUNK 64
#define GEMM_SMEM (NSTAGE * STG_B)  // 122880

struct Frag {
    uint32_t a_h[2][4], a_l[2][4];
    uint32_t b_h[8][2], b_l[8][2];
};

template<int EPI>
__global__ __launch_bounds__(256, 1) void gemm_mma(
    const __nv_bfloat16* __restrict__ Ah, const __nv_bfloat16* __restrict__ Al,
    const __nv_bfloat16* __restrict__ Bh, const __nv_bfloat16* __restrict__ Bl,
    float* __restrict__ Cout,
    __nv_bfloat16* __restrict__ Oh, __nv_bfloat16* __restrict__ Ol,
    const float* __restrict__ ve, const float* __restrict__ gate,
    const float* __restrict__ cosp, const float* __restrict__ sinp) {
    extern __shared__ char smc[];
    const uint32_t sb = smem_u32(smc);
    const int tid = threadIdx.x;
    const int wid = tid >> 5, lane = tid & 31;
    const int warp_m = wid & 3, warp_n = wid >> 2;   // 4 x 2
    const int arow0 = blockIdx.y * 128, brow0 = blockIdx.x * 128;

    auto load_chunk = [&](int stage, int chunk) {
        const int k0 = chunk * 32;
        uint32_t stg = sb + stage * STG_B;
#pragma unroll
        for (int j = 0; j < 8; j++) {
            int u = tid + j * 256;
            int arr = u >> 9;
            int rc = u & 511;
            int r = rc >> 2, c = rc & 3;
            uint32_t sa = stg + arr * ARR_B + r * RS_B + c * 16;
            const __nv_bfloat16* src;
            size_t off;
            if (arr < 2) {
                src = (arr == 0) ? Ah : Al;
                off = (size_t)(arow0 + r) * C_ + k0 + c * 8;
            } else {
                src = (arr == 2) ? Bh : Bl;
                off = (size_t)(brow0 + r) * C_ + k0 + c * 8;
            }
            cpasync16(sa, src + off);
        }
        asm volatile("cp.async.commit_group;" ::: "memory");
    };

    const uint32_t a_lane_off = (uint32_t)((warp_m * 32 + (lane & 15)) * RS_B + (lane >> 4) * 16);
    const uint32_t b_lane_off = (uint32_t)((warp_n * 64 + (lane & 15)) * RS_B + (lane >> 4) * 16);

    auto ldfr = [&](Frag& F, uint32_t stg, uint32_t koff) {
#pragma unroll
        for (int mi = 0; mi < 2; mi++) {
            ldsm4(stg + 0 * ARR_B + a_lane_off + mi * 16 * RS_B + koff, F.a_h[mi]);
            ldsm4(stg + 1 * ARR_B + a_lane_off + mi * 16 * RS_B + koff, F.a_l[mi]);
        }
#pragma unroll
        for (int nf4 = 0; nf4 < 4; nf4++) {
            uint32_t t[4];
            ldsm4(stg + 2 * ARR_B + b_lane_off + nf4 * 16 * RS_B + koff, t);
            F.b_h[nf4 * 2][0] = t[0]; F.b_h[nf4 * 2][1] = t[2];
            F.b_h[nf4 * 2 + 1][0] = t[1]; F.b_h[nf4 * 2 + 1][1] = t[3];
            ldsm4(stg + 3 * ARR_B + b_lane_off + nf4 * 16 * RS_B + koff, t);
            F.b_l[nf4 * 2][0] = t[0]; F.b_l[nf4 * 2][1] = t[2];
            F.b_l[nf4 * 2 + 1][0] = t[1]; F.b_l[nf4 * 2 + 1][1] = t[3];
        }
    };

    float acc[2][8][4];
#pragma unroll
    for (int mi = 0; mi < 2; mi++)
#pragma unroll
        for (int nf = 0; nf < 8; nf++)
#pragma unroll
            for (int q = 0; q < 4; q++) acc[mi][nf][q] = 0.f;

    auto mmab = [&](Frag& F) {
#pragma unroll
        for (int mi = 0; mi < 2; mi++)
#pragma unroll
            for (int nf = 0; nf < 8; nf++) MMA_BF16(acc[mi][nf], F.a_h[mi], F.b_h[nf][0], F.b_h[nf][1]);
#pragma unroll
        for (int mi = 0; mi < 2; mi++)
#pragma unroll
            for (int nf = 0; nf < 8; nf++) MMA_BF16(acc[mi][nf], F.a_h[mi], F.b_l[nf][0], F.b_l[nf][1]);
#pragma unroll
        for (int mi = 0; mi < 2; mi++)
#pragma unroll
            for (int nf = 0; nf < 8; nf++) MMA_BF16(acc[mi][nf], F.a_l[mi], F.b_h[nf][0], F.b_h[nf][1]);
    };

    // prologue: fill 3 stages; publish chunk 0; preload its ks0 fragments
    load_chunk(0, 0);
    load_chunk(1, 1);
    load_chunk(2, 2);
    asm volatile("cp.async.wait_group 2;" ::: "memory");
    __syncthreads();

    Frag Fa, Fb;
    ldfr(Fa, sb, 0);

    for (int i = 0; i < NCHUNK; i++) {
        uint32_t stg = sb + (i % NSTAGE) * STG_B;
        ldfr(Fb, stg, 32);           // chunk i ks1 (published)
        mmab(Fa);                    // chunk i ks0 — overlaps with ldfr above
        if (i < NCHUNK - 1) {
            if (i < NCHUNK - 2) asm volatile("cp.async.wait_group 1;" ::: "memory");
            else                asm volatile("cp.async.wait_group 0;" ::: "memory");
            __syncthreads();         // publish chunk i+1; fence all reads of stage(i)
            uint32_t stg2 = sb + ((i + 1) % NSTAGE) * STG_B;
            ldfr(Fa, stg2, 0);       // chunk i+1 ks0 (now safely published)
            if (i + 3 < NCHUNK) load_chunk(i % NSTAGE, i + 3);
        }
        mmab(Fb);                    // chunk i ks1
    }

    if (EPI == 1) {
        // stage acc tile to smem, then rope+rms+split per row
        __syncthreads();
        float* S = (float*)smc;      // 128 x 132
        const int rbase = warp_m * 32 + (lane >> 2);
        const int cbase = warp_n * 64 + (lane & 3) * 2;
#pragma unroll
        for (int mi = 0; mi < 2; mi++)
#pragma unroll
            for (int nf = 0; nf < 8; nf++) {
                int r = rbase + mi * 16, c = cbase + nf * 8;
                S[r * 132 + c] = acc[mi][nf][0];
                S[r * 132 + c + 1] = acc[mi][nf][1];
                S[(r + 8) * 132 + c] = acc[mi][nf][2];
                S[(r + 8) * 132 + c + 1] = acc[mi][nf][3];
            }
        __syncthreads();
        const int hh = brow0 >> 7;
        const int d0 = lane * 2;
#pragma unroll 4
        for (int rr = wid * 16; rr < wid * 16 + 16; rr++) {
            int m = arow0 + rr, b = m >> 11, t = m & 2047;
            float xa0 = S[rr * 132 + d0],      xa1 = S[rr * 132 + d0 + 1];
            float xb0 = S[rr * 132 + d0 + 64], xb1 = S[rr * 132 + d0 + 65];
            float2 cc = *(const float2*)(cosp + t * 64 + d0);
            float2 sn = *(const float2*)(sinp + t * 64 + d0);
            float y1a = xa0 * cc.x + xb0 * sn.x;
            float y1b = xa1 * cc.y + xb1 * sn.y;
            float y2a = xb0 * cc.x - xa0 * sn.x;
            float y2b = xb1 * cc.y - xa1 * sn.y;
            float ss = y1a * y1a + y1b * y1b + y2a * y2a + y2b * y2b;
#pragma unroll
            for (int off = 16; off; off >>= 1) ss += __shfl_xor_sync(0xffffffffu, ss, off);
            float r = rsqrtf(ss * (1.f / 128.f) + 1e-6f) * 1.2f;
            size_t ob = ((size_t)(b * H_ + hh) * T_ + t) * D_;
            store_hl(Oh + ob + d0, Ol + ob + d0, y1a * r, y1b * r);
            store_hl(Oh + ob + d0 + 64, Ol + ob + d0 + 64, y2a * r, y2b * r);
        }
        return;
    }

    const int r0w = arow0 + warp_m * 32 + (lane >> 2);
    const int c0w = brow0 + warp_n * 64 + (lane & 3) * 2;
#pragma unroll
    for (int mi = 0; mi < 2; mi++) {
#pragma unroll
        for (int nf = 0; nf < 8; nf++) {
            int n = c0w + nf * 8;
            int m0 = r0w + mi * 16;
            int m1 = m0 + 8;
            float v0 = acc[mi][nf][0], v1 = acc[mi][nf][1];
            float v2 = acc[mi][nf][2], v3 = acc[mi][nf][3];
            if (EPI == 2) {
                float g0 = gate[m0 * H_ + (n >> 7)];
                float g1 = gate[m1 * H_ + (n >> 7)];
                const float* ve0 = ve + (size_t)m0 * C_ + n;
                const float* ve1 = ve + (size_t)m1 * C_ + n;
                v0 += g0 * ve0[0]; v1 += g0 * ve0[1];
                v2 += g1 * ve1[0]; v3 += g1 * ve1[1];
                int hh = n >> 7, dd = n & 127;
                size_t o0 = ((size_t)((m0 >> 11) * H_ + hh) * T_ + (m0 & 2047)) * D_ + dd;
                size_t o1 = ((size_t)((m1 >> 11) * H_ + hh) * T_ + (m1 & 2047)) * D_ + dd;
                store_hl(Oh + o0, Ol + o0, v0, v1);
                store_hl(Oh + o1, Ol + o1, v2, v3);
            } else {
                *(float2*)(Cout + (size_t)m0 * C_ + n) = make_float2(v0, v1);
                *(float2*)(Cout + (size_t)m1 * C_ + n) = make_float2(v2, v3);
            }
        }
    }
}

// ---------------- tensor-core flash attention (bf16 hi/lo split) -------------
// 256 threads (8 warps), q-tile 128 rows (16 per warp), KV tile 64, 2 stages.
#define QTB (128 * 272)              // 34816
#define KTB (64 * 272)               // 17408
#define KV_OFF (2 * QTB)             // 69632
#define STG (4 * KTB)                // 69632
#define ATT_SMEM (2 * QTB + 2 * STG) // 208896

__global__ __launch_bounds__(256, 1) void attn_mma(
    const __nv_bfloat16* __restrict__ qh, const __nv_bfloat16* __restrict__ ql,
    const __nv_bfloat16* __restrict__ kh, const __nv_bfloat16* __restrict__ kl,
    const __nv_bfloat16* __restrict__ vh, const __nv_bfloat16* __restrict__ vl,
    __nv_bfloat16* __restrict__ yh, __nv_bfloat16* __restrict__ yl,
    const int* __restrict__ winp) {
    extern __shared__ char smc[];
    const uint32_t sb = smem_u32(smc);
    const int tid = threadIdx.x, w = tid >> 5, l = tid & 31;
    const int t0 = blockIdx.x * 128, h = blockIdx.y, b = blockIdx.z;
    int win = *winp;
    if (win <= 0 || win >= T_) win = T_;
    const size_t hb = (size_t)(b * H_ + h) * ((size_t)T_ * D_);

    // Q hi/lo tiles (128 rows)
#pragma unroll
    for (int j = 0; j < 8; j++) {
        int u = tid + j * 256;
        int r = u >> 4, c = u & 15;
        uint32_t so = (uint32_t)(r * 272 + c * 16);
        size_t go = hb + (size_t)(t0 + r) * D_ + c * 8;
        cpasync16(sb + so, qh + go);
        cpasync16(sb + QTB + so, ql + go);
    }
    asm volatile("cp.async.commit_group;" ::: "memory");

    int start = t0 - win;
    if (start < 0) start = 0;
    start &= ~63;
    const int ntile = ((t0 + 64 - start) >> 6) + 1;

    auto loadKV = [&](int stg, int k0) {
        uint32_t bs = sb + KV_OFF + stg * STG;
#pragma unroll
        for (int j = 0; j < 16; j++) {
            int u = tid + j * 256;          // 0..4095
            int arr = u >> 10;
            int rc = u & 1023;
            int r = rc >> 4, c = rc & 15;
            uint32_t so = (uint32_t)(arr * KTB + r * 272 + c * 16);
            size_t go = hb + (size_t)(k0 + r) * D_ + c * 8;
            const __nv_bfloat16* src = (arr == 0) ? kh : (arr == 1) ? kl : (arr == 2) ? vh : vl;
            cpasync16(bs + so, src + go);
        }
        asm volatile("cp.async.commit_group;" ::: "memory");
    };
    loadKV(0, start);
    if (ntile > 1) loadKV(1, start + 64);

    float o[16][4];
#pragma unroll
    for (int f = 0; f < 16; f++)
#pragma unroll
        for (int q = 0; q < 4; q++) o[f][q] = 0.f;
    float rm0 = -1e4f, rm1 = -1e4f, rl0 = 0.f, rl1 = 0.f;
    const float SC2 = 0.1275187989f;   // 1/sqrt(128) * log2(e)

    const uint32_t aoff = (uint32_t)((w * 16 + (l & 15)) * 272 + (l >> 4) * 16);
    const uint32_t boff = (uint32_t)((l & 15) * 272 + (l >> 4) * 16);
    const int r0 = t0 + w * 16 + (l >> 2), r1 = r0 + 8;
    const int wr_min = t0 + w * 16, wr_max = t0 + w * 16 + 15;

    for (int i = 0; i < ntile; i++) {
        int k0 = start + i * 64;
        if (i + 1 < ntile) asm volatile("cp.async.wait_group 1;" ::: "memory");
        else               asm volatile("cp.async.wait_group 0;" ::: "memory");
        __syncthreads();
        uint32_t bs = sb + KV_OFF + (i & 1) * STG;

        // per-warp tile skip: fully-future or fully-out-of-window
        bool active = (k0 <= wr_max) && (k0 + 63 >= wr_min - win);
        if (active) {
            // ---- S = Qh*Kh + Qh*Kl + Ql*Kh (product-major) ----
            float s[8][4];
#pragma unroll
            for (int f = 0; f < 8; f++)
#pragma unroll
                for (int q = 0; q < 4; q++) s[f][q] = 0.f;
#pragma unroll
            for (int ks = 0; ks < 8; ks++) {
                uint32_t aq[4], al4[4];
                uint32_t tk[4][4], uk[4][4];
                ldsm4(sb + aoff + ks * 32, aq);
                ldsm4(sb + QTB + aoff + ks * 32, al4);
#pragma unroll
                for (int ng = 0; ng < 4; ng++) {
                    ldsm4(bs + boff + ng * 16 * 272 + ks * 32, tk[ng]);
                    ldsm4(bs + KTB + boff + ng * 16 * 272 + ks * 32, uk[ng]);
                }
#pragma unroll
                for (int ng = 0; ng < 4; ng++) {
                    MMA_BF16(s[ng * 2], aq, tk[ng][0], tk[ng][2]);
                    MMA_BF16(s[ng * 2 + 1], aq, tk[ng][1], tk[ng][3]);
                }
#pragma unroll
                for (int ng = 0; ng < 4; ng++) {
                    MMA_BF16(s[ng * 2], aq, uk[ng][0], uk[ng][2]);
                    MMA_BF16(s[ng * 2 + 1], aq, uk[ng][1], uk[ng][3]);
                }
#pragma unroll
                for (int ng = 0; ng < 4; ng++) {
                    MMA_BF16(s[ng * 2], al4, tk[ng][0], tk[ng][2]);
                    MMA_BF16(s[ng * 2 + 1], al4, tk[ng][1], tk[ng][3]);
                }
            }

            // ---- masked online softmax (exp2 domain) ----
            float mx0 = -1e30f, mx1 = -1e30f;
#pragma unroll
            for (int nf = 0; nf < 8; nf++) {
                int c0 = k0 + nf * 8 + (l & 3) * 2, c1 = c0 + 1;
                float x0 = (c0 <= r0 && r0 - c0 <= win) ? s[nf][0] * SC2 : -1e30f;
                float x1 = (c1 <= r0 && r0 - c1 <= win) ? s[nf][1] * SC2 : -1e30f;
                float x2 = (c0 <= r1 && r1 - c0 <= win) ? s[nf][2] * SC2 : -1e30f;
                float x3 = (c1 <= r1 && r1 - c1 <= win) ? s[nf][3] * SC2 : -1e30f;
                s[nf][0] = x0; s[nf][1] = x1; s[nf][2] = x2; s[nf][3] = x3;
                mx0 = fmaxf(mx0, fmaxf(x0, x1));
                mx1 = fmaxf(mx1, fmaxf(x2, x3));
            }
            mx0 = fmaxf(mx0, __shfl_xor_sync(0xffffffffu, mx0, 1));
            mx0 = fmaxf(mx0, __shfl_xor_sync(0xffffffffu, mx0, 2));
            mx1 = fmaxf(mx1, __shfl_xor_sync(0xffffffffu, mx1, 1));
            mx1 = fmaxf(mx1, __shfl_xor_sync(0xffffffffu, mx1, 2));
            float mn0 = fmaxf(rm0, fmaxf(mx0, -1e4f));
            float mn1 = fmaxf(rm1, fmaxf(mx1, -1e4f));
            float corr0 = ex2f(rm0 - mn0), corr1 = ex2f(rm1 - mn1);
            float ls0 = 0.f, ls1 = 0.f;
#pragma unroll
            for (int nf = 0; nf < 8; nf++) {
                float p0 = ex2f(s[nf][0] - mn0);
                float p1 = ex2f(s[nf][1] - mn0);
                float p2 = ex2f(s[nf][2] - mn1);
                float p3 = ex2f(s[nf][3] - mn1);
                s[nf][0] = p0; s[nf][1] = p1; s[nf][2] = p2; s[nf][3] = p3;
                ls0 += p0 + p1; ls1 += p2 + p3;
            }
            ls0 += __shfl_xor_sync(0xffffffffu, ls0, 1);
            ls0 += __shfl_xor_sync(0xffffffffu, ls0, 2);
            ls1 += __shfl_xor_sync(0xffffffffu, ls1, 1);
            ls1 += __shfl_xor_sync(0xffffffffu, ls1, 2);
            rl0 = rl0 * corr0 + ls0;
            rl1 = rl1 * corr1 + ls1;
            rm0 = mn0; rm1 = mn1;
#pragma unroll
            for (int f = 0; f < 16; f++) {
                o[f][0] *= corr0; o[f][1] *= corr0;
                o[f][2] *= corr1; o[f][3] *= corr1;
            }

            // ---- O += Ph*Vh + Ph*Vl + Pl*Vh (product-major per ks) ----
#pragma unroll
            for (int ks = 0; ks < 4; ks++) {
                uint32_t ph[4], pl4[4];
                packhl(s[2 * ks][0], s[2 * ks][1], ph[0], pl4[0]);
                packhl(s[2 * ks][2], s[2 * ks][3], ph[1], pl4[1]);
                packhl(s[2 * ks + 1][0], s[2 * ks + 1][1], ph[2], pl4[2]);
                packhl(s[2 * ks + 1][2], s[2 * ks + 1][3], ph[3], pl4[3]);
                uint32_t voff = (uint32_t)((ks * 16 + (l & 15)) * 272 + (l >> 4) * 16);
                uint32_t tv[8][4], uv[8][4];
#pragma unroll
                for (int dg = 0; dg < 8; dg++) {
                    ldsm4t(bs + 2 * KTB + voff + dg * 32, tv[dg]);
                    ldsm4t(bs + 3 * KTB + voff + dg * 32, uv[dg]);
                }
#pragma unroll
                for (int dg = 0; dg < 8; dg++) {
                    MMA_BF16(o[dg * 2], ph, tv[dg][0], tv[dg][1]);
                    MMA_BF16(o[dg * 2 + 1], ph, tv[dg][2], tv[dg][3]);
                }
#pragma unroll
                for (int dg = 0; dg < 8; dg++) {
                    MMA_BF16(o[dg * 2], ph, uv[dg][0], uv[dg][1]);
                    MMA_BF16(o[dg * 2 + 1], ph, uv[dg][2], uv[dg][3]);
                }
#pragma unroll
                for (int dg = 0; dg < 8; dg++) {
                    MMA_BF16(o[dg * 2], pl4, tv[dg][0], tv[dg][1]);
                    MMA_BF16(o[dg * 2 + 1], pl4, tv[dg][2], tv[dg][3]);
                }
            }
        }
        __syncthreads();
        if (i + 2 < ntile) loadKV(i & 1, k0 + 128);
    }

    float i0 = 1.f / rl0, i1 = 1.f / rl1;
    int m0r = t0 + w * 16 + (l >> 2);
#pragma unroll
    for (int f = 0; f < 16; f++) {
        int col = h * 128 + (f >> 1) * 16 + (f & 1) * 8 + (l & 3) * 2;
        size_t a0 = ((size_t)(b * T_ + m0r)) * C_ + col;
        size_t a1 = a0 + (size_t)8 * C_;
        store_hl(yh + a0, yl + a0, o[f][0] * i0, o[f][1] * i0);
        store_hl(yh + a1, yl + a1, o[f][2] * i1, o[f][3] * i1);
    }
}

// ---------------- launch ------------------------------------------------------
extern "C" void kernel_launch(void* const* d_in, const int* in_sizes, int n_in,
                              void* d_out, int out_size) {
    const float* x     = (const float*)d_in[0];
    const float* ve    = (const float*)d_in[1];
    const float* Wq    = (const float*)d_in[2];
    const float* Wk    = (const float*)d_in[3];
    const float* Wv    = (const float*)d_in[4];
    const float* Wproj = (const float*)d_in[5];
    const float* Wg    = (const float*)d_in[6];
    const float* cosp  = (const float*)d_in[7];
    const float* sinp  = (const float*)d_in[8];
    const int*   winp  = (const int*)d_in[9];
    float* out = (float*)d_out;

    void *pg, *pxh, *pxl, *pyh, *pyl;
    void *pqh, *pql, *pkh, *pkl, *pvh, *pvl;
    void *pwqh, *pwql, *pwkh, *pwkl, *pwvh, *pwvl, *pwph, *pwpl;
    cudaGetSymbolAddress(&pg,  g_gate);
    cudaGetSymbolAddress(&pxh, g_xh);  cudaGetSymbolAddress(&pxl, g_xl);
    cudaGetSymbolAddress(&pyh, g_yh);  cudaGetSymbolAddress(&pyl, g_yl);
    cudaGetSymbolAddress(&pqh, g_qh);  cudaGetSymbolAddress(&pql, g_ql);
    cudaGetSymbolAddress(&pkh, g_kh);  cudaGetSymbolAddress(&pkl, g_kl);
    cudaGetSymbolAddress(&pvh, g_vh);  cudaGetSymbolAddress(&pvl, g_vl);
    cudaGetSymbolAddress(&pwqh, g_wqh); cudaGetSymbolAddress(&pwql, g_wql);
    cudaGetSymbolAddress(&pwkh, g_wkh); cudaGetSymbolAddress(&pwkl, g_wkl);
    cudaGetSymbolAddress(&pwvh, g_wvh); cudaGetSymbolAddress(&pwvl, g_wvl);
    cudaGetSymbolAddress(&pwph, g_wph); cudaGetSymbolAddress(&pwpl, g_wpl);

    cudaFuncSetAttribute(gemm_mma<0>, cudaFuncAttributeMaxDynamicSharedMemorySize, GEMM_SMEM);
    cudaFuncSetAttribute(gemm_mma<1>, cudaFuncAttributeMaxDynamicSharedMemorySize, GEMM_SMEM);
    cudaFuncSetAttribute(gemm_mma<2>, cudaFuncAttributeMaxDynamicSharedMemorySize, GEMM_SMEM);
    cudaFuncSetAttribute(attn_mma, cudaFuncAttributeMaxDynamicSharedMemorySize, ATT_SMEM);

    // 0) splits
    split_kernel<<<M_*C_/1024, 256>>>(x, (__nv_bfloat16*)pxh, (__nv_bfloat16*)pxl, M_*C_);
    wsplit_kernel<<<dim3(C_*C_/1024, 4), 256>>>(
        Wq, Wk, Wv, Wproj,
        (__nv_bfloat16*)pwqh, (__nv_bfloat16*)pwql,
        (__nv_bfloat16*)pwkh, (__nv_bfloat16*)pwkl,
        (__nv_bfloat16*)pwvh, (__nv_bfloat16*)pwvl,
        (__nv_bfloat16*)pwph, (__nv_bfloat16*)pwpl);

    // 1) gate
    gate_kernel<<<(M_ * H_ + 255) / 256, 256>>>(x, Wg, (float*)pg);

    // 2) q, k projections (fused rope+rms+split), v projection (fused gate+split)
    dim3 ggrid(C_ / 128, M_ / 128);
    gemm_mma<1><<<ggrid, 256, GEMM_SMEM>>>((const __nv_bfloat16*)pxh, (const __nv_bfloat16*)pxl,
                                           (const __nv_bfloat16*)pwqh, (const __nv_bfloat16*)pwql,
                                           nullptr, (__nv_bfloat16*)pqh, (__nv_bfloat16*)pql,
                                           nullptr, nullptr, cosp, sinp);
    gemm_mma<1><<<ggrid, 256, GEMM_SMEM>>>((const __nv_bfloat16*)pxh, (const __nv_bfloat16*)pxl,
                                           (const __nv_bfloat16*)pwkh, (const __nv_bfloat16*)pwkl,
                                           nullptr, (__nv_bfloat16*)pkh, (__nv_bfloat16*)pkl,
                                           nullptr, nullptr, cosp, sinp);
    gemm_mma<2><<<ggrid, 256, GEMM_SMEM>>>((const __nv_bfloat16*)pxh, (const __nv_bfloat16*)pxl,
                                           (const __nv_bfloat16*)pwvh, (const __nv_bfloat16*)pwvl,
                                           nullptr, (__nv_bfloat16*)pvh, (__nv_bfloat16*)pvl,
                                           ve, (const float*)pg, nullptr, nullptr);

    // 3) tensor-core attention -> bf16 hi/lo y
    attn_mma<<<dim3(T_ / 128, H_, B_), 256, ATT_SMEM>>>(
        (const __nv_bfloat16*)pqh, (const __nv_bfloat16*)pql,
        (const __nv_bfloat16*)pkh, (const __nv_bfloat16*)pkl,
        (const __nv_bfloat16*)pvh, (const __nv_bfloat16*)pvl,
        (__nv_bfloat16*)pyh, (__nv_bfloat16*)pyl, winp);

    // 4) output projection
    gemm_mma<0><<<ggrid, 256, GEMM_SMEM>>>((const __nv_bfloat16*)pyh, (const __nv_bfloat16*)pyl,
                                           (const __nv_bfloat16*)pwph, (const __nv_bfloat16*)pwpl,
                                           out, nullptr, nullptr, nullptr, nullptr,
                                           nullptr, nullptr);
}

// round 9
// speedup vs baseline: 1.2153x; 1.1617x over previous
#include <cuda_runtime.h>
#include <cuda_fp16.h>
#include <math.h>
#include <stdint.h>

#define B_ 2
#define T_ 2048
#define C_ 2048
#define H_ 16
#define D_ 128
#define M_ (B_*T_)   // 4096 rows

// ---------------- scratch (device globals; no allocation allowed) -------------
__device__ float g_gate[M_*H_];
__device__ __half g_xh[M_*C_],  g_xl[M_*C_];
__device__ __half g_yh[M_*C_],  g_yl[M_*C_];
__device__ __half g_qh[M_*C_],  g_ql[M_*C_];   // [b][h][t][d]
__device__ __half g_kh[M_*C_],  g_kl[M_*C_];   // [b][h][t][d]
__device__ __half g_vh[M_*C_];                 // [b][h][t][d] single fp16
__device__ __half g_wqh[C_*C_], g_wql[C_*C_];
__device__ __half g_wkh[C_*C_], g_wkl[C_*C_];
__device__ __half g_wvh[C_*C_];
__device__ __half g_wph[C_*C_];

// ================= PTX helpers =================
__device__ __forceinline__ uint32_t smem_u32(const void* p) {
    uint32_t a;
    asm("{ .reg .u64 t; cvta.to.shared.u64 t, %1; cvt.u32.u64 %0, t; }" : "=r"(a) : "l"(p));
    return a;
}
__device__ __forceinline__ void cpasync16(uint32_t saddr, const void* gaddr) {
    asm volatile("cp.async.cg.shared.global [%0], [%1], 16;" :: "r"(saddr), "l"(gaddr) : "memory");
}
__device__ __forceinline__ void ldsm4(uint32_t addr, uint32_t* r) {
    asm volatile("ldmatrix.sync.aligned.m8n8.x4.shared.b16 {%0,%1,%2,%3}, [%4];"
                 : "=r"(r[0]), "=r"(r[1]), "=r"(r[2]), "=r"(r[3]) : "r"(addr));
}
__device__ __forceinline__ void ldsm4t(uint32_t addr, uint32_t* r) {
    asm volatile("ldmatrix.sync.aligned.m8n8.x4.trans.shared.b16 {%0,%1,%2,%3}, [%4];"
                 : "=r"(r[0]), "=r"(r[1]), "=r"(r[2]), "=r"(r[3]) : "r"(addr));
}
__device__ __forceinline__ float ex2f(float x) {
    float y; asm("ex2.approx.f32 %0, %1;" : "=f"(y) : "f"(x)); return y;
}
#define MMA_F16(Cf, Af, B0, B1)                                               \
    asm volatile("mma.sync.aligned.m16n8k16.row.col.f32.f16.f16.f32 "          \
        "{%0,%1,%2,%3},{%4,%5,%6,%7},{%8,%9},{%0,%1,%2,%3};"                   \
        : "+f"((Cf)[0]), "+f"((Cf)[1]), "+f"((Cf)[2]), "+f"((Cf)[3])           \
        : "r"((Af)[0]), "r"((Af)[1]), "r"((Af)[2]), "r"((Af)[3]),              \
          "r"(B0), "r"(B1))

__device__ __forceinline__ void store_hl(__half* ph, __half* pl, float a, float b) {
    __half ha = __float2half(a), hb = __float2half(b);
    *reinterpret_cast<__half2*>(ph) = __halves2half2(ha, hb);
    *reinterpret_cast<__half2*>(pl) = __halves2half2(
        __float2half(a - __half2float(ha)),
        __float2half(b - __half2float(hb)));
}
__device__ __forceinline__ void packhl(float a, float b, uint32_t& hi, uint32_t& lo) {
    __half ha = __float2half(a), hb = __float2half(b);
    __half2 hv = __halves2half2(ha, hb);
    hi = *reinterpret_cast<uint32_t*>(&hv);
    __half2 lv = __halves2half2(__float2half(a - __half2float(ha)),
                                __float2half(b - __half2float(hb)));
    lo = *reinterpret_cast<uint32_t*>(&lv);
}

// ---------------- fp32 -> fp16 hi/lo split -------------------------------------
__global__ void split_kernel(const float* __restrict__ src,
                             __half* __restrict__ hi, __half* __restrict__ lo, int n) {
    int i = (blockIdx.x * blockDim.x + threadIdx.x) * 4;
    if (i >= n) return;
    float4 v = *(const float4*)(src + i);
    __half h0 = __float2half(v.x), h1 = __float2half(v.y);
    __half h2 = __float2half(v.z), h3 = __float2half(v.w);
    ((__half2*)(hi + i))[0] = __halves2half2(h0, h1);
    ((__half2*)(hi + i))[1] = __halves2half2(h2, h3);
    ((__half2*)(lo + i))[0] = __halves2half2(
        __float2half(v.x - __half2float(h0)), __float2half(v.y - __half2float(h1)));
    ((__half2*)(lo + i))[1] = __halves2half2(
        __float2half(v.z - __half2float(h2)), __float2half(v.w - __half2float(h3)));
}

// batched weight conversion: Wq,Wk -> hi/lo ; Wv,Wproj -> single
__global__ void wsplit_kernel(const float* __restrict__ w0, const float* __restrict__ w1,
                              const float* __restrict__ w2, const float* __restrict__ w3,
                              __half* __restrict__ h0, __half* __restrict__ l0,
                              __half* __restrict__ h1, __half* __restrict__ l1,
                              __half* __restrict__ h2, __half* __restrict__ h3) {
    int which = blockIdx.y;
    const float* src = (which == 0) ? w0 : (which == 1) ? w1 : (which == 2) ? w2 : w3;
    __half* hi = (which == 0) ? h0 : (which == 1) ? h1 : (which == 2) ? h2 : h3;
    int i = (blockIdx.x * blockDim.x + threadIdx.x) * 4;
    float4 v = *(const float4*)(src + i);
    __half a0 = __float2half(v.x), a1 = __float2half(v.y);
    __half a2 = __float2half(v.z), a3 = __float2half(v.w);
    ((__half2*)(hi + i))[0] = __halves2half2(a0, a1);
    ((__half2*)(hi + i))[1] = __halves2half2(a2, a3);
    if (which < 2) {
        __half* lo = (which == 0) ? l0 : l1;
        ((__half2*)(lo + i))[0] = __halves2half2(
            __float2half(v.x - __half2float(a0)), __float2half(v.y - __half2float(a1)));
        ((__half2*)(lo + i))[1] = __halves2half2(
            __float2half(v.z - __half2float(a2)), __float2half(v.w - __half2float(a3)));
    }
}

// ---------------- gate = 3*sigmoid(x[:, :12] @ Wg^T) --------------------------
__global__ void gate_kernel(const float* __restrict__ x, const float* __restrict__ Wg,
                            float* __restrict__ gate) {
    int idx = blockIdx.x * blockDim.x + threadIdx.x;
    if (idx >= M_ * H_) return;
    int m = idx >> 4, h = idx & 15;
    float s = 0.f;
#pragma unroll
    for (int j = 0; j < 12; j++) s += x[(size_t)m * C_ + j] * Wg[h * 12 + j];
    gate[idx] = 3.f / (1.f + __expf(-s));
}

// ---------------- mma.sync fp16 split GEMM -------------------------------------
// NPROD=3: AhBh + AhBl + AlBh (logit path). NPROD=2: AhBh + AlBh (value path, B single).
// 256 threads, 4x2 warps (32x64 warp tile), BK=32, 3 stages, frag double-buffering.
#define RS_B 80
#define ARR_B (128 * RS_B)
#define NSTAGE 3
#define NCHUNK 64

struct Frag {
    uint32_t a_h[2][4], a_l[2][4];
    uint32_t b_h[8][2], b_l[8][2];
};

template<int EPI, int NPROD>
__global__ __launch_bounds__(256, 1) void gemm_mma(
    const __half* __restrict__ Ah, const __half* __restrict__ Al,
    const __half* __restrict__ Bh, const __half* __restrict__ Bl,
    float* __restrict__ Cout,
    __half* __restrict__ Oh, __half* __restrict__ Ol,
    const float* __restrict__ ve, const float* __restrict__ gate,
    const float* __restrict__ cosp, const float* __restrict__ sinp) {
    constexpr int NARR = NPROD + 1;          // 4 or 3 arrays per stage
    constexpr int STGB = NARR * ARR_B;
    extern __shared__ char smc[];
    const uint32_t sb = smem_u32(smc);
    const int tid = threadIdx.x;
    const int wid = tid >> 5, lane = tid & 31;
    const int warp_m = wid & 3, warp_n = wid >> 2;   // 4 x 2
    const int arow0 = blockIdx.y * 128, brow0 = blockIdx.x * 128;

    auto load_chunk = [&](int stage, int chunk) {
        const int k0 = chunk * 32;
        uint32_t stg = sb + stage * STGB;
#pragma unroll
        for (int j = 0; j < NARR * 2; j++) {
            int u = tid + j * 256;
            int arr = u >> 9;
            int rc = u & 511;
            int r = rc >> 2, c = rc & 3;
            uint32_t sa = stg + arr * ARR_B + r * RS_B + c * 16;
            const __half* src;
            size_t off;
            if (arr == 0)      { src = Ah; off = (size_t)(arow0 + r) * C_ + k0 + c * 8; }
            else if (arr == 1) { src = Al; off = (size_t)(arow0 + r) * C_ + k0 + c * 8; }
            else if (arr == 2) { src = Bh; off = (size_t)(brow0 + r) * C_ + k0 + c * 8; }
            else               { src = Bl; off = (size_t)(brow0 + r) * C_ + k0 + c * 8; }
            cpasync16(sa, src + off);
        }
        asm volatile("cp.async.commit_group;" ::: "memory");
    };

    const uint32_t a_lane_off = (uint32_t)((warp_m * 32 + (lane & 15)) * RS_B + (lane >> 4) * 16);
    const uint32_t b_lane_off = (uint32_t)((warp_n * 64 + (lane & 15)) * RS_B + (lane >> 4) * 16);

    auto ldfr = [&](Frag& F, uint32_t stg, uint32_t koff) {
#pragma unroll
        for (int mi = 0; mi < 2; mi++) {
            ldsm4(stg + 0 * ARR_B + a_lane_off + mi * 16 * RS_B + koff, F.a_h[mi]);
            ldsm4(stg + 1 * ARR_B + a_lane_off + mi * 16 * RS_B + koff, F.a_l[mi]);
        }
#pragma unroll
        for (int nf4 = 0; nf4 < 4; nf4++) {
            uint32_t t[4];
            ldsm4(stg + 2 * ARR_B + b_lane_off + nf4 * 16 * RS_B + koff, t);
            F.b_h[nf4 * 2][0] = t[0]; F.b_h[nf4 * 2][1] = t[2];
            F.b_h[nf4 * 2 + 1][0] = t[1]; F.b_h[nf4 * 2 + 1][1] = t[3];
            if (NPROD == 3) {
                ldsm4(stg + 3 * ARR_B + b_lane_off + nf4 * 16 * RS_B + koff, t);
                F.b_l[nf4 * 2][0] = t[0]; F.b_l[nf4 * 2][1] = t[2];
                F.b_l[nf4 * 2 + 1][0] = t[1]; F.b_l[nf4 * 2 + 1][1] = t[3];
            }
        }
    };

    float acc[2][8][4];
#pragma unroll
    for (int mi = 0; mi < 2; mi++)
#pragma unroll
        for (int nf = 0; nf < 8; nf++)
#pragma unroll
            for (int q = 0; q < 4; q++) acc[mi][nf][q] = 0.f;

    auto mmab = [&](Frag& F) {
#pragma unroll
        for (int mi = 0; mi < 2; mi++)
#pragma unroll
            for (int nf = 0; nf < 8; nf++) MMA_F16(acc[mi][nf], F.a_h[mi], F.b_h[nf][0], F.b_h[nf][1]);
        if (NPROD == 3) {
#pragma unroll
            for (int mi = 0; mi < 2; mi++)
#pragma unroll
                for (int nf = 0; nf < 8; nf++) MMA_F16(acc[mi][nf], F.a_h[mi], F.b_l[nf][0], F.b_l[nf][1]);
        }
#pragma unroll
        for (int mi = 0; mi < 2; mi++)
#pragma unroll
            for (int nf = 0; nf < 8; nf++) MMA_F16(acc[mi][nf], F.a_l[mi], F.b_h[nf][0], F.b_h[nf][1]);
    };

    // prologue
    load_chunk(0, 0);
    load_chunk(1, 1);
    load_chunk(2, 2);
    asm volatile("cp.async.wait_group 2;" ::: "memory");
    __syncthreads();

    Frag Fa, Fb;
    ldfr(Fa, sb, 0);

    for (int i = 0; i < NCHUNK; i++) {
        uint32_t stg = sb + (i % NSTAGE) * STGB;
        ldfr(Fb, stg, 32);           // chunk i ks1
        mmab(Fa);                    // chunk i ks0
        if (i < NCHUNK - 1) {
            if (i < NCHUNK - 2) asm volatile("cp.async.wait_group 1;" ::: "memory");
            else                asm volatile("cp.async.wait_group 0;" ::: "memory");
            __syncthreads();         // publish chunk i+1; fence stage(i)
            uint32_t stg2 = sb + ((i + 1) % NSTAGE) * STGB;
            ldfr(Fa, stg2, 0);
            if (i + 3 < NCHUNK) load_chunk(i % NSTAGE, i + 3);
        }
        mmab(Fb);                    // chunk i ks1
    }

    if (EPI == 1) {
        // stage acc tile to smem, then rope+rms+split per row (hi/lo fp16 out)
        __syncthreads();
        float* S = (float*)smc;      // 128 x 132
        const int rbase = warp_m * 32 + (lane >> 2);
        const int cbase = warp_n * 64 + (lane & 3) * 2;
#pragma unroll
        for (int mi = 0; mi < 2; mi++)
#pragma unroll
            for (int nf = 0; nf < 8; nf++) {
                int r = rbase + mi * 16, c = cbase + nf * 8;
                S[r * 132 + c] = acc[mi][nf][0];
                S[r * 132 + c + 1] = acc[mi][nf][1];
                S[(r + 8) * 132 + c] = acc[mi][nf][2];
                S[(r + 8) * 132 + c + 1] = acc[mi][nf][3];
            }
        __syncthreads();
        const int hh = brow0 >> 7;
        const int d0 = lane * 2;
#pragma unroll 4
        for (int rr = wid * 16; rr < wid * 16 + 16; rr++) {
            int m = arow0 + rr, b = m >> 11, t = m & 2047;
            float xa0 = S[rr * 132 + d0],      xa1 = S[rr * 132 + d0 + 1];
            float xb0 = S[rr * 132 + d0 + 64], xb1 = S[rr * 132 + d0 + 65];
            float2 cc = *(const float2*)(cosp + t * 64 + d0);
            float2 sn = *(const float2*)(sinp + t * 64 + d0);
            float y1a = xa0 * cc.x + xb0 * sn.x;
            float y1b = xa1 * cc.y + xb1 * sn.y;
            float y2a = xb0 * cc.x - xa0 * sn.x;
            float y2b = xb1 * cc.y - xa1 * sn.y;
            float ss = y1a * y1a + y1b * y1b + y2a * y2a + y2b * y2b;
#pragma unroll
            for (int off = 16; off; off >>= 1) ss += __shfl_xor_sync(0xffffffffu, ss, off);
            float r = rsqrtf(ss * (1.f / 128.f) + 1e-6f) * 1.2f;
            size_t ob = ((size_t)(b * H_ + hh) * T_ + t) * D_;
            store_hl(Oh + ob + d0, Ol + ob + d0, y1a * r, y1b * r);
            store_hl(Oh + ob + d0 + 64, Ol + ob + d0 + 64, y2a * r, y2b * r);
        }
        return;
    }

    const int r0w = arow0 + warp_m * 32 + (lane >> 2);
    const int c0w = brow0 + warp_n * 64 + (lane & 3) * 2;
#pragma unroll
    for (int mi = 0; mi < 2; mi++) {
#pragma unroll
        for (int nf = 0; nf < 8; nf++) {
            int n = c0w + nf * 8;
            int m0 = r0w + mi * 16;
            int m1 = m0 + 8;
            float v0 = acc[mi][nf][0], v1 = acc[mi][nf][1];
            float v2 = acc[mi][nf][2], v3 = acc[mi][nf][3];
            if (EPI == 2) {
                float g0 = gate[m0 * H_ + (n >> 7)];
                float g1 = gate[m1 * H_ + (n >> 7)];
                const float* ve0 = ve + (size_t)m0 * C_ + n;
                const float* ve1 = ve + (size_t)m1 * C_ + n;
                v0 += g0 * ve0[0]; v1 += g0 * ve0[1];
                v2 += g1 * ve1[0]; v3 += g1 * ve1[1];
                int hh = n >> 7, dd = n & 127;
                size_t o0 = ((size_t)((m0 >> 11) * H_ + hh) * T_ + (m0 & 2047)) * D_ + dd;
                size_t o1 = ((size_t)((m1 >> 11) * H_ + hh) * T_ + (m1 & 2047)) * D_ + dd;
                *reinterpret_cast<__half2*>(Oh + o0) = __floats2half2_rn(v0, v1);
                *reinterpret_cast<__half2*>(Oh + o1) = __floats2half2_rn(v2, v3);
            } else {
                *(float2*)(Cout + (size_t)m0 * C_ + n) = make_float2(v0, v1);
                *(float2*)(Cout + (size_t)m1 * C_ + n) = make_float2(v2, v3);
            }
        }
    }
}

// ---------------- tensor-core flash attention (fp16) --------------------------
// 256 threads (8 warps), q-tile 128 rows, KV tile 64, 2 stages (Kh|Kl|Vh).
#define QTB (128 * 272)              // 34816
#define KTB (64 * 272)               // 17408
#define KV_OFF (2 * QTB)             // 69632
#define STG (3 * KTB)                // 52224
#define ATT_SMEM (2 * QTB + 2 * STG) // 174080

__global__ __launch_bounds__(256, 1) void attn_mma(
    const __half* __restrict__ qh, const __half* __restrict__ ql,
    const __half* __restrict__ kh, const __half* __restrict__ kl,
    const __half* __restrict__ vh,
    __half* __restrict__ yh, __half* __restrict__ yl,
    const int* __restrict__ winp) {
    extern __shared__ char smc[];
    const uint32_t sb = smem_u32(smc);
    const int tid = threadIdx.x, w = tid >> 5, l = tid & 31;
    const int t0 = blockIdx.x * 128, h = blockIdx.y, b = blockIdx.z;
    int win = *winp;
    if (win <= 0 || win >= T_) win = T_;
    const size_t hb = (size_t)(b * H_ + h) * ((size_t)T_ * D_);

    // Q hi/lo tiles (128 rows)
#pragma unroll
    for (int j = 0; j < 8; j++) {
        int u = tid + j * 256;
        int r = u >> 4, c = u & 15;
        uint32_t so = (uint32_t)(r * 272 + c * 16);
        size_t go = hb + (size_t)(t0 + r) * D_ + c * 8;
        cpasync16(sb + so, qh + go);
        cpasync16(sb + QTB + so, ql + go);
    }
    asm volatile("cp.async.commit_group;" ::: "memory");

    int start = t0 - win;
    if (start < 0) start = 0;
    start &= ~63;
    const int ntile = ((t0 + 64 - start) >> 6) + 1;

    auto loadKV = [&](int stg, int k0) {
        uint32_t bs = sb + KV_OFF + stg * STG;
#pragma unroll
        for (int j = 0; j < 12; j++) {
            int u = tid + j * 256;          // 0..3071
            int arr = u >> 10;
            int rc = u & 1023;
            int r = rc >> 4, c = rc & 15;
            uint32_t so = (uint32_t)(arr * KTB + r * 272 + c * 16);
            size_t go = hb + (size_t)(k0 + r) * D_ + c * 8;
            const __half* src = (arr == 0) ? kh : (arr == 1) ? kl : vh;
            cpasync16(bs + so, src + go);
        }
        asm volatile("cp.async.commit_group;" ::: "memory");
    };
    loadKV(0, start);
    if (ntile > 1) loadKV(1, start + 64);

    float o[16][4];
#pragma unroll
    for (int f = 0; f < 16; f++)
#pragma unroll
        for (int q = 0; q < 4; q++) o[f][q] = 0.f;
    float rm0 = -1e4f, rm1 = -1e4f, rl0 = 0.f, rl1 = 0.f;
    const float SC2 = 0.1275187989f;   // 1/sqrt(128) * log2(e)

    const uint32_t aoff = (uint32_t)((w * 16 + (l & 15)) * 272 + (l >> 4) * 16);
    const uint32_t boff = (uint32_t)((l & 15) * 272 + (l >> 4) * 16);
    const int r0 = t0 + w * 16 + (l >> 2), r1 = r0 + 8;
    const int wr_min = t0 + w * 16, wr_max = t0 + w * 16 + 15;

    for (int i = 0; i < ntile; i++) {
        int k0 = start + i * 64;
        if (i + 1 < ntile) asm volatile("cp.async.wait_group 1;" ::: "memory");
        else               asm volatile("cp.async.wait_group 0;" ::: "memory");
        __syncthreads();
        uint32_t bs = sb + KV_OFF + (i & 1) * STG;

        bool active = (k0 <= wr_max) && (k0 + 63 >= wr_min - win);
        if (active) {
            // ---- S = QhKh + QhKl + QlKh (3-product, logit path) ----
            float s[8][4];
#pragma unroll
            for (int f = 0; f < 8; f++)
#pragma unroll
                for (int q = 0; q < 4; q++) s[f][q] = 0.f;
#pragma unroll
            for (int ks = 0; ks < 8; ks++) {
                uint32_t aq[4], al4[4];
                uint32_t tk[4][4], uk[4][4];
                ldsm4(sb + aoff + ks * 32, aq);
                ldsm4(sb + QTB + aoff + ks * 32, al4);
#pragma unroll
                for (int ng = 0; ng < 4; ng++) {
                    ldsm4(bs + boff + ng * 16 * 272 + ks * 32, tk[ng]);
                    ldsm4(bs + KTB + boff + ng * 16 * 272 + ks * 32, uk[ng]);
                }
#pragma unroll
                for (int ng = 0; ng < 4; ng++) {
                    MMA_F16(s[ng * 2], aq, tk[ng][0], tk[ng][2]);
                    MMA_F16(s[ng * 2 + 1], aq, tk[ng][1], tk[ng][3]);
                }
#pragma unroll
                for (int ng = 0; ng < 4; ng++) {
                    MMA_F16(s[ng * 2], aq, uk[ng][0], uk[ng][2]);
                    MMA_F16(s[ng * 2 + 1], aq, uk[ng][1], uk[ng][3]);
                }
#pragma unroll
                for (int ng = 0; ng < 4; ng++) {
                    MMA_F16(s[ng * 2], al4, tk[ng][0], tk[ng][2]);
                    MMA_F16(s[ng * 2 + 1], al4, tk[ng][1], tk[ng][3]);
                }
            }

            // ---- masked online softmax (exp2 domain) ----
            float mx0 = -1e30f, mx1 = -1e30f;
#pragma unroll
            for (int nf = 0; nf < 8; nf++) {
                int c0 = k0 + nf * 8 + (l & 3) * 2, c1 = c0 + 1;
                float x0 = (c0 <= r0 && r0 - c0 <= win) ? s[nf][0] * SC2 : -1e30f;
                float x1 = (c1 <= r0 && r0 - c1 <= win) ? s[nf][1] * SC2 : -1e30f;
                float x2 = (c0 <= r1 && r1 - c0 <= win) ? s[nf][2] * SC2 : -1e30f;
                float x3 = (c1 <= r1 && r1 - c1 <= win) ? s[nf][3] * SC2 : -1e30f;
                s[nf][0] = x0; s[nf][1] = x1; s[nf][2] = x2; s[nf][3] = x3;
                mx0 = fmaxf(mx0, fmaxf(x0, x1));
                mx1 = fmaxf(mx1, fmaxf(x2, x3));
            }
            mx0 = fmaxf(mx0, __shfl_xor_sync(0xffffffffu, mx0, 1));
            mx0 = fmaxf(mx0, __shfl_xor_sync(0xffffffffu, mx0, 2));
            mx1 = fmaxf(mx1, __shfl_xor_sync(0xffffffffu, mx1, 1));
            mx1 = fmaxf(mx1, __shfl_xor_sync(0xffffffffu, mx1, 2));
            float mn0 = fmaxf(rm0, fmaxf(mx0, -1e4f));
            float mn1 = fmaxf(rm1, fmaxf(mx1, -1e4f));
            float corr0 = ex2f(rm0 - mn0), corr1 = ex2f(rm1 - mn1);
            float ls0 = 0.f, ls1 = 0.f;
#pragma unroll
            for (int nf = 0; nf < 8; nf++) {
                float p0 = ex2f(s[nf][0] - mn0);
                float p1 = ex2f(s[nf][1] - mn0);
                float p2 = ex2f(s[nf][2] - mn1);
                float p3 = ex2f(s[nf][3] - mn1);
                s[nf][0] = p0; s[nf][1] = p1; s[nf][2] = p2; s[nf][3] = p3;
                ls0 += p0 + p1; ls1 += p2 + p3;
            }
            ls0 += __shfl_xor_sync(0xffffffffu, ls0, 1);
            ls0 += __shfl_xor_sync(0xffffffffu, ls0, 2);
            ls1 += __shfl_xor_sync(0xffffffffu, ls1, 1);
            ls1 += __shfl_xor_sync(0xffffffffu, ls1, 2);
            rl0 = rl0 * corr0 + ls0;
            rl1 = rl1 * corr1 + ls1;
            rm0 = mn0; rm1 = mn1;
#pragma unroll
            for (int f = 0; f < 16; f++) {
                o[f][0] *= corr0; o[f][1] *= corr0;
                o[f][2] *= corr1; o[f][3] *= corr1;
            }

            // ---- O += Ph*Vh + Pl*Vh (2-product, value path) ----
#pragma unroll
            for (int ks = 0; ks < 4; ks++) {
                uint32_t ph[4], pl4[4];
                packhl(s[2 * ks][0], s[2 * ks][1], ph[0], pl4[0]);
                packhl(s[2 * ks][2], s[2 * ks][3], ph[1], pl4[1]);
                packhl(s[2 * ks + 1][0], s[2 * ks + 1][1], ph[2], pl4[2]);
                packhl(s[2 * ks + 1][2], s[2 * ks + 1][3], ph[3], pl4[3]);
                uint32_t voff = (uint32_t)((ks * 16 + (l & 15)) * 272 + (l >> 4) * 16);
                uint32_t tv[8][4];
#pragma unroll
                for (int dg = 0; dg < 8; dg++)
                    ldsm4t(bs + 2 * KTB + voff + dg * 32, tv[dg]);
#pragma unroll
                for (int dg = 0; dg < 8; dg++) {
                    MMA_F16(o[dg * 2], ph, tv[dg][0], tv[dg][1]);
                    MMA_F16(o[dg * 2 + 1], ph, tv[dg][2], tv[dg][3]);
                }
#pragma unroll
                for (int dg = 0; dg < 8; dg++) {
                    MMA_F16(o[dg * 2], pl4, tv[dg][0], tv[dg][1]);
                    MMA_F16(o[dg * 2 + 1], pl4, tv[dg][2], tv[dg][3]);
                }
            }
        }
        __syncthreads();
        if (i + 2 < ntile) loadKV(i & 1, k0 + 128);
    }

    float i0 = 1.f / rl0, i1 = 1.f / rl1;
    int m0r = t0 + w * 16 + (l >> 2);
#pragma unroll
    for (int f = 0; f < 16; f++) {
        int col = h * 128 + (f >> 1) * 16 + (f & 1) * 8 + (l & 3) * 2;
        size_t a0 = ((size_t)(b * T_ + m0r)) * C_ + col;
        size_t a1 = a0 + (size_t)8 * C_;
        store_hl(yh + a0, yl + a0, o[f][0] * i0, o[f][1] * i0);
        store_hl(yh + a1, yl + a1, o[f][2] * i1, o[f][3] * i1);
    }
}

// ---------------- launch ------------------------------------------------------
#define GEMM3_SMEM (3 * 4 * ARR_B)   // 122880
#define GEMM2_SMEM (3 * 3 * ARR_B)   // 92160

extern "C" void kernel_launch(void* const* d_in, const int* in_sizes, int n_in,
                              void* d_out, int out_size) {
    const float* x     = (const float*)d_in[0];
    const float* ve    = (const float*)d_in[1];
    const float* Wq    = (const float*)d_in[2];
    const float* Wk    = (const float*)d_in[3];
    const float* Wv    = (const float*)d_in[4];
    const float* Wproj = (const float*)d_in[5];
    const float* Wg    = (const float*)d_in[6];
    const float* cosp  = (const float*)d_in[7];
    const float* sinp  = (const float*)d_in[8];
    const int*   winp  = (const int*)d_in[9];
    float* out = (float*)d_out;

    void *pg, *pxh, *pxl, *pyh, *pyl;
    void *pqh, *pql, *pkh, *pkl, *pvh;
    void *pwqh, *pwql, *pwkh, *pwkl, *pwvh, *pwph;
    cudaGetSymbolAddress(&pg,  g_gate);
    cudaGetSymbolAddress(&pxh, g_xh);  cudaGetSymbolAddress(&pxl, g_xl);
    cudaGetSymbolAddress(&pyh, g_yh);  cudaGetSymbolAddress(&pyl, g_yl);
    cudaGetSymbolAddress(&pqh, g_qh);  cudaGetSymbolAddress(&pql, g_ql);
    cudaGetSymbolAddress(&pkh, g_kh);  cudaGetSymbolAddress(&pkl, g_kl);
    cudaGetSymbolAddress(&pvh, g_vh);
    cudaGetSymbolAddress(&pwqh, g_wqh); cudaGetSymbolAddress(&pwql, g_wql);
    cudaGetSymbolAddress(&pwkh, g_wkh); cudaGetSymbolAddress(&pwkl, g_wkl);
    cudaGetSymbolAddress(&pwvh, g_wvh); cudaGetSymbolAddress(&pwph, g_wph);

    cudaFuncSetAttribute((const void*)gemm_mma<1,3>, cudaFuncAttributeMaxDynamicSharedMemorySize, GEMM3_SMEM);
    cudaFuncSetAttribute((const void*)gemm_mma<2,2>, cudaFuncAttributeMaxDynamicSharedMemorySize, GEMM2_SMEM);
    cudaFuncSetAttribute((const void*)gemm_mma<0,2>, cudaFuncAttributeMaxDynamicSharedMemorySize, GEMM2_SMEM);
    cudaFuncSetAttribute(attn_mma, cudaFuncAttributeMaxDynamicSharedMemorySize, ATT_SMEM);

    // 0) splits
    split_kernel<<<M_*C_/1024, 256>>>(x, (__half*)pxh, (__half*)pxl, M_*C_);
    wsplit_kernel<<<dim3(C_*C_/1024, 4), 256>>>(
        Wq, Wk, Wv, Wproj,
        (__half*)pwqh, (__half*)pwql,
        (__half*)pwkh, (__half*)pwkl,
        (__half*)pwvh, (__half*)pwph);

    // 1) gate
    gate_kernel<<<(M_ * H_ + 255) / 256, 256>>>(x, Wg, (float*)pg);

    // 2) q, k projections (3-product, rope fused), v projection (2-product, gate fused)
    dim3 ggrid(C_ / 128, M_ / 128);
    gemm_mma<1,3><<<ggrid, 256, GEMM3_SMEM>>>((const __half*)pxh, (const __half*)pxl,
                                              (const __half*)pwqh, (const __half*)pwql,
                                              nullptr, (__half*)pqh, (__half*)pql,
                                              nullptr, nullptr, cosp, sinp);
    gemm_mma<1,3><<<ggrid, 256, GEMM3_SMEM>>>((const __half*)pxh, (const __half*)pxl,
                                              (const __half*)pwkh, (const __half*)pwkl,
                                              nullptr, (__half*)pkh, (__half*)pkl,
                                              nullptr, nullptr, cosp, sinp);
    gemm_mma<2,2><<<ggrid, 256, GEMM2_SMEM>>>((const __half*)pxh, (const __half*)pxl,
                                              (const __half*)pwvh, nullptr,
                                              nullptr, (__half*)pvh, nullptr,
                                              ve, (const float*)pg, nullptr, nullptr);

    // 3) tensor-core attention -> fp16 hi/lo y
    attn_mma<<<dim3(T_ / 128, H_, B_), 256, ATT_SMEM>>>(
        (const __half*)pqh, (const __half*)pql,
        (const __half*)pkh, (const __half*)pkl,
        (const __half*)pvh,
        (__half*)pyh, (__half*)pyl, winp);

    // 4) output projection (2-product)
    gemm_mma<0,2><<<ggrid, 256, GEMM2_SMEM>>>((const __half*)pyh, (const __half*)pyl,
                                              (const __half*)pwph, nullptr,
                                              out, nullptr, nullptr, nullptr, nullptr,
                                              nullptr, nullptr);
}

// round 10
// speedup vs baseline: 1.4147x; 1.1641x over previous
#include <cuda_runtime.h>
#include <cuda_fp16.h>
#include <math.h>
#include <stdint.h>

#define B_ 2
#define T_ 2048
#define C_ 2048
#define H_ 16
#define D_ 128
#define M_ (B_*T_)   // 4096 rows

// ---------------- scratch (device globals; no allocation allowed) -------------
__device__ float g_gate[M_*H_];
__device__ __half g_xh[M_*C_],  g_xl[M_*C_];
__device__ __half g_yh[M_*C_],  g_yl[M_*C_];
__device__ __half g_qh[M_*C_],  g_ql[M_*C_];   // [b][h][t][d]
__device__ __half g_kh[M_*C_],  g_kl[M_*C_];   // [b][h][t][d]
__device__ __half g_vh[M_*C_];                 // [b][h][t][d] single fp16
__device__ __half g_wqh[C_*C_];
__device__ __half g_wkh[C_*C_];
__device__ __half g_wvh[C_*C_];
__device__ __half g_wph[C_*C_];

// ================= PTX helpers =================
__device__ __forceinline__ uint32_t smem_u32(const void* p) {
    uint32_t a;
    asm("{ .reg .u64 t; cvta.to.shared.u64 t, %1; cvt.u32.u64 %0, t; }" : "=r"(a) : "l"(p));
    return a;
}
__device__ __forceinline__ void cpasync16(uint32_t saddr, const void* gaddr) {
    asm volatile("cp.async.cg.shared.global [%0], [%1], 16;" :: "r"(saddr), "l"(gaddr) : "memory");
}
__device__ __forceinline__ void ldsm4(uint32_t addr, uint32_t* r) {
    asm volatile("ldmatrix.sync.aligned.m8n8.x4.shared.b16 {%0,%1,%2,%3}, [%4];"
                 : "=r"(r[0]), "=r"(r[1]), "=r"(r[2]), "=r"(r[3]) : "r"(addr));
}
__device__ __forceinline__ void ldsm4t(uint32_t addr, uint32_t* r) {
    asm volatile("ldmatrix.sync.aligned.m8n8.x4.trans.shared.b16 {%0,%1,%2,%3}, [%4];"
                 : "=r"(r[0]), "=r"(r[1]), "=r"(r[2]), "=r"(r[3]) : "r"(addr));
}
__device__ __forceinline__ float ex2f(float x) {
    float y; asm("ex2.approx.f32 %0, %1;" : "=f"(y) : "f"(x)); return y;
}
#define MMA_F16(Cf, Af, B0, B1)                                               \
    asm volatile("mma.sync.aligned.m16n8k16.row.col.f32.f16.f16.f32 "          \
        "{%0,%1,%2,%3},{%4,%5,%6,%7},{%8,%9},{%0,%1,%2,%3};"                   \
        : "+f"((Cf)[0]), "+f"((Cf)[1]), "+f"((Cf)[2]), "+f"((Cf)[3])           \
        : "r"((Af)[0]), "r"((Af)[1]), "r"((Af)[2]), "r"((Af)[3]),              \
          "r"(B0), "r"(B1))

__device__ __forceinline__ void store_hl(__half* ph, __half* pl, float a, float b) {
    __half ha = __float2half(a), hb = __float2half(b);
    *reinterpret_cast<__half2*>(ph) = __halves2half2(ha, hb);
    *reinterpret_cast<__half2*>(pl) = __halves2half2(
        __float2half(a - __half2float(ha)),
        __float2half(b - __half2float(hb)));
}
__device__ __forceinline__ void packhl(float a, float b, uint32_t& hi, uint32_t& lo) {
    __half ha = __float2half(a), hb = __float2half(b);
    __half2 hv = __halves2half2(ha, hb);
    hi = *reinterpret_cast<uint32_t*>(&hv);
    __half2 lv = __halves2half2(__float2half(a - __half2float(ha)),
                                __float2half(b - __half2float(hb)));
    lo = *reinterpret_cast<uint32_t*>(&lv);
}

// ---------------- fp32 -> fp16 hi/lo split -------------------------------------
__global__ void split_kernel(const float* __restrict__ src,
                             __half* __restrict__ hi, __half* __restrict__ lo, int n) {
    int i = (blockIdx.x * blockDim.x + threadIdx.x) * 4;
    if (i >= n) return;
    float4 v = *(const float4*)(src + i);
    __half h0 = __float2half(v.x), h1 = __float2half(v.y);
    __half h2 = __float2half(v.z), h3 = __float2half(v.w);
    ((__half2*)(hi + i))[0] = __halves2half2(h0, h1);
    ((__half2*)(hi + i))[1] = __halves2half2(h2, h3);
    ((__half2*)(lo + i))[0] = __halves2half2(
        __float2half(v.x - __half2float(h0)), __float2half(v.y - __half2float(h1)));
    ((__half2*)(lo + i))[1] = __halves2half2(
        __float2half(v.z - __half2float(h2)), __float2half(v.w - __half2float(h3)));
}

// batched weight conversion: all four weights -> single fp16
__global__ void wsplit_kernel(const float* __restrict__ w0, const float* __restrict__ w1,
                              const float* __restrict__ w2, const float* __restrict__ w3,
                              __half* __restrict__ h0, __half* __restrict__ h1,
                              __half* __restrict__ h2, __half* __restrict__ h3) {
    int which = blockIdx.y;
    const float* src = (which == 0) ? w0 : (which == 1) ? w1 : (which == 2) ? w2 : w3;
    __half* hi = (which == 0) ? h0 : (which == 1) ? h1 : (which == 2) ? h2 : h3;
    int i = (blockIdx.x * blockDim.x + threadIdx.x) * 4;
    float4 v = *(const float4*)(src + i);
    ((__half2*)(hi + i))[0] = __floats2half2_rn(v.x, v.y);
    ((__half2*)(hi + i))[1] = __floats2half2_rn(v.z, v.w);
}

// ---------------- gate = 3*sigmoid(x[:, :12] @ Wg^T) --------------------------
__global__ void gate_kernel(const float* __restrict__ x, const float* __restrict__ Wg,
                            float* __restrict__ gate) {
    int idx = blockIdx.x * blockDim.x + threadIdx.x;
    if (idx >= M_ * H_) return;
    int m = idx >> 4, h = idx & 15;
    float s = 0.f;
#pragma unroll
    for (int j = 0; j < 12; j++) s += x[(size_t)m * C_ + j] * Wg[h * 12 + j];
    gate[idx] = 3.f / (1.f + __expf(-s));
}

// ---------------- mma.sync fp16 split GEMM (2-product: AhBh + AlBh) ------------
// 256 threads, 4x2 warps (32x64 warp tile), BK=32, 3 stages, frag double-buffering.
#define RS_B 80
#define ARR_B (128 * RS_B)
#define NSTAGE 3
#define NCHUNK 64
#define STGB (3 * ARR_B)            // Ah | Al | Bh
#define GEMM_SMEM (NSTAGE * STGB)   // 92160

struct Frag {
    uint32_t a_h[2][4], a_l[2][4];
    uint32_t b_h[8][2];
};

template<int EPI>
__global__ __launch_bounds__(256, 1) void gemm_mma(
    const __half* __restrict__ Ah, const __half* __restrict__ Al,
    const __half* __restrict__ Bh,
    float* __restrict__ Cout,
    __half* __restrict__ Oh, __half* __restrict__ Ol,
    const float* __restrict__ ve, const float* __restrict__ gate,
    const float* __restrict__ cosp, const float* __restrict__ sinp) {
    extern __shared__ char smc[];
    const uint32_t sb = smem_u32(smc);
    const int tid = threadIdx.x;
    const int wid = tid >> 5, lane = tid & 31;
    const int warp_m = wid & 3, warp_n = wid >> 2;   // 4 x 2
    const int arow0 = blockIdx.y * 128, brow0 = blockIdx.x * 128;

    auto load_chunk = [&](int stage, int chunk) {
        const int k0 = chunk * 32;
        uint32_t stg = sb + stage * STGB;
#pragma unroll
        for (int j = 0; j < 6; j++) {
            int u = tid + j * 256;          // 0..1535
            int arr = u >> 9;
            int rc = u & 511;
            int r = rc >> 2, c = rc & 3;
            uint32_t sa = stg + arr * ARR_B + r * RS_B + c * 16;
            const __half* src;
            size_t off;
            if (arr == 0)      { src = Ah; off = (size_t)(arow0 + r) * C_ + k0 + c * 8; }
            else if (arr == 1) { src = Al; off = (size_t)(arow0 + r) * C_ + k0 + c * 8; }
            else               { src = Bh; off = (size_t)(brow0 + r) * C_ + k0 + c * 8; }
            cpasync16(sa, src + off);
        }
        asm volatile("cp.async.commit_group;" ::: "memory");
    };

    const uint32_t a_lane_off = (uint32_t)((warp_m * 32 + (lane & 15)) * RS_B + (lane >> 4) * 16);
    const uint32_t b_lane_off = (uint32_t)((warp_n * 64 + (lane & 15)) * RS_B + (lane >> 4) * 16);

    auto ldfr = [&](Frag& F, uint32_t stg, uint32_t koff) {
#pragma unroll
        for (int mi = 0; mi < 2; mi++) {
            ldsm4(stg + 0 * ARR_B + a_lane_off + mi * 16 * RS_B + koff, F.a_h[mi]);
            ldsm4(stg + 1 * ARR_B + a_lane_off + mi * 16 * RS_B + koff, F.a_l[mi]);
        }
#pragma unroll
        for (int nf4 = 0; nf4 < 4; nf4++) {
            uint32_t t[4];
            ldsm4(stg + 2 * ARR_B + b_lane_off + nf4 * 16 * RS_B + koff, t);
            F.b_h[nf4 * 2][0] = t[0]; F.b_h[nf4 * 2][1] = t[2];
            F.b_h[nf4 * 2 + 1][0] = t[1]; F.b_h[nf4 * 2 + 1][1] = t[3];
        }
    };

    float acc[2][8][4];
#pragma unroll
    for (int mi = 0; mi < 2; mi++)
#pragma unroll
        for (int nf = 0; nf < 8; nf++)
#pragma unroll
            for (int q = 0; q < 4; q++) acc[mi][nf][q] = 0.f;

    auto mmab = [&](Frag& F) {
#pragma unroll
        for (int mi = 0; mi < 2; mi++)
#pragma unroll
            for (int nf = 0; nf < 8; nf++) MMA_F16(acc[mi][nf], F.a_h[mi], F.b_h[nf][0], F.b_h[nf][1]);
#pragma unroll
        for (int mi = 0; mi < 2; mi++)
#pragma unroll
            for (int nf = 0; nf < 8; nf++) MMA_F16(acc[mi][nf], F.a_l[mi], F.b_h[nf][0], F.b_h[nf][1]);
    };

    // prologue
    load_chunk(0, 0);
    load_chunk(1, 1);
    load_chunk(2, 2);
    asm volatile("cp.async.wait_group 2;" ::: "memory");
    __syncthreads();

    Frag Fa, Fb;
    ldfr(Fa, sb, 0);

    for (int i = 0; i < NCHUNK; i++) {
        uint32_t stg = sb + (i % NSTAGE) * STGB;
        ldfr(Fb, stg, 32);           // chunk i ks1
        mmab(Fa);                    // chunk i ks0
        if (i < NCHUNK - 1) {
            if (i < NCHUNK - 2) asm volatile("cp.async.wait_group 1;" ::: "memory");
            else                asm volatile("cp.async.wait_group 0;" ::: "memory");
            __syncthreads();         // publish chunk i+1; fence stage(i)
            uint32_t stg2 = sb + ((i + 1) % NSTAGE) * STGB;
            ldfr(Fa, stg2, 0);
            if (i + 3 < NCHUNK) load_chunk(i % NSTAGE, i + 3);
        }
        mmab(Fb);                    // chunk i ks1
    }

    if (EPI == 1) {
        // stage acc tile to smem, then rope+rms+split per row (hi/lo fp16 out)
        __syncthreads();
        float* S = (float*)smc;      // 128 x 132
        const int rbase = warp_m * 32 + (lane >> 2);
        const int cbase = warp_n * 64 + (lane & 3) * 2;
#pragma unroll
        for (int mi = 0; mi < 2; mi++)
#pragma unroll
            for (int nf = 0; nf < 8; nf++) {
                int r = rbase + mi * 16, c = cbase + nf * 8;
                S[r * 132 + c] = acc[mi][nf][0];
                S[r * 132 + c + 1] = acc[mi][nf][1];
                S[(r + 8) * 132 + c] = acc[mi][nf][2];
                S[(r + 8) * 132 + c + 1] = acc[mi][nf][3];
            }
        __syncthreads();
        const int hh = brow0 >> 7;
        const int d0 = lane * 2;
#pragma unroll 4
        for (int rr = wid * 16; rr < wid * 16 + 16; rr++) {
            int m = arow0 + rr, b = m >> 11, t = m & 2047;
            float xa0 = S[rr * 132 + d0],      xa1 = S[rr * 132 + d0 + 1];
            float xb0 = S[rr * 132 + d0 + 64], xb1 = S[rr * 132 + d0 + 65];
            float2 cc = *(const float2*)(cosp + t * 64 + d0);
            float2 sn = *(const float2*)(sinp + t * 64 + d0);
            float y1a = xa0 * cc.x + xb0 * sn.x;
            float y1b = xa1 * cc.y + xb1 * sn.y;
            float y2a = xb0 * cc.x - xa0 * sn.x;
            float y2b = xb1 * cc.y - xa1 * sn.y;
            float ss = y1a * y1a + y1b * y1b + y2a * y2a + y2b * y2b;
#pragma unroll
            for (int off = 16; off; off >>= 1) ss += __shfl_xor_sync(0xffffffffu, ss, off);
            float r = rsqrtf(ss * (1.f / 128.f) + 1e-6f) * 1.2f;
            size_t ob = ((size_t)(b * H_ + hh) * T_ + t) * D_;
            store_hl(Oh + ob + d0, Ol + ob + d0, y1a * r, y1b * r);
            store_hl(Oh + ob + d0 + 64, Ol + ob + d0 + 64, y2a * r, y2b * r);
        }
        return;
    }

    const int r0w = arow0 + warp_m * 32 + (lane >> 2);
    const int c0w = brow0 + warp_n * 64 + (lane & 3) * 2;
#pragma unroll
    for (int mi = 0; mi < 2; mi++) {
#pragma unroll
        for (int nf = 0; nf < 8; nf++) {
            int n = c0w + nf * 8;
            int m0 = r0w + mi * 16;
            int m1 = m0 + 8;
            float v0 = acc[mi][nf][0], v1 = acc[mi][nf][1];
            float v2 = acc[mi][nf][2], v3 = acc[mi][nf][3];
            if (EPI == 2) {
                float g0 = gate[m0 * H_ + (n >> 7)];
                float g1 = gate[m1 * H_ + (n >> 7)];
                const float* ve0 = ve + (size_t)m0 * C_ + n;
                const float* ve1 = ve + (size_t)m1 * C_ + n;
                v0 += g0 * ve0[0]; v1 += g0 * ve0[1];
                v2 += g1 * ve1[0]; v3 += g1 * ve1[1];
                int hh = n >> 7, dd = n & 127;
                size_t o0 = ((size_t)((m0 >> 11) * H_ + hh) * T_ + (m0 & 2047)) * D_ + dd;
                size_t o1 = ((size_t)((m1 >> 11) * H_ + hh) * T_ + (m1 & 2047)) * D_ + dd;
                *reinterpret_cast<__half2*>(Oh + o0) = __floats2half2_rn(v0, v1);
                *reinterpret_cast<__half2*>(Oh + o1) = __floats2half2_rn(v2, v3);
            } else {
                *(float2*)(Cout + (size_t)m0 * C_ + n) = make_float2(v0, v1);
                *(float2*)(Cout + (size_t)m1 * C_ + n) = make_float2(v2, v3);
            }
        }
    }
}

// ---------------- tensor-core flash attention (fp16) --------------------------
// 256 threads (8 warps), q-tile 128 rows, KV tile 64, 2 stages (Kh|Kl|Vh).
#define QTB (128 * 272)              // 34816
#define KTB (64 * 272)               // 17408
#define KV_OFF (2 * QTB)             // 69632
#define STG (3 * KTB)                // 52224
#define ATT_SMEM (2 * QTB + 2 * STG) // 174080

__global__ __launch_bounds__(256, 1) void attn_mma(
    const __half* __restrict__ qh, const __half* __restrict__ ql,
    const __half* __restrict__ kh, const __half* __restrict__ kl,
    const __half* __restrict__ vh,
    __half* __restrict__ yh, __half* __restrict__ yl,
    const int* __restrict__ winp) {
    extern __shared__ char smc[];
    const uint32_t sb = smem_u32(smc);
    const int tid = threadIdx.x, w = tid >> 5, l = tid & 31;
    const int t0 = blockIdx.x * 128, h = blockIdx.y, b = blockIdx.z;
    int win = *winp;
    if (win <= 0 || win >= T_) win = T_;
    const size_t hb = (size_t)(b * H_ + h) * ((size_t)T_ * D_);

    // Q hi/lo tiles (128 rows)
#pragma unroll
    for (int j = 0; j < 8; j++) {
        int u = tid + j * 256;
        int r = u >> 4, c = u & 15;
        uint32_t so = (uint32_t)(r * 272 + c * 16);
        size_t go = hb + (size_t)(t0 + r) * D_ + c * 8;
        cpasync16(sb + so, qh + go);
        cpasync16(sb + QTB + so, ql + go);
    }
    asm volatile("cp.async.commit_group;" ::: "memory");

    int start = t0 - win;
    if (start < 0) start = 0;
    start &= ~63;
    const int ntile = ((t0 + 64 - start) >> 6) + 1;

    auto loadKV = [&](int stg, int k0) {
        uint32_t bs = sb + KV_OFF + stg * STG;
#pragma unroll
        for (int j = 0; j < 12; j++) {
            int u = tid + j * 256;          // 0..3071
            int arr = u >> 10;
            int rc = u & 1023;
            int r = rc >> 4, c = rc & 15;
            uint32_t so = (uint32_t)(arr * KTB + r * 272 + c * 16);
            size_t go = hb + (size_t)(k0 + r) * D_ + c * 8;
            const __half* src = (arr == 0) ? kh : (arr == 1) ? kl : vh;
            cpasync16(bs + so, src + go);
        }
        asm volatile("cp.async.commit_group;" ::: "memory");
    };
    loadKV(0, start);
    if (ntile > 1) loadKV(1, start + 64);

    float o[16][4];
#pragma unroll
    for (int f = 0; f < 16; f++)
#pragma unroll
        for (int q = 0; q < 4; q++) o[f][q] = 0.f;
    float rm0 = -1e4f, rm1 = -1e4f, rl0 = 0.f, rl1 = 0.f;
    const float SC2 = 0.1275187989f;   // 1/sqrt(128) * log2(e)

    const uint32_t aoff = (uint32_t)((w * 16 + (l & 15)) * 272 + (l >> 4) * 16);
    const uint32_t boff = (uint32_t)((l & 15) * 272 + (l >> 4) * 16);
    const int r0 = t0 + w * 16 + (l >> 2), r1 = r0 + 8;
    const int wr_min = t0 + w * 16, wr_max = t0 + w * 16 + 15;

    for (int i = 0; i < ntile; i++) {
        int k0 = start + i * 64;
        if (i + 1 < ntile) asm volatile("cp.async.wait_group 1;" ::: "memory");
        else               asm volatile("cp.async.wait_group 0;" ::: "memory");
        __syncthreads();
        uint32_t bs = sb + KV_OFF + (i & 1) * STG;

        bool active = (k0 <= wr_max) && (k0 + 63 >= wr_min - win);
        if (active) {
            // ---- S = QhKh + QhKl + QlKh (3-product, logit path) ----
            float s[8][4];
#pragma unroll
            for (int f = 0; f < 8; f++)
#pragma unroll
                for (int q = 0; q < 4; q++) s[f][q] = 0.f;
#pragma unroll
            for (int ks = 0; ks < 8; ks++) {
                uint32_t aq[4], al4[4];
                uint32_t tk[4][4], uk[4][4];
                ldsm4(sb + aoff + ks * 32, aq);
                ldsm4(sb + QTB + aoff + ks * 32, al4);
#pragma unroll
                for (int ng = 0; ng < 4; ng++) {
                    ldsm4(bs + boff + ng * 16 * 272 + ks * 32, tk[ng]);
                    ldsm4(bs + KTB + boff + ng * 16 * 272 + ks * 32, uk[ng]);
                }
#pragma unroll
                for (int ng = 0; ng < 4; ng++) {
                    MMA_F16(s[ng * 2], aq, tk[ng][0], tk[ng][2]);
                    MMA_F16(s[ng * 2 + 1], aq, tk[ng][1], tk[ng][3]);
                }
#pragma unroll
                for (int ng = 0; ng < 4; ng++) {
                    MMA_F16(s[ng * 2], aq, uk[ng][0], uk[ng][2]);
                    MMA_F16(s[ng * 2 + 1], aq, uk[ng][1], uk[ng][3]);
                }
#pragma unroll
                for (int ng = 0; ng < 4; ng++) {
                    MMA_F16(s[ng * 2], al4, tk[ng][0], tk[ng][2]);
                    MMA_F16(s[ng * 2 + 1], al4, tk[ng][1], tk[ng][3]);
                }
            }

            // ---- masked online softmax (exp2 domain) ----
            float mx0 = -1e30f, mx1 = -1e30f;
#pragma unroll
            for (int nf = 0; nf < 8; nf++) {
                int c0 = k0 + nf * 8 + (l & 3) * 2, c1 = c0 + 1;
                float x0 = (c0 <= r0 && r0 - c0 <= win) ? s[nf][0] * SC2 : -1e30f;
                float x1 = (c1 <= r0 && r0 - c1 <= win) ? s[nf][1] * SC2 : -1e30f;
                float x2 = (c0 <= r1 && r1 - c0 <= win) ? s[nf][2] * SC2 : -1e30f;
                float x3 = (c1 <= r1 && r1 - c1 <= win) ? s[nf][3] * SC2 : -1e30f;
                s[nf][0] = x0; s[nf][1] = x1; s[nf][2] = x2; s[nf][3] = x3;
                mx0 = fmaxf(mx0, fmaxf(x0, x1));
                mx1 = fmaxf(mx1, fmaxf(x2, x3));
            }
            mx0 = fmaxf(mx0, __shfl_xor_sync(0xffffffffu, mx0, 1));
            mx0 = fmaxf(mx0, __shfl_xor_sync(0xffffffffu, mx0, 2));
            mx1 = fmaxf(mx1, __shfl_xor_sync(0xffffffffu, mx1, 1));
            mx1 = fmaxf(mx1, __shfl_xor_sync(0xffffffffu, mx1, 2));
            float mn0 = fmaxf(rm0, fmaxf(mx0, -1e4f));
            float mn1 = fmaxf(rm1, fmaxf(mx1, -1e4f));
            float corr0 = ex2f(rm0 - mn0), corr1 = ex2f(rm1 - mn1);
            float ls0 = 0.f, ls1 = 0.f;
#pragma unroll
            for (int nf = 0; nf < 8; nf++) {
                float p0 = ex2f(s[nf][0] - mn0);
                float p1 = ex2f(s[nf][1] - mn0);
                float p2 = ex2f(s[nf][2] - mn1);
                float p3 = ex2f(s[nf][3] - mn1);
                s[nf][0] = p0; s[nf][1] = p1; s[nf][2] = p2; s[nf][3] = p3;
                ls0 += p0 + p1; ls1 += p2 + p3;
            }
            ls0 += __shfl_xor_sync(0xffffffffu, ls0, 1);
            ls0 += __shfl_xor_sync(0xffffffffu, ls0, 2);
            ls1 += __shfl_xor_sync(0xffffffffu, ls1, 1);
            ls1 += __shfl_xor_sync(0xffffffffu, ls1, 2);
            rl0 = rl0 * corr0 + ls0;
            rl1 = rl1 * corr1 + ls1;
            rm0 = mn0; rm1 = mn1;
#pragma unroll
            for (int f = 0; f < 16; f++) {
                o[f][0] *= corr0; o[f][1] *= corr0;
                o[f][2] *= corr1; o[f][3] *= corr1;
            }

            // ---- O += Ph*Vh + Pl*Vh (2-product, value path) ----
#pragma unroll
            for (int ks = 0; ks < 4; ks++) {
                uint32_t ph[4], pl4[4];
                packhl(s[2 * ks][0], s[2 * ks][1], ph[0], pl4[0]);
                packhl(s[2 * ks][2], s[2 * ks][3], ph[1], pl4[1]);
                packhl(s[2 * ks + 1][0], s[2 * ks + 1][1], ph[2], pl4[2]);
                packhl(s[2 * ks + 1][2], s[2 * ks + 1][3], ph[3], pl4[3]);
                uint32_t voff = (uint32_t)((ks * 16 + (l & 15)) * 272 + (l >> 4) * 16);
                uint32_t tv[8][4];
#pragma unroll
                for (int dg = 0; dg < 8; dg++)
                    ldsm4t(bs + 2 * KTB + voff + dg * 32, tv[dg]);
#pragma unroll
                for (int dg = 0; dg < 8; dg++) {
                    MMA_F16(o[dg * 2], ph, tv[dg][0], tv[dg][1]);
                    MMA_F16(o[dg * 2 + 1], ph, tv[dg][2], tv[dg][3]);
                }
#pragma unroll
                for (int dg = 0; dg < 8; dg++) {
                    MMA_F16(o[dg * 2], pl4, tv[dg][0], tv[dg][1]);
                    MMA_F16(o[dg * 2 + 1], pl4, tv[dg][2], tv[dg][3]);
                }
            }
        }
        __syncthreads();
        if (i + 2 < ntile) loadKV(i & 1, k0 + 128);
    }

    float i0 = 1.f / rl0, i1 = 1.f / rl1;
    int m0r = t0 + w * 16 + (l >> 2);
#pragma unroll
    for (int f = 0; f < 16; f++) {
        int col = h * 128 + (f >> 1) * 16 + (f & 1) * 8 + (l & 3) * 2;
        size_t a0 = ((size_t)(b * T_ + m0r)) * C_ + col;
        size_t a1 = a0 + (size_t)8 * C_;
        store_hl(yh + a0, yl + a0, o[f][0] * i0, o[f][1] * i0);
        store_hl(yh + a1, yl + a1, o[f][2] * i1, o[f][3] * i1);
    }
}

// ---------------- launch ------------------------------------------------------
extern "C" void kernel_launch(void* const* d_in, const int* in_sizes, int n_in,
                              void* d_out, int out_size) {
    const float* x     = (const float*)d_in[0];
    const float* ve    = (const float*)d_in[1];
    const float* Wq    = (const float*)d_in[2];
    const float* Wk    = (const float*)d_in[3];
    const float* Wv    = (const float*)d_in[4];
    const float* Wproj = (const float*)d_in[5];
    const float* Wg    = (const float*)d_in[6];
    const float* cosp  = (const float*)d_in[7];
    const float* sinp  = (const float*)d_in[8];
    const int*   winp  = (const int*)d_in[9];
    float* out = (float*)d_out;

    void *pg, *pxh, *pxl, *pyh, *pyl;
    void *pqh, *pql, *pkh, *pkl, *pvh;
    void *pwqh, *pwkh, *pwvh, *pwph;
    cudaGetSymbolAddress(&pg,  g_gate);
    cudaGetSymbolAddress(&pxh, g_xh);  cudaGetSymbolAddress(&pxl, g_xl);
    cudaGetSymbolAddress(&pyh, g_yh);  cudaGetSymbolAddress(&pyl, g_yl);
    cudaGetSymbolAddress(&pqh, g_qh);  cudaGetSymbolAddress(&pql, g_ql);
    cudaGetSymbolAddress(&pkh, g_kh);  cudaGetSymbolAddress(&pkl, g_kl);
    cudaGetSymbolAddress(&pvh, g_vh);
    cudaGetSymbolAddress(&pwqh, g_wqh); cudaGetSymbolAddress(&pwkh, g_wkh);
    cudaGetSymbolAddress(&pwvh, g_wvh); cudaGetSymbolAddress(&pwph, g_wph);

    cudaFuncSetAttribute((const void*)gemm_mma<0>, cudaFuncAttributeMaxDynamicSharedMemorySize, GEMM_SMEM);
    cudaFuncSetAttribute((const void*)gemm_mma<1>, cudaFuncAttributeMaxDynamicSharedMemorySize, GEMM_SMEM);
    cudaFuncSetAttribute((const void*)gemm_mma<2>, cudaFuncAttributeMaxDynamicSharedMemorySize, GEMM_SMEM);
    cudaFuncSetAttribute(attn_mma, cudaFuncAttributeMaxDynamicSharedMemorySize, ATT_SMEM);

    // 0) splits
    split_kernel<<<M_*C_/1024, 256>>>(x, (__half*)pxh, (__half*)pxl, M_*C_);
    wsplit_kernel<<<dim3(C_*C_/1024, 4), 256>>>(
        Wq, Wk, Wv, Wproj,
        (__half*)pwqh, (__half*)pwkh, (__half*)pwvh, (__half*)pwph);

    // 1) gate
    gate_kernel<<<(M_ * H_ + 255) / 256, 256>>>(x, Wg, (float*)pg);

    // 2) projections: all 2-product (AhBh + AlBh)
    dim3 ggrid(C_ / 128, M_ / 128);
    gemm_mma<1><<<ggrid, 256, GEMM_SMEM>>>((const __half*)pxh, (const __half*)pxl,
                                           (const __half*)pwqh,
                                           nullptr, (__half*)pqh, (__half*)pql,
                                           nullptr, nullptr, cosp, sinp);
    gemm_mma<1><<<ggrid, 256, GEMM_SMEM>>>((const __half*)pxh, (const __half*)pxl,
                                           (const __half*)pwkh,
                                           nullptr, (__half*)pkh, (__half*)pkl,
                                           nullptr, nullptr, cosp, sinp);
    gemm_mma<2><<<ggrid, 256, GEMM_SMEM>>>((const __half*)pxh, (const __half*)pxl,
                                           (const __half*)pwvh,
                                           nullptr, (__half*)pvh, nullptr,
                                           ve, (const float*)pg, nullptr, nullptr);

    // 3) tensor-core attention -> fp16 hi/lo y
    attn_mma<<<dim3(T_ / 128, H_, B_), 256, ATT_SMEM>>>(
        (const __half*)pqh, (const __half*)pql,
        (const __half*)pkh, (const __half*)pkl,
        (const __half*)pvh,
        (__half*)pyh, (__half*)pyl, winp);

    // 4) output projection (2-product)
    gemm_mma<0><<<ggrid, 256, GEMM_SMEM>>>((const __half*)pyh, (const __half*)pyl,
                                           (const __half*)pwph,
                                           out, nullptr, nullptr, nullptr, nullptr,
                                           nullptr, nullptr);
}

// round 11
// speedup vs baseline: 1.6723x; 1.1821x over previous
#include <cuda_runtime.h>
#include <cuda_fp16.h>
#include <math.h>
#include <stdint.h>

#define B_ 2
#define T_ 2048
#define C_ 2048
#define H_ 16
#define D_ 128
#define M_ (B_*T_)   // 4096 rows

// ---------------- scratch (device globals; no allocation allowed) -------------
__device__ float g_gate[M_*H_];
__device__ __half g_xh[M_*C_],  g_xl[M_*C_];
__device__ __half g_yh[M_*C_];
__device__ __half g_qh[M_*C_],  g_ql[M_*C_];   // [b][h][t][d]
__device__ __half g_kh[M_*C_],  g_kl[M_*C_];   // [b][h][t][d]
__device__ __half g_vh[M_*C_];                 // [b][h][t][d] single fp16
__device__ __half g_wqh[C_*C_];
__device__ __half g_wkh[C_*C_];
__device__ __half g_wvh[C_*C_];
__device__ __half g_wph[C_*C_];

// ================= PTX helpers =================
__device__ __forceinline__ uint32_t smem_u32(const void* p) {
    uint32_t a;
    asm("{ .reg .u64 t; cvta.to.shared.u64 t, %1; cvt.u32.u64 %0, t; }" : "=r"(a) : "l"(p));
    return a;
}
__device__ __forceinline__ void cpasync16(uint32_t saddr, const void* gaddr) {
    asm volatile("cp.async.cg.shared.global [%0], [%1], 16;" :: "r"(saddr), "l"(gaddr) : "memory");
}
__device__ __forceinline__ void ldsm4(uint32_t addr, uint32_t* r) {
    asm volatile("ldmatrix.sync.aligned.m8n8.x4.shared.b16 {%0,%1,%2,%3}, [%4];"
                 : "=r"(r[0]), "=r"(r[1]), "=r"(r[2]), "=r"(r[3]) : "r"(addr));
}
__device__ __forceinline__ void ldsm4t(uint32_t addr, uint32_t* r) {
    asm volatile("ldmatrix.sync.aligned.m8n8.x4.trans.shared.b16 {%0,%1,%2,%3}, [%4];"
                 : "=r"(r[0]), "=r"(r[1]), "=r"(r[2]), "=r"(r[3]) : "r"(addr));
}
__device__ __forceinline__ float ex2f(float x) {
    float y; asm("ex2.approx.f32 %0, %1;" : "=f"(y) : "f"(x)); return y;
}
#define MMA_F16(Cf, Af, B0, B1)                                               \
    asm volatile("mma.sync.aligned.m16n8k16.row.col.f32.f16.f16.f32 "          \
        "{%0,%1,%2,%3},{%4,%5,%6,%7},{%8,%9},{%0,%1,%2,%3};"                   \
        : "+f"((Cf)[0]), "+f"((Cf)[1]), "+f"((Cf)[2]), "+f"((Cf)[3])           \
        : "r"((Af)[0]), "r"((Af)[1]), "r"((Af)[2]), "r"((Af)[3]),              \
          "r"(B0), "r"(B1))

__device__ __forceinline__ void store_hl(__half* ph, __half* pl, float a, float b) {
    __half ha = __float2half(a), hb = __float2half(b);
    *reinterpret_cast<__half2*>(ph) = __halves2half2(ha, hb);
    *reinterpret_cast<__half2*>(pl) = __halves2half2(
        __float2half(a - __half2float(ha)),
        __float2half(b - __half2float(hb)));
}
__device__ __forceinline__ void packhl(float a, float b, uint32_t& hi, uint32_t& lo) {
    __half ha = __float2half(a), hb = __float2half(b);
    __half2 hv = __halves2half2(ha, hb);
    hi = *reinterpret_cast<uint32_t*>(&hv);
    __half2 lv = __halves2half2(__float2half(a - __half2float(ha)),
                                __float2half(b - __half2float(hb)));
    lo = *reinterpret_cast<uint32_t*>(&lv);
}

// ---------------- fp32 -> fp16 hi/lo split -------------------------------------
__global__ void split_kernel(const float* __restrict__ src,
                             __half* __restrict__ hi, __half* __restrict__ lo, int n) {
    int i = (blockIdx.x * blockDim.x + threadIdx.x) * 4;
    if (i >= n) return;
    float4 v = *(const float4*)(src + i);
    __half h0 = __float2half(v.x), h1 = __float2half(v.y);
    __half h2 = __float2half(v.z), h3 = __float2half(v.w);
    ((__half2*)(hi + i))[0] = __halves2half2(h0, h1);
    ((__half2*)(hi + i))[1] = __halves2half2(h2, h3);
    ((__half2*)(lo + i))[0] = __halves2half2(
        __float2half(v.x - __half2float(h0)), __float2half(v.y - __half2float(h1)));
    ((__half2*)(lo + i))[1] = __halves2half2(
        __float2half(v.z - __half2float(h2)), __float2half(v.w - __half2float(h3)));
}

// batched weight conversion: all four weights -> single fp16
__global__ void wsplit_kernel(const float* __restrict__ w0, const float* __restrict__ w1,
                              const float* __restrict__ w2, const float* __restrict__ w3,
                              __half* __restrict__ h0, __half* __restrict__ h1,
                              __half* __restrict__ h2, __half* __restrict__ h3) {
    int which = blockIdx.y;
    const float* src = (which == 0) ? w0 : (which == 1) ? w1 : (which == 2) ? w2 : w3;
    __half* hi = (which == 0) ? h0 : (which == 1) ? h1 : (which == 2) ? h2 : h3;
    int i = (blockIdx.x * blockDim.x + threadIdx.x) * 4;
    float4 v = *(const float4*)(src + i);
    ((__half2*)(hi + i))[0] = __floats2half2_rn(v.x, v.y);
    ((__half2*)(hi + i))[1] = __floats2half2_rn(v.z, v.w);
}

// ---------------- gate = 3*sigmoid(x[:, :12] @ Wg^T) --------------------------
__global__ void gate_kernel(const float* __restrict__ x, const float* __restrict__ Wg,
                            float* __restrict__ gate) {
    int idx = blockIdx.x * blockDim.x + threadIdx.x;
    if (idx >= M_ * H_) return;
    int m = idx >> 4, h = idx & 15;
    float s = 0.f;
#pragma unroll
    for (int j = 0; j < 12; j++) s += x[(size_t)m * C_ + j] * Wg[h * 12 + j];
    gate[idx] = 3.f / (1.f + __expf(-s));
}

// ---------------- mma.sync fp16 GEMM -------------------------------------------
// NPROD=2: AhBh + AlBh (logit path). NPROD=1: AhBh (value path).
// 256 threads, 4x2 warps (32x64 warp tile), BK=32, 3 stages, frag double-buffering.
#define RS_B 80
#define ARR_B (128 * RS_B)
#define NSTAGE 3
#define NCHUNK 64

struct Frag {
    uint32_t a_h[2][4], a_l[2][4];
    uint32_t b_h[8][2];
};

template<int EPI, int NPROD>
__global__ __launch_bounds__(256, 1) void gemm_mma(
    const __half* __restrict__ Ah, const __half* __restrict__ Al,
    const __half* __restrict__ Bh,
    float* __restrict__ Cout,
    __half* __restrict__ Oh, __half* __restrict__ Ol,
    const float* __restrict__ ve, const float* __restrict__ gate,
    const float* __restrict__ cosp, const float* __restrict__ sinp) {
    constexpr int NARR = NPROD + 1;            // arrays per stage (A parts + Bh)
    constexpr int STGB = NARR * ARR_B;
    extern __shared__ char smc[];
    const uint32_t sb = smem_u32(smc);
    const int tid = threadIdx.x;
    const int wid = tid >> 5, lane = tid & 31;
    const int warp_m = wid & 3, warp_n = wid >> 2;   // 4 x 2
    const int arow0 = blockIdx.y * 128, brow0 = blockIdx.x * 128;

    auto load_chunk = [&](int stage, int chunk) {
        const int k0 = chunk * 32;
        uint32_t stg = sb + stage * STGB;
#pragma unroll
        for (int j = 0; j < NARR * 2; j++) {
            int u = tid + j * 256;
            int arr = u >> 9;
            int rc = u & 511;
            int r = rc >> 2, c = rc & 3;
            uint32_t sa = stg + arr * ARR_B + r * RS_B + c * 16;
            const __half* src;
            size_t off;
            if (arr < NPROD) {
                src = (arr == 0) ? Ah : Al;
                off = (size_t)(arow0 + r) * C_ + k0 + c * 8;
            } else {
                src = Bh;
                off = (size_t)(brow0 + r) * C_ + k0 + c * 8;
            }
            cpasync16(sa, src + off);
        }
        asm volatile("cp.async.commit_group;" ::: "memory");
    };

    const uint32_t a_lane_off = (uint32_t)((warp_m * 32 + (lane & 15)) * RS_B + (lane >> 4) * 16);
    const uint32_t b_lane_off = (uint32_t)((warp_n * 64 + (lane & 15)) * RS_B + (lane >> 4) * 16);
    const uint32_t b_arr = (uint32_t)(NPROD * ARR_B);

    auto ldfr = [&](Frag& F, uint32_t stg, uint32_t koff) {
#pragma unroll
        for (int mi = 0; mi < 2; mi++) {
            ldsm4(stg + 0 * ARR_B + a_lane_off + mi * 16 * RS_B + koff, F.a_h[mi]);
            if (NPROD == 2)
                ldsm4(stg + 1 * ARR_B + a_lane_off + mi * 16 * RS_B + koff, F.a_l[mi]);
        }
#pragma unroll
        for (int nf4 = 0; nf4 < 4; nf4++) {
            uint32_t t[4];
            ldsm4(stg + b_arr + b_lane_off + nf4 * 16 * RS_B + koff, t);
            F.b_h[nf4 * 2][0] = t[0]; F.b_h[nf4 * 2][1] = t[2];
            F.b_h[nf4 * 2 + 1][0] = t[1]; F.b_h[nf4 * 2 + 1][1] = t[3];
        }
    };

    float acc[2][8][4];
#pragma unroll
    for (int mi = 0; mi < 2; mi++)
#pragma unroll
        for (int nf = 0; nf < 8; nf++)
#pragma unroll
            for (int q = 0; q < 4; q++) acc[mi][nf][q] = 0.f;

    auto mmab = [&](Frag& F) {
#pragma unroll
        for (int mi = 0; mi < 2; mi++)
#pragma unroll
            for (int nf = 0; nf < 8; nf++) MMA_F16(acc[mi][nf], F.a_h[mi], F.b_h[nf][0], F.b_h[nf][1]);
        if (NPROD == 2) {
#pragma unroll
            for (int mi = 0; mi < 2; mi++)
#pragma unroll
                for (int nf = 0; nf < 8; nf++) MMA_F16(acc[mi][nf], F.a_l[mi], F.b_h[nf][0], F.b_h[nf][1]);
        }
    };

    // prologue
    load_chunk(0, 0);
    load_chunk(1, 1);
    load_chunk(2, 2);
    asm volatile("cp.async.wait_group 2;" ::: "memory");
    __syncthreads();

    Frag Fa, Fb;
    ldfr(Fa, sb, 0);

    for (int i = 0; i < NCHUNK; i++) {
        uint32_t stg = sb + (i % NSTAGE) * STGB;
        ldfr(Fb, stg, 32);           // chunk i ks1
        mmab(Fa);                    // chunk i ks0
        if (i < NCHUNK - 1) {
            if (i < NCHUNK - 2) asm volatile("cp.async.wait_group 1;" ::: "memory");
            else                asm volatile("cp.async.wait_group 0;" ::: "memory");
            __syncthreads();         // publish chunk i+1; fence stage(i)
            uint32_t stg2 = sb + ((i + 1) % NSTAGE) * STGB;
            ldfr(Fa, stg2, 0);
            if (i + 3 < NCHUNK) load_chunk(i % NSTAGE, i + 3);
        }
        mmab(Fb);                    // chunk i ks1
    }

    if (EPI == 1) {
        // stage acc tile to smem, then rope+rms+split per row (hi/lo fp16 out)
        __syncthreads();
        float* S = (float*)smc;      // 128 x 132
        const int rbase = warp_m * 32 + (lane >> 2);
        const int cbase = warp_n * 64 + (lane & 3) * 2;
#pragma unroll
        for (int mi = 0; mi < 2; mi++)
#pragma unroll
            for (int nf = 0; nf < 8; nf++) {
                int r = rbase + mi * 16, c = cbase + nf * 8;
                S[r * 132 + c] = acc[mi][nf][0];
                S[r * 132 + c + 1] = acc[mi][nf][1];
                S[(r + 8) * 132 + c] = acc[mi][nf][2];
                S[(r + 8) * 132 + c + 1] = acc[mi][nf][3];
            }
        __syncthreads();
        const int hh = brow0 >> 7;
        const int d0 = lane * 2;
#pragma unroll 4
        for (int rr = wid * 16; rr < wid * 16 + 16; rr++) {
            int m = arow0 + rr, b = m >> 11, t = m & 2047;
            float xa0 = S[rr * 132 + d0],      xa1 = S[rr * 132 + d0 + 1];
            float xb0 = S[rr * 132 + d0 + 64], xb1 = S[rr * 132 + d0 + 65];
            float2 cc = *(const float2*)(cosp + t * 64 + d0);
            float2 sn = *(const float2*)(sinp + t * 64 + d0);
            float y1a = xa0 * cc.x + xb0 * sn.x;
            float y1b = xa1 * cc.y + xb1 * sn.y;
            float y2a = xb0 * cc.x - xa0 * sn.x;
            float y2b = xb1 * cc.y - xa1 * sn.y;
            float ss = y1a * y1a + y1b * y1b + y2a * y2a + y2b * y2b;
#pragma unroll
            for (int off = 16; off; off >>= 1) ss += __shfl_xor_sync(0xffffffffu, ss, off);
            float r = rsqrtf(ss * (1.f / 128.f) + 1e-6f) * 1.2f;
            size_t ob = ((size_t)(b * H_ + hh) * T_ + t) * D_;
            store_hl(Oh + ob + d0, Ol + ob + d0, y1a * r, y1b * r);
            store_hl(Oh + ob + d0 + 64, Ol + ob + d0 + 64, y2a * r, y2b * r);
        }
        return;
    }

    const int r0w = arow0 + warp_m * 32 + (lane >> 2);
    const int c0w = brow0 + warp_n * 64 + (lane & 3) * 2;
#pragma unroll
    for (int mi = 0; mi < 2; mi++) {
#pragma unroll
        for (int nf = 0; nf < 8; nf++) {
            int n = c0w + nf * 8;
            int m0 = r0w + mi * 16;
            int m1 = m0 + 8;
            float v0 = acc[mi][nf][0], v1 = acc[mi][nf][1];
            float v2 = acc[mi][nf][2], v3 = acc[mi][nf][3];
            if (EPI == 2) {
                float g0 = gate[m0 * H_ + (n >> 7)];
                float g1 = gate[m1 * H_ + (n >> 7)];
                const float* ve0 = ve + (size_t)m0 * C_ + n;
                const float* ve1 = ve + (size_t)m1 * C_ + n;
                v0 += g0 * ve0[0]; v1 += g0 * ve0[1];
                v2 += g1 * ve1[0]; v3 += g1 * ve1[1];
                int hh = n >> 7, dd = n & 127;
                size_t o0 = ((size_t)((m0 >> 11) * H_ + hh) * T_ + (m0 & 2047)) * D_ + dd;
                size_t o1 = ((size_t)((m1 >> 11) * H_ + hh) * T_ + (m1 & 2047)) * D_ + dd;
                *reinterpret_cast<__half2*>(Oh + o0) = __floats2half2_rn(v0, v1);
                *reinterpret_cast<__half2*>(Oh + o1) = __floats2half2_rn(v2, v3);
            } else {
                *(float2*)(Cout + (size_t)m0 * C_ + n) = make_float2(v0, v1);
                *(float2*)(Cout + (size_t)m1 * C_ + n) = make_float2(v2, v3);
            }
        }
    }
}

// ---------------- tensor-core flash attention (fp16) --------------------------
// 256 threads (8 warps), q-tile 128 rows, KV tile 64, 2 stages (Kh|Kl|Vh).
#define QTB (128 * 272)              // 34816
#define KTB (64 * 272)               // 17408
#define KV_OFF (2 * QTB)             // 69632
#define STG (3 * KTB)                // 52224
#define ATT_SMEM (2 * QTB + 2 * STG) // 174080

__global__ __launch_bounds__(256, 1) void attn_mma(
    const __half* __restrict__ qh, const __half* __restrict__ ql,
    const __half* __restrict__ kh, const __half* __restrict__ kl,
    const __half* __restrict__ vh,
    __half* __restrict__ yh,
    const int* __restrict__ winp) {
    extern __shared__ char smc[];
    const uint32_t sb = smem_u32(smc);
    const int tid = threadIdx.x, w = tid >> 5, l = tid & 31;
    const int t0 = blockIdx.x * 128, h = blockIdx.y, b = blockIdx.z;
    int win = *winp;
    if (win <= 0 || win >= T_) win = T_;
    const size_t hb = (size_t)(b * H_ + h) * ((size_t)T_ * D_);

    // Q hi/lo tiles (128 rows)
#pragma unroll
    for (int j = 0; j < 8; j++) {
        int u = tid + j * 256;
        int r = u >> 4, c = u & 15;
        uint32_t so = (uint32_t)(r * 272 + c * 16);
        size_t go = hb + (size_t)(t0 + r) * D_ + c * 8;
        cpasync16(sb + so, qh + go);
        cpasync16(sb + QTB + so, ql + go);
    }
    asm volatile("cp.async.commit_group;" ::: "memory");

    int start = t0 - win;
    if (start < 0) start = 0;
    start &= ~63;
    const int ntile = ((t0 + 64 - start) >> 6) + 1;

    auto loadKV = [&](int stg, int k0) {
        uint32_t bs = sb + KV_OFF + stg * STG;
#pragma unroll
        for (int j = 0; j < 12; j++) {
            int u = tid + j * 256;          // 0..3071
            int arr = u >> 10;
            int rc = u & 1023;
            int r = rc >> 4, c = rc & 15;
            uint32_t so = (uint32_t)(arr * KTB + r * 272 + c * 16);
            size_t go = hb + (size_t)(k0 + r) * D_ + c * 8;
            const __half* src = (arr == 0) ? kh : (arr == 1) ? kl : vh;
            cpasync16(bs + so, src + go);
        }
        asm volatile("cp.async.commit_group;" ::: "memory");
    };
    loadKV(0, start);
    if (ntile > 1) loadKV(1, start + 64);

    float o[16][4];
#pragma unroll
    for (int f = 0; f < 16; f++)
#pragma unroll
        for (int q = 0; q < 4; q++) o[f][q] = 0.f;
    float rm0 = -1e4f, rm1 = -1e4f, rl0 = 0.f, rl1 = 0.f;
    const float SC2 = 0.1275187989f;   // 1/sqrt(128) * log2(e)

    const uint32_t aoff = (uint32_t)((w * 16 + (l & 15)) * 272 + (l >> 4) * 16);
    const uint32_t boff = (uint32_t)((l & 15) * 272 + (l >> 4) * 16);
    const int r0 = t0 + w * 16 + (l >> 2), r1 = r0 + 8;
    const int wr_min = t0 + w * 16, wr_max = t0 + w * 16 + 15;

    for (int i = 0; i < ntile; i++) {
        int k0 = start + i * 64;
        if (i + 1 < ntile) asm volatile("cp.async.wait_group 1;" ::: "memory");
        else               asm volatile("cp.async.wait_group 0;" ::: "memory");
        __syncthreads();
        uint32_t bs = sb + KV_OFF + (i & 1) * STG;

        bool active = (k0 <= wr_max) && (k0 + 63 >= wr_min - win);
        if (active) {
            // ---- S = QhKh + QhKl + QlKh (3-product, logit path) ----
            float s[8][4];
#pragma unroll
            for (int f = 0; f < 8; f++)
#pragma unroll
                for (int q = 0; q < 4; q++) s[f][q] = 0.f;
#pragma unroll
            for (int ks = 0; ks < 8; ks++) {
                uint32_t aq[4], al4[4];
                uint32_t tk[4][4], uk[4][4];
                ldsm4(sb + aoff + ks * 32, aq);
                ldsm4(sb + QTB + aoff + ks * 32, al4);
#pragma unroll
                for (int ng = 0; ng < 4; ng++) {
                    ldsm4(bs + boff + ng * 16 * 272 + ks * 32, tk[ng]);
                    ldsm4(bs + KTB + boff + ng * 16 * 272 + ks * 32, uk[ng]);
                }
#pragma unroll
                for (int ng = 0; ng < 4; ng++) {
                    MMA_F16(s[ng * 2], aq, tk[ng][0], tk[ng][2]);
                    MMA_F16(s[ng * 2 + 1], aq, tk[ng][1], tk[ng][3]);
                }
#pragma unroll
                for (int ng = 0; ng < 4; ng++) {
                    MMA_F16(s[ng * 2], aq, uk[ng][0], uk[ng][2]);
                    MMA_F16(s[ng * 2 + 1], aq, uk[ng][1], uk[ng][3]);
                }
#pragma unroll
                for (int ng = 0; ng < 4; ng++) {
                    MMA_F16(s[ng * 2], al4, tk[ng][0], tk[ng][2]);
                    MMA_F16(s[ng * 2 + 1], al4, tk[ng][1], tk[ng][3]);
                }
            }

            // ---- masked online softmax (exp2 domain) ----
            float mx0 = -1e30f, mx1 = -1e30f;
#pragma unroll
            for (int nf = 0; nf < 8; nf++) {
                int c0 = k0 + nf * 8 + (l & 3) * 2, c1 = c0 + 1;
                float x0 = (c0 <= r0 && r0 - c0 <= win) ? s[nf][0] * SC2 : -1e30f;
                float x1 = (c1 <= r0 && r0 - c1 <= win) ? s[nf][1] * SC2 : -1e30f;
                float x2 = (c0 <= r1 && r1 - c0 <= win) ? s[nf][2] * SC2 : -1e30f;
                float x3 = (c1 <= r1 && r1 - c1 <= win) ? s[nf][3] * SC2 : -1e30f;
                s[nf][0] = x0; s[nf][1] = x1; s[nf][2] = x2; s[nf][3] = x3;
                mx0 = fmaxf(mx0, fmaxf(x0, x1));
                mx1 = fmaxf(mx1, fmaxf(x2, x3));
            }
            mx0 = fmaxf(mx0, __shfl_xor_sync(0xffffffffu, mx0, 1));
            mx0 = fmaxf(mx0, __shfl_xor_sync(0xffffffffu, mx0, 2));
            mx1 = fmaxf(mx1, __shfl_xor_sync(0xffffffffu, mx1, 1));
            mx1 = fmaxf(mx1, __shfl_xor_sync(0xffffffffu, mx1, 2));
            float mn0 = fmaxf(rm0, fmaxf(mx0, -1e4f));
            float mn1 = fmaxf(rm1, fmaxf(mx1, -1e4f));
            float corr0 = ex2f(rm0 - mn0), corr1 = ex2f(rm1 - mn1);
            float ls0 = 0.f, ls1 = 0.f;
#pragma unroll
            for (int nf = 0; nf < 8; nf++) {
                float p0 = ex2f(s[nf][0] - mn0);
                float p1 = ex2f(s[nf][1] - mn0);
                float p2 = ex2f(s[nf][2] - mn1);
                float p3 = ex2f(s[nf][3] - mn1);
                s[nf][0] = p0; s[nf][1] = p1; s[nf][2] = p2; s[nf][3] = p3;
                ls0 += p0 + p1; ls1 += p2 + p3;
            }
            ls0 += __shfl_xor_sync(0xffffffffu, ls0, 1);
            ls0 += __shfl_xor_sync(0xffffffffu, ls0, 2);
            ls1 += __shfl_xor_sync(0xffffffffu, ls1, 1);
            ls1 += __shfl_xor_sync(0xffffffffu, ls1, 2);
            rl0 = rl0 * corr0 + ls0;
            rl1 = rl1 * corr1 + ls1;
            rm0 = mn0; rm1 = mn1;
#pragma unroll
            for (int f = 0; f < 16; f++) {
                o[f][0] *= corr0; o[f][1] *= corr0;
                o[f][2] *= corr1; o[f][3] *= corr1;
            }

            // ---- O += Ph*Vh + Pl*Vh (2-product, value path) ----
#pragma unroll
            for (int ks = 0; ks < 4; ks++) {
                uint32_t ph[4], pl4[4];
                packhl(s[2 * ks][0], s[2 * ks][1], ph[0], pl4[0]);
                packhl(s[2 * ks][2], s[2 * ks][3], ph[1], pl4[1]);
                packhl(s[2 * ks + 1][0], s[2 * ks + 1][1], ph[2], pl4[2]);
                packhl(s[2 * ks + 1][2], s[2 * ks + 1][3], ph[3], pl4[3]);
                uint32_t voff = (uint32_t)((ks * 16 + (l & 15)) * 272 + (l >> 4) * 16);
                uint32_t tv[8][4];
#pragma unroll
                for (int dg = 0; dg < 8; dg++)
                    ldsm4t(bs + 2 * KTB + voff + dg * 32, tv[dg]);
#pragma unroll
                for (int dg = 0; dg < 8; dg++) {
                    MMA_F16(o[dg * 2], ph, tv[dg][0], tv[dg][1]);
                    MMA_F16(o[dg * 2 + 1], ph, tv[dg][2], tv[dg][3]);
                }
#pragma unroll
                for (int dg = 0; dg < 8; dg++) {
                    MMA_F16(o[dg * 2], pl4, tv[dg][0], tv[dg][1]);
                    MMA_F16(o[dg * 2 + 1], pl4, tv[dg][2], tv[dg][3]);
                }
            }
        }
        __syncthreads();
        if (i + 2 < ntile) loadKV(i & 1, k0 + 128);
    }

    float i0 = 1.f / rl0, i1 = 1.f / rl1;
    int m0r = t0 + w * 16 + (l >> 2);
#pragma unroll
    for (int f = 0; f < 16; f++) {
        int col = h * 128 + (f >> 1) * 16 + (f & 1) * 8 + (l & 3) * 2;
        size_t a0 = ((size_t)(b * T_ + m0r)) * C_ + col;
        size_t a1 = a0 + (size_t)8 * C_;
        *reinterpret_cast<__half2*>(yh + a0) = __floats2half2_rn(o[f][0] * i0, o[f][1] * i0);
        *reinterpret_cast<__half2*>(yh + a1) = __floats2half2_rn(o[f][2] * i1, o[f][3] * i1);
    }
}

// ---------------- launch ------------------------------------------------------
#define GEMM2_SMEM (NSTAGE * 3 * ARR_B)   // 92160
#define GEMM1_SMEM (NSTAGE * 2 * ARR_B)   // 61440

extern "C" void kernel_launch(void* const* d_in, const int* in_sizes, int n_in,
                              void* d_out, int out_size) {
    const float* x     = (const float*)d_in[0];
    const float* ve    = (const float*)d_in[1];
    const float* Wq    = (const float*)d_in[2];
    const float* Wk    = (const float*)d_in[3];
    const float* Wv    = (const float*)d_in[4];
    const float* Wproj = (const float*)d_in[5];
    const float* Wg    = (const float*)d_in[6];
    const float* cosp  = (const float*)d_in[7];
    const float* sinp  = (const float*)d_in[8];
    const int*   winp  = (const int*)d_in[9];
    float* out = (float*)d_out;

    void *pg, *pxh, *pxl, *pyh;
    void *pqh, *pql, *pkh, *pkl, *pvh;
    void *pwqh, *pwkh, *pwvh, *pwph;
    cudaGetSymbolAddress(&pg,  g_gate);
    cudaGetSymbolAddress(&pxh, g_xh);  cudaGetSymbolAddress(&pxl, g_xl);
    cudaGetSymbolAddress(&pyh, g_yh);
    cudaGetSymbolAddress(&pqh, g_qh);  cudaGetSymbolAddress(&pql, g_ql);
    cudaGetSymbolAddress(&pkh, g_kh);  cudaGetSymbolAddress(&pkl, g_kl);
    cudaGetSymbolAddress(&pvh, g_vh);
    cudaGetSymbolAddress(&pwqh, g_wqh); cudaGetSymbolAddress(&pwkh, g_wkh);
    cudaGetSymbolAddress(&pwvh, g_wvh); cudaGetSymbolAddress(&pwph, g_wph);

    cudaFuncSetAttribute((const void*)gemm_mma<1,2>, cudaFuncAttributeMaxDynamicSharedMemorySize, GEMM2_SMEM);
    cudaFuncSetAttribute((const void*)gemm_mma<2,1>, cudaFuncAttributeMaxDynamicSharedMemorySize, GEMM1_SMEM);
    cudaFuncSetAttribute((const void*)gemm_mma<0,1>, cudaFuncAttributeMaxDynamicSharedMemorySize, GEMM1_SMEM);
    cudaFuncSetAttribute(attn_mma, cudaFuncAttributeMaxDynamicSharedMemorySize, ATT_SMEM);

    // 0) splits
    split_kernel<<<M_*C_/1024, 256>>>(x, (__half*)pxh, (__half*)pxl, M_*C_);
    wsplit_kernel<<<dim3(C_*C_/1024, 4), 256>>>(
        Wq, Wk, Wv, Wproj,
        (__half*)pwqh, (__half*)pwkh, (__half*)pwvh, (__half*)pwph);

    // 1) gate
    gate_kernel<<<(M_ * H_ + 255) / 256, 256>>>(x, Wg, (float*)pg);

    // 2) projections: q/k 2-product (logit), v 1-product (value path)
    dim3 ggrid(C_ / 128, M_ / 128);
    gemm_mma<1,2><<<ggrid, 256, GEMM2_SMEM>>>((const __half*)pxh, (const __half*)pxl,
                                              (const __half*)pwqh,
                                              nullptr, (__half*)pqh, (__half*)pql,
                                              nullptr, nullptr, cosp, sinp);
    gemm_mma<1,2><<<ggrid, 256, GEMM2_SMEM>>>((const __half*)pxh, (const __half*)pxl,
                                              (const __half*)pwkh,
                                              nullptr, (__half*)pkh, (__half*)pkl,
                                              nullptr, nullptr, cosp, sinp);
    gemm_mma<2,1><<<ggrid, 256, GEMM1_SMEM>>>((const __half*)pxh, nullptr,
                                              (const __half*)pwvh,
                                              nullptr, (__half*)pvh, nullptr,
                                              ve, (const float*)pg, nullptr, nullptr);

    // 3) tensor-core attention -> single fp16 y
    attn_mma<<<dim3(T_ / 128, H_, B_), 256, ATT_SMEM>>>(
        (const __half*)pqh, (const __half*)pql,
        (const __half*)pkh, (const __half*)pkl,
        (const __half*)pvh,
        (__half*)pyh, winp);

    // 4) output projection (1-product)
    gemm_mma<0,1><<<ggrid, 256, GEMM1_SMEM>>>((const __half*)pyh, nullptr,
                                              (const __half*)pwph,
                                              out, nullptr, nullptr, nullptr, nullptr,
                                              nullptr, nullptr);
}

// round 13
// speedup vs baseline: 2.1466x; 1.2836x over previous
#include <cuda_runtime.h>
#include <cuda_fp16.h>
#include <math.h>
#include <stdint.h>

#define B_ 2
#define T_ 2048
#define C_ 2048
#define H_ 16
#define D_ 128
#define M_ (B_*T_)   // 4096 rows

// ---------------- scratch (device globals; no allocation allowed) -------------
__device__ float g_gate[M_*H_];
__device__ __half g_xh[M_*C_];
__device__ __half g_yh[M_*C_];
__device__ __half g_qh[M_*C_],  g_ql[M_*C_];   // [b][h][t][d]
__device__ __half g_kh[M_*C_],  g_kl[M_*C_];   // [b][h][t][d]
__device__ __half g_vh[M_*C_];                 // [b][h][t][d] single fp16
__device__ __half g_wqh[C_*C_];
__device__ __half g_wkh[C_*C_];
__device__ __half g_wvh[C_*C_];
__device__ __half g_wph[C_*C_];

// ================= PTX helpers =================
__device__ __forceinline__ uint32_t smem_u32(const void* p) {
    uint32_t a;
    asm("{ .reg .u64 t; cvta.to.shared.u64 t, %1; cvt.u32.u64 %0, t; }" : "=r"(a) : "l"(p));
    return a;
}
__device__ __forceinline__ void cpasync16(uint32_t saddr, const void* gaddr) {
    asm volatile("cp.async.cg.shared.global [%0], [%1], 16;" :: "r"(saddr), "l"(gaddr) : "memory");
}
__device__ __forceinline__ void ldsm4(uint32_t addr, uint32_t* r) {
    asm volatile("ldmatrix.sync.aligned.m8n8.x4.shared.b16 {%0,%1,%2,%3}, [%4];"
                 : "=r"(r[0]), "=r"(r[1]), "=r"(r[2]), "=r"(r[3]) : "r"(addr));
}
__device__ __forceinline__ void ldsm4t(uint32_t addr, uint32_t* r) {
    asm volatile("ldmatrix.sync.aligned.m8n8.x4.trans.shared.b16 {%0,%1,%2,%3}, [%4];"
                 : "=r"(r[0]), "=r"(r[1]), "=r"(r[2]), "=r"(r[3]) : "r"(addr));
}
__device__ __forceinline__ float ex2f(float x) {
    float y; asm("ex2.approx.f32 %0, %1;" : "=f"(y) : "f"(x)); return y;
}
#define MMA_F16(Cf, Af, B0, B1)                                               \
    asm volatile("mma.sync.aligned.m16n8k16.row.col.f32.f16.f16.f32 "          \
        "{%0,%1,%2,%3},{%4,%5,%6,%7},{%8,%9},{%0,%1,%2,%3};"                   \
        : "+f"((Cf)[0]), "+f"((Cf)[1]), "+f"((Cf)[2]), "+f"((Cf)[3])           \
        : "r"((Af)[0]), "r"((Af)[1]), "r"((Af)[2]), "r"((Af)[3]),              \
          "r"(B0), "r"(B1))

__device__ __forceinline__ void store_hl(__half* ph, __half* pl, float a, float b) {
    __half ha = __float2half(a), hb = __float2half(b);
    *reinterpret_cast<__half2*>(ph) = __halves2half2(ha, hb);
    *reinterpret_cast<__half2*>(pl) = __halves2half2(
        __float2half(a - __half2float(ha)),
        __float2half(b - __half2float(hb)));
}
__device__ __forceinline__ void packhl(float a, float b, uint32_t& hi, uint32_t& lo) {
    __half ha = __float2half(a), hb = __float2half(b);
    __half2 hv = __halves2half2(ha, hb);
    hi = *reinterpret_cast<uint32_t*>(&hv);
    __half2 lv = __halves2half2(__float2half(a - __half2float(ha)),
                                __float2half(b - __half2float(hb)));
    lo = *reinterpret_cast<uint32_t*>(&lv);
}

// ---------------- fp32 -> fp16 conversions -------------------------------------
// blockIdx.y: 0 -> x (M*C), 1..4 -> weights (C*C each)
__global__ void conv_kernel(const float* __restrict__ x,
                            const float* __restrict__ w0, const float* __restrict__ w1,
                            const float* __restrict__ w2, const float* __restrict__ w3,
                            __half* __restrict__ xh,
                            __half* __restrict__ h0, __half* __restrict__ h1,
                            __half* __restrict__ h2, __half* __restrict__ h3) {
    int which = blockIdx.y;
    const float* src; __half* dst; int n;
    switch (which) {
        case 0: src = x;  dst = xh; n = M_*C_; break;
        case 1: src = w0; dst = h0; n = C_*C_; break;
        case 2: src = w1; dst = h1; n = C_*C_; break;
        case 3: src = w2; dst = h2; n = C_*C_; break;
        default: src = w3; dst = h3; n = C_*C_; break;
    }
    int i = (blockIdx.x * blockDim.x + threadIdx.x) * 4;
    if (i >= n) return;
    float4 v = *(const float4*)(src + i);
    ((__half2*)(dst + i))[0] = __floats2half2_rn(v.x, v.y);
    ((__half2*)(dst + i))[1] = __floats2half2_rn(v.z, v.w);
}

// ---------------- gate = 3*sigmoid(x[:, :12] @ Wg^T) --------------------------
__global__ void gate_kernel(const float* __restrict__ x, const float* __restrict__ Wg,
                            float* __restrict__ gate) {
    int idx = blockIdx.x * blockDim.x + threadIdx.x;
    if (idx >= M_ * H_) return;
    int m = idx >> 4, h = idx & 15;
    float s = 0.f;
#pragma unroll
    for (int j = 0; j < 12; j++) s += x[(size_t)m * C_ + j] * Wg[h * 12 + j];
    gate[idx] = 3.f / (1.f + __expf(-s));
}

// ---------------- 1-product fp16 GEMM core (shared by proj + out) --------------
#define RS_B 80
#define ARR_B (128 * RS_B)
#define NSTAGE 3
#define NCHUNK 64
#define STGB (2 * ARR_B)                 // Ah | Bh
#define GEMM_SMEM (NSTAGE * STGB)        // 61440
#define PROJ_SMEM (128 * 132 * 4)        // 67584 — epilogue staging needs more

struct Frag {
    uint32_t a_h[2][4];
    uint32_t b_h[8][2];
};

__device__ __forceinline__ void gemm_core(
    uint32_t sb, int tid, int wid, int lane,
    const __half* Ah, const __half* Bh, int arow0, int brow0,
    float (&acc)[2][8][4]) {
    const int warp_m = wid & 3, warp_n = wid >> 2;

    auto load_chunk = [&](int stage, int chunk) {
        const int k0 = chunk * 32;
        uint32_t stg = sb + stage * STGB;
#pragma unroll
        for (int j = 0; j < 4; j++) {
            int u = tid + j * 256;          // 0..1023
            int arr = u >> 9;
            int rc = u & 511;
            int r = rc >> 2, c = rc & 3;
            uint32_t sa = stg + arr * ARR_B + r * RS_B + c * 16;
            const __half* src = arr ? Bh : Ah;
            int row = arr ? (brow0 + r) : (arow0 + r);
            cpasync16(sa, src + (size_t)row * C_ + k0 + c * 8);
        }
        asm volatile("cp.async.commit_group;" ::: "memory");
    };

    const uint32_t a_lane_off = (uint32_t)((warp_m * 32 + (lane & 15)) * RS_B + (lane >> 4) * 16);
    const uint32_t b_lane_off = (uint32_t)((warp_n * 64 + (lane & 15)) * RS_B + (lane >> 4) * 16);

    auto ldfr = [&](Frag& F, uint32_t stg, uint32_t koff) {
#pragma unroll
        for (int mi = 0; mi < 2; mi++)
            ldsm4(stg + a_lane_off + mi * 16 * RS_B + koff, F.a_h[mi]);
#pragma unroll
        for (int nf4 = 0; nf4 < 4; nf4++) {
            uint32_t t[4];
            ldsm4(stg + ARR_B + b_lane_off + nf4 * 16 * RS_B + koff, t);
            F.b_h[nf4 * 2][0] = t[0]; F.b_h[nf4 * 2][1] = t[2];
            F.b_h[nf4 * 2 + 1][0] = t[1]; F.b_h[nf4 * 2 + 1][1] = t[3];
        }
    };

    auto mmab = [&](Frag& F) {
#pragma unroll
        for (int mi = 0; mi < 2; mi++)
#pragma unroll
            for (int nf = 0; nf < 8; nf++) MMA_F16(acc[mi][nf], F.a_h[mi], F.b_h[nf][0], F.b_h[nf][1]);
    };

    load_chunk(0, 0);
    load_chunk(1, 1);
    load_chunk(2, 2);
    asm volatile("cp.async.wait_group 2;" ::: "memory");
    __syncthreads();

    Frag Fa, Fb;
    ldfr(Fa, sb, 0);

    for (int i = 0; i < NCHUNK; i++) {
        uint32_t stg = sb + (i % NSTAGE) * STGB;
        ldfr(Fb, stg, 32);
        mmab(Fa);
        if (i < NCHUNK - 1) {
            if (i < NCHUNK - 2) asm volatile("cp.async.wait_group 1;" ::: "memory");
            else                asm volatile("cp.async.wait_group 0;" ::: "memory");
            __syncthreads();
            uint32_t stg2 = sb + ((i + 1) % NSTAGE) * STGB;
            ldfr(Fa, stg2, 0);
            if (i + 3 < NCHUNK) load_chunk(i % NSTAGE, i + 3);
        }
        mmab(Fb);
    }
}

// fused q/k/v projection: blockIdx.z selects weight + epilogue
__global__ __launch_bounds__(256, 1) void proj_mma(
    const __half* __restrict__ xh,
    const __half* __restrict__ Wq, const __half* __restrict__ Wk,
    const __half* __restrict__ Wv,
    __half* __restrict__ qh, __half* __restrict__ ql,
    __half* __restrict__ kh, __half* __restrict__ kl,
    __half* __restrict__ vh,
    const float* __restrict__ ve, const float* __restrict__ gate,
    const float* __restrict__ cosp, const float* __restrict__ sinp) {
    extern __shared__ char smc[];
    const uint32_t sb = smem_u32(smc);
    const int tid = threadIdx.x;
    const int wid = tid >> 5, lane = tid & 31;
    const int warp_m = wid & 3, warp_n = wid >> 2;
    const int arow0 = blockIdx.y * 128, brow0 = blockIdx.x * 128;
    const int z = blockIdx.z;
    const __half* Bh = (z == 0) ? Wq : (z == 1) ? Wk : Wv;

    float acc[2][8][4];
#pragma unroll
    for (int mi = 0; mi < 2; mi++)
#pragma unroll
        for (int nf = 0; nf < 8; nf++)
#pragma unroll
            for (int q = 0; q < 4; q++) acc[mi][nf][q] = 0.f;

    gemm_core(sb, tid, wid, lane, xh, Bh, arow0, brow0, acc);

    if (z < 2) {
        // rope + rms + hi/lo split epilogue (S uses 128*132*4 = 67584 B)
        __half* Oh = (z == 0) ? qh : kh;
        __half* Ol = (z == 0) ? ql : kl;
        __syncthreads();
        float* S = (float*)smc;
        const int rbase = warp_m * 32 + (lane >> 2);
        const int cbase = warp_n * 64 + (lane & 3) * 2;
#pragma unroll
        for (int mi = 0; mi < 2; mi++)
#pragma unroll
            for (int nf = 0; nf < 8; nf++) {
                int r = rbase + mi * 16, c = cbase + nf * 8;
                S[r * 132 + c] = acc[mi][nf][0];
                S[r * 132 + c + 1] = acc[mi][nf][1];
                S[(r + 8) * 132 + c] = acc[mi][nf][2];
                S[(r + 8) * 132 + c + 1] = acc[mi][nf][3];
            }
        __syncthreads();
        const int hh = brow0 >> 7;
        const int d0 = lane * 2;
#pragma unroll 4
        for (int rr = wid * 16; rr < wid * 16 + 16; rr++) {
            int m = arow0 + rr, b = m >> 11, t = m & 2047;
            float xa0 = S[rr * 132 + d0],      xa1 = S[rr * 132 + d0 + 1];
            float xb0 = S[rr * 132 + d0 + 64], xb1 = S[rr * 132 + d0 + 65];
            float2 cc = *(const float2*)(cosp + t * 64 + d0);
            float2 sn = *(const float2*)(sinp + t * 64 + d0);
            float y1a = xa0 * cc.x + xb0 * sn.x;
            float y1b = xa1 * cc.y + xb1 * sn.y;
            float y2a = xb0 * cc.x - xa0 * sn.x;
            float y2b = xb1 * cc.y - xa1 * sn.y;
            float ss = y1a * y1a + y1b * y1b + y2a * y2a + y2b * y2b;
#pragma unroll
            for (int off = 16; off; off >>= 1) ss += __shfl_xor_sync(0xffffffffu, ss, off);
            float r = rsqrtf(ss * (1.f / 128.f) + 1e-6f) * 1.2f;
            size_t ob = ((size_t)(b * H_ + hh) * T_ + t) * D_;
            store_hl(Oh + ob + d0, Ol + ob + d0, y1a * r, y1b * r);
            store_hl(Oh + ob + d0 + 64, Ol + ob + d0 + 64, y2a * r, y2b * r);
        }
        return;
    }

    // v epilogue: + gate*ve -> single fp16 [b][h][t][d]
    const int r0w = arow0 + warp_m * 32 + (lane >> 2);
    const int c0w = brow0 + warp_n * 64 + (lane & 3) * 2;
#pragma unroll
    for (int mi = 0; mi < 2; mi++) {
#pragma unroll
        for (int nf = 0; nf < 8; nf++) {
            int n = c0w + nf * 8;
            int m0 = r0w + mi * 16;
            int m1 = m0 + 8;
            float v0 = acc[mi][nf][0], v1 = acc[mi][nf][1];
            float v2 = acc[mi][nf][2], v3 = acc[mi][nf][3];
            float g0 = gate[m0 * H_ + (n >> 7)];
            float g1 = gate[m1 * H_ + (n >> 7)];
            const float* ve0 = ve + (size_t)m0 * C_ + n;
            const float* ve1 = ve + (size_t)m1 * C_ + n;
            v0 += g0 * ve0[0]; v1 += g0 * ve0[1];
            v2 += g1 * ve1[0]; v3 += g1 * ve1[1];
            int hh = n >> 7, dd = n & 127;
            size_t o0 = ((size_t)((m0 >> 11) * H_ + hh) * T_ + (m0 & 2047)) * D_ + dd;
            size_t o1 = ((size_t)((m1 >> 11) * H_ + hh) * T_ + (m1 & 2047)) * D_ + dd;
            *reinterpret_cast<__half2*>(vh + o0) = __floats2half2_rn(v0, v1);
            *reinterpret_cast<__half2*>(vh + o1) = __floats2half2_rn(v2, v3);
        }
    }
}

// output projection: 1-product, fp32 out
__global__ __launch_bounds__(256, 1) void outproj_mma(
    const __half* __restrict__ yh, const __half* __restrict__ Wp,
    float* __restrict__ out) {
    extern __shared__ char smc[];
    const uint32_t sb = smem_u32(smc);
    const int tid = threadIdx.x;
    const int wid = tid >> 5, lane = tid & 31;
    const int warp_m = wid & 3, warp_n = wid >> 2;
    const int arow0 = blockIdx.y * 128, brow0 = blockIdx.x * 128;

    float acc[2][8][4];
#pragma unroll
    for (int mi = 0; mi < 2; mi++)
#pragma unroll
        for (int nf = 0; nf < 8; nf++)
#pragma unroll
            for (int q = 0; q < 4; q++) acc[mi][nf][q] = 0.f;

    gemm_core(sb, tid, wid, lane, yh, Wp, arow0, brow0, acc);

    const int r0w = arow0 + warp_m * 32 + (lane >> 2);
    const int c0w = brow0 + warp_n * 64 + (lane & 3) * 2;
#pragma unroll
    for (int mi = 0; mi < 2; mi++) {
#pragma unroll
        for (int nf = 0; nf < 8; nf++) {
            int n = c0w + nf * 8;
            int m0 = r0w + mi * 16;
            int m1 = m0 + 8;
            *(float2*)(out + (size_t)m0 * C_ + n) = make_float2(acc[mi][nf][0], acc[mi][nf][1]);
            *(float2*)(out + (size_t)m1 * C_ + n) = make_float2(acc[mi][nf][2], acc[mi][nf][3]);
        }
    }
}

// ---------------- tensor-core flash attention (fp16) --------------------------
// 256 threads (8 warps), q-tile 128 rows, KV tile 64, 2 stages (Kh|Kl|Vh).
#define QTB (128 * 272)              // 34816
#define KTB (64 * 272)               // 17408
#define KV_OFF (2 * QTB)             // 69632
#define STG (3 * KTB)                // 52224
#define ATT_SMEM (2 * QTB + 2 * STG) // 174080

__global__ __launch_bounds__(256, 1) void attn_mma(
    const __half* __restrict__ qh, const __half* __restrict__ ql,
    const __half* __restrict__ kh, const __half* __restrict__ kl,
    const __half* __restrict__ vh,
    __half* __restrict__ yh,
    const int* __restrict__ winp) {
    extern __shared__ char smc[];
    const uint32_t sb = smem_u32(smc);
    const int tid = threadIdx.x, w = tid >> 5, l = tid & 31;
    const int t0 = blockIdx.x * 128, h = blockIdx.y, b = blockIdx.z;
    int win = *winp;
    if (win <= 0 || win >= T_) win = T_;
    const size_t hb = (size_t)(b * H_ + h) * ((size_t)T_ * D_);

#pragma unroll
    for (int j = 0; j < 8; j++) {
        int u = tid + j * 256;
        int r = u >> 4, c = u & 15;
        uint32_t so = (uint32_t)(r * 272 + c * 16);
        size_t go = hb + (size_t)(t0 + r) * D_ + c * 8;
        cpasync16(sb + so, qh + go);
        cpasync16(sb + QTB + so, ql + go);
    }
    asm volatile("cp.async.commit_group;" ::: "memory");

    int start = t0 - win;
    if (start < 0) start = 0;
    start &= ~63;
    const int ntile = ((t0 + 64 - start) >> 6) + 1;

    auto loadKV = [&](int stg, int k0) {
        uint32_t bs = sb + KV_OFF + stg * STG;
#pragma unroll
        for (int j = 0; j < 12; j++) {
            int u = tid + j * 256;
            int arr = u >> 10;
            int rc = u & 1023;
            int r = rc >> 4, c = rc & 15;
            uint32_t so = (uint32_t)(arr * KTB + r * 272 + c * 16);
            size_t go = hb + (size_t)(k0 + r) * D_ + c * 8;
            const __half* src = (arr == 0) ? kh : (arr == 1) ? kl : vh;
            cpasync16(bs + so, src + go);
        }
        asm volatile("cp.async.commit_group;" ::: "memory");
    };
    loadKV(0, start);
    if (ntile > 1) loadKV(1, start + 64);

    float o[16][4];
#pragma unroll
    for (int f = 0; f < 16; f++)
#pragma unroll
        for (int q = 0; q < 4; q++) o[f][q] = 0.f;
    float rm0 = -1e4f, rm1 = -1e4f, rl0 = 0.f, rl1 = 0.f;
    const float SC2 = 0.1275187989f;   // 1/sqrt(128) * log2(e)

    const uint32_t aoff = (uint32_t)((w * 16 + (l & 15)) * 272 + (l >> 4) * 16);
    const uint32_t boff = (uint32_t)((l & 15) * 272 + (l >> 4) * 16);
    const int r0 = t0 + w * 16 + (l >> 2), r1 = r0 + 8;
    const int wr_min = t0 + w * 16, wr_max = t0 + w * 16 + 15;

    for (int i = 0; i < ntile; i++) {
        int k0 = start + i * 64;
        if (i + 1 < ntile) asm volatile("cp.async.wait_group 1;" ::: "memory");
        else               asm volatile("cp.async.wait_group 0;" ::: "memory");
        __syncthreads();
        uint32_t bs = sb + KV_OFF + (i & 1) * STG;

        bool active = (k0 <= wr_max) && (k0 + 63 >= wr_min - win);
        if (active) {
            // ---- S = QhKh + QhKl + QlKh (3-product, logit path) ----
            float s[8][4];
#pragma unroll
            for (int f = 0; f < 8; f++)
#pragma unroll
                for (int q = 0; q < 4; q++) s[f][q] = 0.f;
#pragma unroll
            for (int ks = 0; ks < 8; ks++) {
                uint32_t aq[4], al4[4];
                uint32_t tk[4][4], uk[4][4];
                ldsm4(sb + aoff + ks * 32, aq);
                ldsm4(sb + QTB + aoff + ks * 32, al4);
#pragma unroll
                for (int ng = 0; ng < 4; ng++) {
                    ldsm4(bs + boff + ng * 16 * 272 + ks * 32, tk[ng]);
                    ldsm4(bs + KTB + boff + ng * 16 * 272 + ks * 32, uk[ng]);
                }
#pragma unroll
                for (int ng = 0; ng < 4; ng++) {
                    MMA_F16(s[ng * 2], aq, tk[ng][0], tk[ng][2]);
                    MMA_F16(s[ng * 2 + 1], aq, tk[ng][1], tk[ng][3]);
                }
#pragma unroll
                for (int ng = 0; ng < 4; ng++) {
                    MMA_F16(s[ng * 2], aq, uk[ng][0], uk[ng][2]);
                    MMA_F16(s[ng * 2 + 1], aq, uk[ng][1], uk[ng][3]);
                }
#pragma unroll
                for (int ng = 0; ng < 4; ng++) {
                    MMA_F16(s[ng * 2], al4, tk[ng][0], tk[ng][2]);
                    MMA_F16(s[ng * 2 + 1], al4, tk[ng][1], tk[ng][3]);
                }
            }

            // ---- masked online softmax (exp2 domain) ----
            float mx0 = -1e30f, mx1 = -1e30f;
#pragma unroll
            for (int nf = 0; nf < 8; nf++) {
                int c0 = k0 + nf * 8 + (l & 3) * 2, c1 = c0 + 1;
                float x0 = (c0 <= r0 && r0 - c0 <= win) ? s[nf][0] * SC2 : -1e30f;
                float x1 = (c1 <= r0 && r0 - c1 <= win) ? s[nf][1] * SC2 : -1e30f;
                float x2 = (c0 <= r1 && r1 - c0 <= win) ? s[nf][2] * SC2 : -1e30f;
                float x3 = (c1 <= r1 && r1 - c1 <= win) ? s[nf][3] * SC2 : -1e30f;
                s[nf][0] = x0; s[nf][1] = x1; s[nf][2] = x2; s[nf][3] = x3;
                mx0 = fmaxf(mx0, fmaxf(x0, x1));
                mx1 = fmaxf(mx1, fmaxf(x2, x3));
            }
            mx0 = fmaxf(mx0, __shfl_xor_sync(0xffffffffu, mx0, 1));
            mx0 = fmaxf(mx0, __shfl_xor_sync(0xffffffffu, mx0, 2));
            mx1 = fmaxf(mx1, __shfl_xor_sync(0xffffffffu, mx1, 1));
            mx1 = fmaxf(mx1, __shfl_xor_sync(0xffffffffu, mx1, 2));
            float mn0 = fmaxf(rm0, fmaxf(mx0, -1e4f));
            float mn1 = fmaxf(rm1, fmaxf(mx1, -1e4f));
            float corr0 = ex2f(rm0 - mn0), corr1 = ex2f(rm1 - mn1);
            float ls0 = 0.f, ls1 = 0.f;
#pragma unroll
            for (int nf = 0; nf < 8; nf++) {
                float p0 = ex2f(s[nf][0] - mn0);
                float p1 = ex2f(s[nf][1] - mn0);
                float p2 = ex2f(s[nf][2] - mn1);
                float p3 = ex2f(s[nf][3] - mn1);
                s[nf][0] = p0; s[nf][1] = p1; s[nf][2] = p2; s[nf][3] = p3;
                ls0 += p0 + p1; ls1 += p2 + p3;
            }
            ls0 += __shfl_xor_sync(0xffffffffu, ls0, 1);
            ls0 += __shfl_xor_sync(0xffffffffu, ls0, 2);
            ls1 += __shfl_xor_sync(0xffffffffu, ls1, 1);
            ls1 += __shfl_xor_sync(0xffffffffu, ls1, 2);
            rl0 = rl0 * corr0 + ls0;
            rl1 = rl1 * corr1 + ls1;
            rm0 = mn0; rm1 = mn1;
#pragma unroll
            for (int f = 0; f < 16; f++) {
                o[f][0] *= corr0; o[f][1] *= corr0;
                o[f][2] *= corr1; o[f][3] *= corr1;
            }

            // ---- O += Ph*Vh + Pl*Vh (2-product, value path) ----
#pragma unroll
            for (int ks = 0; ks < 4; ks++) {
                uint32_t ph[4], pl4[4];
                packhl(s[2 * ks][0], s[2 * ks][1], ph[0], pl4[0]);
                packhl(s[2 * ks][2], s[2 * ks][3], ph[1], pl4[1]);
                packhl(s[2 * ks + 1][0], s[2 * ks + 1][1], ph[2], pl4[2]);
                packhl(s[2 * ks + 1][2], s[2 * ks + 1][3], ph[3], pl4[3]);
                uint32_t voff = (uint32_t)((ks * 16 + (l & 15)) * 272 + (l >> 4) * 16);
                uint32_t tv[8][4];
#pragma unroll
                for (int dg = 0; dg < 8; dg++)
                    ldsm4t(bs + 2 * KTB + voff + dg * 32, tv[dg]);
#pragma unroll
                for (int dg = 0; dg < 8; dg++) {
                    MMA_F16(o[dg * 2], ph, tv[dg][0], tv[dg][1]);
                    MMA_F16(o[dg * 2 + 1], ph, tv[dg][2], tv[dg][3]);
                }
#pragma unroll
                for (int dg = 0; dg < 8; dg++) {
                    MMA_F16(o[dg * 2], pl4, tv[dg][0], tv[dg][1]);
                    MMA_F16(o[dg * 2 + 1], pl4, tv[dg][2], tv[dg][3]);
                }
            }
        }
        __syncthreads();
        if (i + 2 < ntile) loadKV(i & 1, k0 + 128);
    }

    float i0 = 1.f / rl0, i1 = 1.f / rl1;
    int m0r = t0 + w * 16 + (l >> 2);
#pragma unroll
    for (int f = 0; f < 16; f++) {
        int col = h * 128 + (f >> 1) * 16 + (f & 1) * 8 + (l & 3) * 2;
        size_t a0 = ((size_t)(b * T_ + m0r)) * C_ + col;
        size_t a1 = a0 + (size_t)8 * C_;
        *reinterpret_cast<__half2*>(yh + a0) = __floats2half2_rn(o[f][0] * i0, o[f][1] * i0);
        *reinterpret_cast<__half2*>(yh + a1) = __floats2half2_rn(o[f][2] * i1, o[f][3] * i1);
    }
}

// ---------------- launch ------------------------------------------------------
extern "C" void kernel_launch(void* const* d_in, const int* in_sizes, int n_in,
                              void* d_out, int out_size) {
    const float* x     = (const float*)d_in[0];
    const float* ve    = (const float*)d_in[1];
    const float* Wq    = (const float*)d_in[2];
    const float* Wk    = (const float*)d_in[3];
    const float* Wv    = (const float*)d_in[4];
    const float* Wproj = (const float*)d_in[5];
    const float* Wg    = (const float*)d_in[6];
    const float* cosp  = (const float*)d_in[7];
    const float* sinp  = (const float*)d_in[8];
    const int*   winp  = (const int*)d_in[9];
    float* out = (float*)d_out;

    void *pg, *pxh, *pyh;
    void *pqh, *pql, *pkh, *pkl, *pvh;
    void *pwqh, *pwkh, *pwvh, *pwph;
    cudaGetSymbolAddress(&pg,  g_gate);
    cudaGetSymbolAddress(&pxh, g_xh);
    cudaGetSymbolAddress(&pyh, g_yh);
    cudaGetSymbolAddress(&pqh, g_qh);  cudaGetSymbolAddress(&pql, g_ql);
    cudaGetSymbolAddress(&pkh, g_kh);  cudaGetSymbolAddress(&pkl, g_kl);
    cudaGetSymbolAddress(&pvh, g_vh);
    cudaGetSymbolAddress(&pwqh, g_wqh); cudaGetSymbolAddress(&pwkh, g_wkh);
    cudaGetSymbolAddress(&pwvh, g_wvh); cudaGetSymbolAddress(&pwph, g_wph);

    cudaFuncSetAttribute(proj_mma, cudaFuncAttributeMaxDynamicSharedMemorySize, PROJ_SMEM);
    cudaFuncSetAttribute(outproj_mma, cudaFuncAttributeMaxDynamicSharedMemorySize, GEMM_SMEM);
    cudaFuncSetAttribute(attn_mma, cudaFuncAttributeMaxDynamicSharedMemorySize, ATT_SMEM);

    // 0) fp16 conversions (x + 4 weights, one launch)
    conv_kernel<<<dim3(M_*C_/1024, 5), 256>>>(
        x, Wq, Wk, Wv, Wproj,
        (__half*)pxh, (__half*)pwqh, (__half*)pwkh, (__half*)pwvh, (__half*)pwph);

    // 1) gate
    gate_kernel<<<(M_ * H_ + 255) / 256, 256>>>(x, Wg, (float*)pg);

    // 2) fused q/k/v projections (1-product each)
    proj_mma<<<dim3(C_ / 128, M_ / 128, 3), 256, PROJ_SMEM>>>(
        (const __half*)pxh,
        (const __half*)pwqh, (const __half*)pwkh, (const __half*)pwvh,
        (__half*)pqh, (__half*)pql, (__half*)pkh, (__half*)pkl, (__half*)pvh,
        ve, (const float*)pg, cosp, sinp);

    // 3) tensor-core attention -> single fp16 y
    attn_mma<<<dim3(T_ / 128, H_, B_), 256, ATT_SMEM>>>(
        (const __half*)pqh, (const __half*)pql,
        (const __half*)pkh, (const __half*)pkl,
        (const __half*)pvh,
        (__half*)pyh, winp);

    // 4) output projection (1-product)
    outproj_mma<<<dim3(C_ / 128, M_ / 128), 256, GEMM_SMEM>>>(
        (const __half*)pyh, (const __half*)pwph, out);
}

// round 14
// speedup vs baseline: 2.4396x; 1.1365x over previous
#include <cuda_runtime.h>
#include <cuda_fp16.h>
#include <math.h>
#include <stdint.h>

#define B_ 2
#define T_ 2048
#define C_ 2048
#define H_ 16
#define D_ 128
#define M_ (B_*T_)   // 4096 rows

// ---------------- scratch (device globals; no allocation allowed) -------------
__device__ float g_gate[M_*H_];
__device__ __half g_xh[M_*C_];
__device__ __half g_yh[M_*C_];
__device__ __half g_qh[M_*C_];     // [b][h][t][d] single fp16
__device__ __half g_kh[M_*C_];     // [b][h][t][d] single fp16
__device__ __half g_vh[M_*C_];     // [b][h][t][d] single fp16
__device__ __half g_wqh[C_*C_];
__device__ __half g_wkh[C_*C_];
__device__ __half g_wvh[C_*C_];
__device__ __half g_wph[C_*C_];

// ================= PTX helpers =================
__device__ __forceinline__ uint32_t smem_u32(const void* p) {
    uint32_t a;
    asm("{ .reg .u64 t; cvta.to.shared.u64 t, %1; cvt.u32.u64 %0, t; }" : "=r"(a) : "l"(p));
    return a;
}
__device__ __forceinline__ void cpasync16(uint32_t saddr, const void* gaddr) {
    asm volatile("cp.async.cg.shared.global [%0], [%1], 16;" :: "r"(saddr), "l"(gaddr) : "memory");
}
__device__ __forceinline__ void ldsm4(uint32_t addr, uint32_t* r) {
    asm volatile("ldmatrix.sync.aligned.m8n8.x4.shared.b16 {%0,%1,%2,%3}, [%4];"
                 : "=r"(r[0]), "=r"(r[1]), "=r"(r[2]), "=r"(r[3]) : "r"(addr));
}
__device__ __forceinline__ void ldsm4t(uint32_t addr, uint32_t* r) {
    asm volatile("ldmatrix.sync.aligned.m8n8.x4.trans.shared.b16 {%0,%1,%2,%3}, [%4];"
                 : "=r"(r[0]), "=r"(r[1]), "=r"(r[2]), "=r"(r[3]) : "r"(addr));
}
__device__ __forceinline__ float ex2f(float x) {
    float y; asm("ex2.approx.f32 %0, %1;" : "=f"(y) : "f"(x)); return y;
}
#define MMA_F16(Cf, Af, B0, B1)                                               \
    asm volatile("mma.sync.aligned.m16n8k16.row.col.f32.f16.f16.f32 "          \
        "{%0,%1,%2,%3},{%4,%5,%6,%7},{%8,%9},{%0,%1,%2,%3};"                   \
        : "+f"((Cf)[0]), "+f"((Cf)[1]), "+f"((Cf)[2]), "+f"((Cf)[3])           \
        : "r"((Af)[0]), "r"((Af)[1]), "r"((Af)[2]), "r"((Af)[3]),              \
          "r"(B0), "r"(B1))

__device__ __forceinline__ uint32_t packh(float a, float b) {
    __half2 h = __floats2half2_rn(a, b);
    return *reinterpret_cast<uint32_t*>(&h);
}

// ---------------- fp32 -> fp16 conversions -------------------------------------
__global__ void conv_kernel(const float* __restrict__ x,
                            const float* __restrict__ w0, const float* __restrict__ w1,
                            const float* __restrict__ w2, const float* __restrict__ w3,
                            __half* __restrict__ xh,
                            __half* __restrict__ h0, __half* __restrict__ h1,
                            __half* __restrict__ h2, __half* __restrict__ h3) {
    int which = blockIdx.y;
    const float* src; __half* dst; int n;
    switch (which) {
        case 0: src = x;  dst = xh; n = M_*C_; break;
        case 1: src = w0; dst = h0; n = C_*C_; break;
        case 2: src = w1; dst = h1; n = C_*C_; break;
        case 3: src = w2; dst = h2; n = C_*C_; break;
        default: src = w3; dst = h3; n = C_*C_; break;
    }
    int i = (blockIdx.x * blockDim.x + threadIdx.x) * 4;
    if (i >= n) return;
    float4 v = *(const float4*)(src + i);
    ((__half2*)(dst + i))[0] = __floats2half2_rn(v.x, v.y);
    ((__half2*)(dst + i))[1] = __floats2half2_rn(v.z, v.w);
}

// ---------------- gate = 3*sigmoid(x[:, :12] @ Wg^T) --------------------------
__global__ void gate_kernel(const float* __restrict__ x, const float* __restrict__ Wg,
                            float* __restrict__ gate) {
    int idx = blockIdx.x * blockDim.x + threadIdx.x;
    if (idx >= M_ * H_) return;
    int m = idx >> 4, h = idx & 15;
    float s = 0.f;
#pragma unroll
    for (int j = 0; j < 12; j++) s += x[(size_t)m * C_ + j] * Wg[h * 12 + j];
    gate[idx] = 3.f / (1.f + __expf(-s));
}

// ---------------- 1-product fp16 GEMM core (shared by proj + out) --------------
#define RS_B 80
#define ARR_B (128 * RS_B)
#define NSTAGE 3
#define NCHUNK 64
#define STGB (2 * ARR_B)                 // Ah | Bh
#define GEMM_SMEM (NSTAGE * STGB)        // 61440
#define PROJ_SMEM (128 * 132 * 4)        // 67584 — rope epilogue staging

struct Frag {
    uint32_t a_h[2][4];
    uint32_t b_h[8][2];
};

__device__ __forceinline__ void gemm_core(
    uint32_t sb, int tid, int wid, int lane,
    const __half* Ah, const __half* Bh, int arow0, int brow0,
    float (&acc)[2][8][4]) {
    const int warp_m = wid & 3, warp_n = wid >> 2;

    auto load_chunk = [&](int stage, int chunk) {
        const int k0 = chunk * 32;
        uint32_t stg = sb + stage * STGB;
#pragma unroll
        for (int j = 0; j < 4; j++) {
            int u = tid + j * 256;
            int arr = u >> 9;
            int rc = u & 511;
            int r = rc >> 2, c = rc & 3;
            uint32_t sa = stg + arr * ARR_B + r * RS_B + c * 16;
            const __half* src = arr ? Bh : Ah;
            int row = arr ? (brow0 + r) : (arow0 + r);
            cpasync16(sa, src + (size_t)row * C_ + k0 + c * 8);
        }
        asm volatile("cp.async.commit_group;" ::: "memory");
    };

    const uint32_t a_lane_off = (uint32_t)((warp_m * 32 + (lane & 15)) * RS_B + (lane >> 4) * 16);
    const uint32_t b_lane_off = (uint32_t)((warp_n * 64 + (lane & 15)) * RS_B + (lane >> 4) * 16);

    auto ldfr = [&](Frag& F, uint32_t stg, uint32_t koff) {
#pragma unroll
        for (int mi = 0; mi < 2; mi++)
            ldsm4(stg + a_lane_off + mi * 16 * RS_B + koff, F.a_h[mi]);
#pragma unroll
        for (int nf4 = 0; nf4 < 4; nf4++) {
            uint32_t t[4];
            ldsm4(stg + ARR_B + b_lane_off + nf4 * 16 * RS_B + koff, t);
            F.b_h[nf4 * 2][0] = t[0]; F.b_h[nf4 * 2][1] = t[2];
            F.b_h[nf4 * 2 + 1][0] = t[1]; F.b_h[nf4 * 2 + 1][1] = t[3];
        }
    };

    auto mmab = [&](Frag& F) {
#pragma unroll
        for (int mi = 0; mi < 2; mi++)
#pragma unroll
            for (int nf = 0; nf < 8; nf++) MMA_F16(acc[mi][nf], F.a_h[mi], F.b_h[nf][0], F.b_h[nf][1]);
    };

    load_chunk(0, 0);
    load_chunk(1, 1);
    load_chunk(2, 2);
    asm volatile("cp.async.wait_group 2;" ::: "memory");
    __syncthreads();

    Frag Fa, Fb;
    ldfr(Fa, sb, 0);

    for (int i = 0; i < NCHUNK; i++) {
        uint32_t stg = sb + (i % NSTAGE) * STGB;
        ldfr(Fb, stg, 32);
        mmab(Fa);
        if (i < NCHUNK - 1) {
            if (i < NCHUNK - 2) asm volatile("cp.async.wait_group 1;" ::: "memory");
            else                asm volatile("cp.async.wait_group 0;" ::: "memory");
            __syncthreads();
            uint32_t stg2 = sb + ((i + 1) % NSTAGE) * STGB;
            ldfr(Fa, stg2, 0);
            if (i + 3 < NCHUNK) load_chunk(i % NSTAGE, i + 3);
        }
        mmab(Fb);
    }
}

// fused q/k/v projection: blockIdx.z selects weight + epilogue
__global__ __launch_bounds__(256, 1) void proj_mma(
    const __half* __restrict__ xh,
    const __half* __restrict__ Wq, const __half* __restrict__ Wk,
    const __half* __restrict__ Wv,
    __half* __restrict__ qh, __half* __restrict__ kh, __half* __restrict__ vh,
    const float* __restrict__ ve, const float* __restrict__ gate,
    const float* __restrict__ cosp, const float* __restrict__ sinp) {
    extern __shared__ char smc[];
    const uint32_t sb = smem_u32(smc);
    const int tid = threadIdx.x;
    const int wid = tid >> 5, lane = tid & 31;
    const int warp_m = wid & 3, warp_n = wid >> 2;
    const int arow0 = blockIdx.y * 128, brow0 = blockIdx.x * 128;
    const int z = blockIdx.z;
    const __half* Bh = (z == 0) ? Wq : (z == 1) ? Wk : Wv;

    float acc[2][8][4];
#pragma unroll
    for (int mi = 0; mi < 2; mi++)
#pragma unroll
        for (int nf = 0; nf < 8; nf++)
#pragma unroll
            for (int q = 0; q < 4; q++) acc[mi][nf][q] = 0.f;

    gemm_core(sb, tid, wid, lane, xh, Bh, arow0, brow0, acc);

    if (z < 2) {
        // rope + rms epilogue -> single fp16 [b][h][t][d]
        __half* Oh = (z == 0) ? qh : kh;
        __syncthreads();
        float* S = (float*)smc;
        const int rbase = warp_m * 32 + (lane >> 2);
        const int cbase = warp_n * 64 + (lane & 3) * 2;
#pragma unroll
        for (int mi = 0; mi < 2; mi++)
#pragma unroll
            for (int nf = 0; nf < 8; nf++) {
                int r = rbase + mi * 16, c = cbase + nf * 8;
                S[r * 132 + c] = acc[mi][nf][0];
                S[r * 132 + c + 1] = acc[mi][nf][1];
                S[(r + 8) * 132 + c] = acc[mi][nf][2];
                S[(r + 8) * 132 + c + 1] = acc[mi][nf][3];
            }
        __syncthreads();
        const int hh = brow0 >> 7;
        const int d0 = lane * 2;
#pragma unroll 4
        for (int rr = wid * 16; rr < wid * 16 + 16; rr++) {
            int m = arow0 + rr, b = m >> 11, t = m & 2047;
            float xa0 = S[rr * 132 + d0],      xa1 = S[rr * 132 + d0 + 1];
            float xb0 = S[rr * 132 + d0 + 64], xb1 = S[rr * 132 + d0 + 65];
            float2 cc = *(const float2*)(cosp + t * 64 + d0);
            float2 sn = *(const float2*)(sinp + t * 64 + d0);
            float y1a = xa0 * cc.x + xb0 * sn.x;
            float y1b = xa1 * cc.y + xb1 * sn.y;
            float y2a = xb0 * cc.x - xa0 * sn.x;
            float y2b = xb1 * cc.y - xa1 * sn.y;
            float ss = y1a * y1a + y1b * y1b + y2a * y2a + y2b * y2b;
#pragma unroll
            for (int off = 16; off; off >>= 1) ss += __shfl_xor_sync(0xffffffffu, ss, off);
            float r = rsqrtf(ss * (1.f / 128.f) + 1e-6f) * 1.2f;
            size_t ob = ((size_t)(b * H_ + hh) * T_ + t) * D_;
            *reinterpret_cast<__half2*>(Oh + ob + d0) = __floats2half2_rn(y1a * r, y1b * r);
            *reinterpret_cast<__half2*>(Oh + ob + d0 + 64) = __floats2half2_rn(y2a * r, y2b * r);
        }
        return;
    }

    // v epilogue: + gate*ve -> single fp16 [b][h][t][d]
    const int r0w = arow0 + warp_m * 32 + (lane >> 2);
    const int c0w = brow0 + warp_n * 64 + (lane & 3) * 2;
#pragma unroll
    for (int mi = 0; mi < 2; mi++) {
#pragma unroll
        for (int nf = 0; nf < 8; nf++) {
            int n = c0w + nf * 8;
            int m0 = r0w + mi * 16;
            int m1 = m0 + 8;
            float v0 = acc[mi][nf][0], v1 = acc[mi][nf][1];
            float v2 = acc[mi][nf][2], v3 = acc[mi][nf][3];
            float g0 = gate[m0 * H_ + (n >> 7)];
            float g1 = gate[m1 * H_ + (n >> 7)];
            const float* ve0 = ve + (size_t)m0 * C_ + n;
            const float* ve1 = ve + (size_t)m1 * C_ + n;
            v0 += g0 * ve0[0]; v1 += g0 * ve0[1];
            v2 += g1 * ve1[0]; v3 += g1 * ve1[1];
            int hh = n >> 7, dd = n & 127;
            size_t o0 = ((size_t)((m0 >> 11) * H_ + hh) * T_ + (m0 & 2047)) * D_ + dd;
            size_t o1 = ((size_t)((m1 >> 11) * H_ + hh) * T_ + (m1 & 2047)) * D_ + dd;
            *reinterpret_cast<__half2*>(vh + o0) = __floats2half2_rn(v0, v1);
            *reinterpret_cast<__half2*>(vh + o1) = __floats2half2_rn(v2, v3);
        }
    }
}

// output projection: 1-product, fp32 out
__global__ __launch_bounds__(256, 1) void outproj_mma(
    const __half* __restrict__ yh, const __half* __restrict__ Wp,
    float* __restrict__ out) {
    extern __shared__ char smc[];
    const uint32_t sb = smem_u32(smc);
    const int tid = threadIdx.x;
    const int wid = tid >> 5, lane = tid & 31;
    const int warp_m = wid & 3, warp_n = wid >> 2;
    const int arow0 = blockIdx.y * 128, brow0 = blockIdx.x * 128;

    float acc[2][8][4];
#pragma unroll
    for (int mi = 0; mi < 2; mi++)
#pragma unroll
        for (int nf = 0; nf < 8; nf++)
#pragma unroll
            for (int q = 0; q < 4; q++) acc[mi][nf][q] = 0.f;

    gemm_core(sb, tid, wid, lane, yh, Wp, arow0, brow0, acc);

    const int r0w = arow0 + warp_m * 32 + (lane >> 2);
    const int c0w = brow0 + warp_n * 64 + (lane & 3) * 2;
#pragma unroll
    for (int mi = 0; mi < 2; mi++) {
#pragma unroll
        for (int nf = 0; nf < 8; nf++) {
            int n = c0w + nf * 8;
            int m0 = r0w + mi * 16;
            int m1 = m0 + 8;
            *(float2*)(out + (size_t)m0 * C_ + n) = make_float2(acc[mi][nf][0], acc[mi][nf][1]);
            *(float2*)(out + (size_t)m1 * C_ + n) = make_float2(acc[mi][nf][2], acc[mi][nf][3]);
        }
    }
}

// ---------------- tensor-core flash attention (single fp16) -------------------
// 256 threads (8 warps), q-tile 128 rows, KV tile 64, 2 stages (Kh|Vh).
// S and PV both 1-product.
#define QTB (128 * 272)              // 34816
#define KTB (64 * 272)               // 17408
#define KV_OFF QTB                   // 34816
#define STG (2 * KTB)                // 34816
#define ATT_SMEM (QTB + 2 * STG)     // 104448

__global__ __launch_bounds__(256, 1) void attn_mma(
    const __half* __restrict__ qh, const __half* __restrict__ kh,
    const __half* __restrict__ vh,
    __half* __restrict__ yh,
    const int* __restrict__ winp) {
    extern __shared__ char smc[];
    const uint32_t sb = smem_u32(smc);
    const int tid = threadIdx.x, w = tid >> 5, l = tid & 31;
    const int t0 = blockIdx.x * 128, h = blockIdx.y, b = blockIdx.z;
    int win = *winp;
    if (win <= 0 || win >= T_) win = T_;
    const size_t hb = (size_t)(b * H_ + h) * ((size_t)T_ * D_);

    // Q tile (128 rows, single fp16)
#pragma unroll
    for (int j = 0; j < 8; j++) {
        int u = tid + j * 256;
        int r = u >> 4, c = u & 15;
        uint32_t so = (uint32_t)(r * 272 + c * 16);
        cpasync16(sb + so, qh + hb + (size_t)(t0 + r) * D_ + c * 8);
    }
    asm volatile("cp.async.commit_group;" ::: "memory");

    int start = t0 - win;
    if (start < 0) start = 0;
    start &= ~63;
    const int ntile = ((t0 + 64 - start) >> 6) + 1;

    auto loadKV = [&](int stg, int k0) {
        uint32_t bs = sb + KV_OFF + stg * STG;
#pragma unroll
        for (int j = 0; j < 8; j++) {
            int u = tid + j * 256;          // 0..2047
            int arr = u >> 10;
            int rc = u & 1023;
            int r = rc >> 4, c = rc & 15;
            uint32_t so = (uint32_t)(arr * KTB + r * 272 + c * 16);
            const __half* src = arr ? vh : kh;
            cpasync16(bs + so, src + hb + (size_t)(k0 + r) * D_ + c * 8);
        }
        asm volatile("cp.async.commit_group;" ::: "memory");
    };
    loadKV(0, start);
    if (ntile > 1) loadKV(1, start + 64);

    float o[16][4];
#pragma unroll
    for (int f = 0; f < 16; f++)
#pragma unroll
        for (int q = 0; q < 4; q++) o[f][q] = 0.f;
    float rm0 = -1e4f, rm1 = -1e4f, rl0 = 0.f, rl1 = 0.f;
    const float SC2 = 0.1275187989f;   // 1/sqrt(128) * log2(e)

    const uint32_t aoff = (uint32_t)((w * 16 + (l & 15)) * 272 + (l >> 4) * 16);
    const uint32_t boff = (uint32_t)((l & 15) * 272 + (l >> 4) * 16);
    const int r0 = t0 + w * 16 + (l >> 2), r1 = r0 + 8;
    const int wr_min = t0 + w * 16, wr_max = t0 + w * 16 + 15;

    for (int i = 0; i < ntile; i++) {
        int k0 = start + i * 64;
        if (i + 1 < ntile) asm volatile("cp.async.wait_group 1;" ::: "memory");
        else               asm volatile("cp.async.wait_group 0;" ::: "memory");
        __syncthreads();
        uint32_t bs = sb + KV_OFF + (i & 1) * STG;

        bool active = (k0 <= wr_max) && (k0 + 63 >= wr_min - win);
        if (active) {
            // ---- S = Q K^T (1-product) ----
            float s[8][4];
#pragma unroll
            for (int f = 0; f < 8; f++)
#pragma unroll
                for (int q = 0; q < 4; q++) s[f][q] = 0.f;
#pragma unroll
            for (int ks = 0; ks < 8; ks++) {
                uint32_t aq[4];
                uint32_t tk[4][4];
                ldsm4(sb + aoff + ks * 32, aq);
#pragma unroll
                for (int ng = 0; ng < 4; ng++)
                    ldsm4(bs + boff + ng * 16 * 272 + ks * 32, tk[ng]);
#pragma unroll
                for (int ng = 0; ng < 4; ng++) {
                    MMA_F16(s[ng * 2], aq, tk[ng][0], tk[ng][2]);
                    MMA_F16(s[ng * 2 + 1], aq, tk[ng][1], tk[ng][3]);
                }
            }

            // ---- masked online softmax (exp2 domain) ----
            float mx0 = -1e30f, mx1 = -1e30f;
#pragma unroll
            for (int nf = 0; nf < 8; nf++) {
                int c0 = k0 + nf * 8 + (l & 3) * 2, c1 = c0 + 1;
                float x0 = (c0 <= r0 && r0 - c0 <= win) ? s[nf][0] * SC2 : -1e30f;
                float x1 = (c1 <= r0 && r0 - c1 <= win) ? s[nf][1] * SC2 : -1e30f;
                float x2 = (c0 <= r1 && r1 - c0 <= win) ? s[nf][2] * SC2 : -1e30f;
                float x3 = (c1 <= r1 && r1 - c1 <= win) ? s[nf][3] * SC2 : -1e30f;
                s[nf][0] = x0; s[nf][1] = x1; s[nf][2] = x2; s[nf][3] = x3;
                mx0 = fmaxf(mx0, fmaxf(x0, x1));
                mx1 = fmaxf(mx1, fmaxf(x2, x3));
            }
            mx0 = fmaxf(mx0, __shfl_xor_sync(0xffffffffu, mx0, 1));
            mx0 = fmaxf(mx0, __shfl_xor_sync(0xffffffffu, mx0, 2));
            mx1 = fmaxf(mx1, __shfl_xor_sync(0xffffffffu, mx1, 1));
            mx1 = fmaxf(mx1, __shfl_xor_sync(0xffffffffu, mx1, 2));
            float mn0 = fmaxf(rm0, fmaxf(mx0, -1e4f));
            float mn1 = fmaxf(rm1, fmaxf(mx1, -1e4f));
            float corr0 = ex2f(rm0 - mn0), corr1 = ex2f(rm1 - mn1);
            float ls0 = 0.f, ls1 = 0.f;
#pragma unroll
            for (int nf = 0; nf < 8; nf++) {
                float p0 = ex2f(s[nf][0] - mn0);
                float p1 = ex2f(s[nf][1] - mn0);
                float p2 = ex2f(s[nf][2] - mn1);
                float p3 = ex2f(s[nf][3] - mn1);
                s[nf][0] = p0; s[nf][1] = p1; s[nf][2] = p2; s[nf][3] = p3;
                ls0 += p0 + p1; ls1 += p2 + p3;
            }
            ls0 += __shfl_xor_sync(0xffffffffu, ls0, 1);
            ls0 += __shfl_xor_sync(0xffffffffu, ls0, 2);
            ls1 += __shfl_xor_sync(0xffffffffu, ls1, 1);
            ls1 += __shfl_xor_sync(0xffffffffu, ls1, 2);
            rl0 = rl0 * corr0 + ls0;
            rl1 = rl1 * corr1 + ls1;
            rm0 = mn0; rm1 = mn1;
#pragma unroll
            for (int f = 0; f < 16; f++) {
                o[f][0] *= corr0; o[f][1] *= corr0;
                o[f][2] *= corr1; o[f][3] *= corr1;
            }

            // ---- O += P V (1-product) ----
#pragma unroll
            for (int ks = 0; ks < 4; ks++) {
                uint32_t ph[4];
                ph[0] = packh(s[2 * ks][0], s[2 * ks][1]);
                ph[1] = packh(s[2 * ks][2], s[2 * ks][3]);
                ph[2] = packh(s[2 * ks + 1][0], s[2 * ks + 1][1]);
                ph[3] = packh(s[2 * ks + 1][2], s[2 * ks + 1][3]);
                uint32_t voff = (uint32_t)((ks * 16 + (l & 15)) * 272 + (l >> 4) * 16);
                uint32_t tv[8][4];
#pragma unroll
                for (int dg = 0; dg < 8; dg++)
                    ldsm4t(bs + KTB + voff + dg * 32, tv[dg]);
#pragma unroll
                for (int dg = 0; dg < 8; dg++) {
                    MMA_F16(o[dg * 2], ph, tv[dg][0], tv[dg][1]);
                    MMA_F16(o[dg * 2 + 1], ph, tv[dg][2], tv[dg][3]);
                }
            }
        }
        __syncthreads();
        if (i + 2 < ntile) loadKV(i & 1, k0 + 128);
    }

    float i0 = 1.f / rl0, i1 = 1.f / rl1;
    int m0r = t0 + w * 16 + (l >> 2);
#pragma unroll
    for (int f = 0; f < 16; f++) {
        int col = h * 128 + (f >> 1) * 16 + (f & 1) * 8 + (l & 3) * 2;
        size_t a0 = ((size_t)(b * T_ + m0r)) * C_ + col;
        size_t a1 = a0 + (size_t)8 * C_;
        *reinterpret_cast<__half2*>(yh + a0) = __floats2half2_rn(o[f][0] * i0, o[f][1] * i0);
        *reinterpret_cast<__half2*>(yh + a1) = __floats2half2_rn(o[f][2] * i1, o[f][3] * i1);
    }
}

// ---------------- launch ------------------------------------------------------
extern "C" void kernel_launch(void* const* d_in, const int* in_sizes, int n_in,
                              void* d_out, int out_size) {
    const float* x     = (const float*)d_in[0];
    const float* ve    = (const float*)d_in[1];
    const float* Wq    = (const float*)d_in[2];
    const float* Wk    = (const float*)d_in[3];
    const float* Wv    = (const float*)d_in[4];
    const float* Wproj = (const float*)d_in[5];
    const float* Wg    = (const float*)d_in[6];
    const float* cosp  = (const float*)d_in[7];
    const float* sinp  = (const float*)d_in[8];
    const int*   winp  = (const int*)d_in[9];
    float* out = (float*)d_out;

    void *pg, *pxh, *pyh, *pqh, *pkh, *pvh;
    void *pwqh, *pwkh, *pwvh, *pwph;
    cudaGetSymbolAddress(&pg,  g_gate);
    cudaGetSymbolAddress(&pxh, g_xh);
    cudaGetSymbolAddress(&pyh, g_yh);
    cudaGetSymbolAddress(&pqh, g_qh);
    cudaGetSymbolAddress(&pkh, g_kh);
    cudaGetSymbolAddress(&pvh, g_vh);
    cudaGetSymbolAddress(&pwqh, g_wqh); cudaGetSymbolAddress(&pwkh, g_wkh);
    cudaGetSymbolAddress(&pwvh, g_wvh); cudaGetSymbolAddress(&pwph, g_wph);

    cudaFuncSetAttribute(proj_mma, cudaFuncAttributeMaxDynamicSharedMemorySize, PROJ_SMEM);
    cudaFuncSetAttribute(outproj_mma, cudaFuncAttributeMaxDynamicSharedMemorySize, GEMM_SMEM);
    cudaFuncSetAttribute(attn_mma, cudaFuncAttributeMaxDynamicSharedMemorySize, ATT_SMEM);

    // 0) fp16 conversions (x + 4 weights, one launch)
    conv_kernel<<<dim3(M_*C_/1024, 5), 256>>>(
        x, Wq, Wk, Wv, Wproj,
        (__half*)pxh, (__half*)pwqh, (__half*)pwkh, (__half*)pwvh, (__half*)pwph);

    // 1) gate
    gate_kernel<<<(M_ * H_ + 255) / 256, 256>>>(x, Wg, (float*)pg);

    // 2) fused q/k/v projections (1-product each)
    proj_mma<<<dim3(C_ / 128, M_ / 128, 3), 256, PROJ_SMEM>>>(
        (const __half*)pxh,
        (const __half*)pwqh, (const __half*)pwkh, (const __half*)pwvh,
        (__half*)pqh, (__half*)pkh, (__half*)pvh,
        ve, (const float*)pg, cosp, sinp);

    // 3) tensor-core attention (S and PV 1-product) -> fp16 y
    attn_mma<<<dim3(T_ / 128, H_, B_), 256, ATT_SMEM>>>(
        (const __half*)pqh, (const __half*)pkh, (const __half*)pvh,
        (__half*)pyh, winp);

    // 4) output projection (1-product)
    outproj_mma<<<dim3(C_ / 128, M_ / 128), 256, GEMM_SMEM>>>(
        (const __half*)pyh, (const __half*)pwph, out);
}

// round 15
// speedup vs baseline: 2.4660x; 1.0108x over previous
#include <cuda_runtime.h>
#include <cuda_fp16.h>
#include <math.h>
#include <stdint.h>

#define B_ 2
#define T_ 2048
#define C_ 2048
#define H_ 16
#define D_ 128
#define M_ (B_*T_)   // 4096 rows

// ---------------- scratch (device globals; no allocation allowed) -------------
__device__ float g_gate[M_*H_];
__device__ __half g_xh[M_*C_];
__device__ __half g_yh[M_*C_];
__device__ __half g_qh[M_*C_];     // [b][h][t][d] single fp16
__device__ __half g_kh[M_*C_];     // [b][h][t][d] single fp16
__device__ __half g_vh[M_*C_];     // [b][h][t][d] single fp16
__device__ __half g_wqh[C_*C_];
__device__ __half g_wkh[C_*C_];
__device__ __half g_wvh[C_*C_];
__device__ __half g_wph[C_*C_];

// ================= PTX helpers =================
__device__ __forceinline__ uint32_t smem_u32(const void* p) {
    uint32_t a;
    asm("{ .reg .u64 t; cvta.to.shared.u64 t, %1; cvt.u32.u64 %0, t; }" : "=r"(a) : "l"(p));
    return a;
}
__device__ __forceinline__ void cpasync16(uint32_t saddr, const void* gaddr) {
    asm volatile("cp.async.cg.shared.global [%0], [%1], 16;" :: "r"(saddr), "l"(gaddr) : "memory");
}
__device__ __forceinline__ void ldsm4(uint32_t addr, uint32_t* r) {
    asm volatile("ldmatrix.sync.aligned.m8n8.x4.shared.b16 {%0,%1,%2,%3}, [%4];"
                 : "=r"(r[0]), "=r"(r[1]), "=r"(r[2]), "=r"(r[3]) : "r"(addr));
}
__device__ __forceinline__ void ldsm4t(uint32_t addr, uint32_t* r) {
    asm volatile("ldmatrix.sync.aligned.m8n8.x4.trans.shared.b16 {%0,%1,%2,%3}, [%4];"
                 : "=r"(r[0]), "=r"(r[1]), "=r"(r[2]), "=r"(r[3]) : "r"(addr));
}
__device__ __forceinline__ float ex2f(float x) {
    float y; asm("ex2.approx.f32 %0, %1;" : "=f"(y) : "f"(x)); return y;
}
#define MMA_F16(Cf, Af, B0, B1)                                               \
    asm volatile("mma.sync.aligned.m16n8k16.row.col.f32.f16.f16.f32 "          \
        "{%0,%1,%2,%3},{%4,%5,%6,%7},{%8,%9},{%0,%1,%2,%3};"                   \
        : "+f"((Cf)[0]), "+f"((Cf)[1]), "+f"((Cf)[2]), "+f"((Cf)[3])           \
        : "r"((Af)[0]), "r"((Af)[1]), "r"((Af)[2]), "r"((Af)[3]),              \
          "r"(B0), "r"(B1))

__device__ __forceinline__ uint32_t packh(float a, float b) {
    __half2 h = __floats2half2_rn(a, b);
    return *reinterpret_cast<uint32_t*>(&h);
}

// ---------------- fp32 -> fp16 conversions -------------------------------------
__global__ void conv_kernel(const float* __restrict__ x,
                            const float* __restrict__ w0, const float* __restrict__ w1,
                            const float* __restrict__ w2, const float* __restrict__ w3,
                            __half* __restrict__ xh,
                            __half* __restrict__ h0, __half* __restrict__ h1,
                            __half* __restrict__ h2, __half* __restrict__ h3) {
    int which = blockIdx.y;
    const float* src; __half* dst; int n;
    switch (which) {
        case 0: src = x;  dst = xh; n = M_*C_; break;
        case 1: src = w0; dst = h0; n = C_*C_; break;
        case 2: src = w1; dst = h1; n = C_*C_; break;
        case 3: src = w2; dst = h2; n = C_*C_; break;
        default: src = w3; dst = h3; n = C_*C_; break;
    }
    int i = (blockIdx.x * blockDim.x + threadIdx.x) * 4;
    if (i >= n) return;
    float4 v = *(const float4*)(src + i);
    ((__half2*)(dst + i))[0] = __floats2half2_rn(v.x, v.y);
    ((__half2*)(dst + i))[1] = __floats2half2_rn(v.z, v.w);
}

// ---------------- gate = 3*sigmoid(x[:, :12] @ Wg^T) --------------------------
__global__ void gate_kernel(const float* __restrict__ x, const float* __restrict__ Wg,
                            float* __restrict__ gate) {
    int idx = blockIdx.x * blockDim.x + threadIdx.x;
    if (idx >= M_ * H_) return;
    int m = idx >> 4, h = idx & 15;
    float s = 0.f;
#pragma unroll
    for (int j = 0; j < 12; j++) s += x[(size_t)m * C_ + j] * Wg[h * 12 + j];
    gate[idx] = 3.f / (1.f + __expf(-s));
}

// ---------------- 1-product fp16 GEMM core (shared by proj + out) --------------
#define RS_B 80
#define ARR_B (128 * RS_B)
#define NSTAGE 3
#define NCHUNK 64
#define STGB (2 * ARR_B)                 // Ah | Bh
#define GEMM_SMEM (NSTAGE * STGB)        // 61440
#define PROJ_SMEM (128 * 132 * 4)        // 67584 — rope epilogue staging

struct Frag {
    uint32_t a_h[2][4];
    uint32_t b_h[8][2];
};

__device__ __forceinline__ void gemm_core(
    uint32_t sb, int tid, int wid, int lane,
    const __half* Ah, const __half* Bh, int arow0, int brow0,
    float (&acc)[2][8][4]) {
    const int warp_m = wid & 3, warp_n = wid >> 2;

    auto load_chunk = [&](int stage, int chunk) {
        const int k0 = chunk * 32;
        uint32_t stg = sb + stage * STGB;
#pragma unroll
        for (int j = 0; j < 4; j++) {
            int u = tid + j * 256;
            int arr = u >> 9;
            int rc = u & 511;
            int r = rc >> 2, c = rc & 3;
            uint32_t sa = stg + arr * ARR_B + r * RS_B + c * 16;
            const __half* src = arr ? Bh : Ah;
            int row = arr ? (brow0 + r) : (arow0 + r);
            cpasync16(sa, src + (size_t)row * C_ + k0 + c * 8);
        }
        asm volatile("cp.async.commit_group;" ::: "memory");
    };

    const uint32_t a_lane_off = (uint32_t)((warp_m * 32 + (lane & 15)) * RS_B + (lane >> 4) * 16);
    const uint32_t b_lane_off = (uint32_t)((warp_n * 64 + (lane & 15)) * RS_B + (lane >> 4) * 16);

    auto ldfr = [&](Frag& F, uint32_t stg, uint32_t koff) {
#pragma unroll
        for (int mi = 0; mi < 2; mi++)
            ldsm4(stg + a_lane_off + mi * 16 * RS_B + koff, F.a_h[mi]);
#pragma unroll
        for (int nf4 = 0; nf4 < 4; nf4++) {
            uint32_t t[4];
            ldsm4(stg + ARR_B + b_lane_off + nf4 * 16 * RS_B + koff, t);
            F.b_h[nf4 * 2][0] = t[0]; F.b_h[nf4 * 2][1] = t[2];
            F.b_h[nf4 * 2 + 1][0] = t[1]; F.b_h[nf4 * 2 + 1][1] = t[3];
        }
    };

    auto mmab = [&](Frag& F) {
#pragma unroll
        for (int mi = 0; mi < 2; mi++)
#pragma unroll
            for (int nf = 0; nf < 8; nf++) MMA_F16(acc[mi][nf], F.a_h[mi], F.b_h[nf][0], F.b_h[nf][1]);
    };

    load_chunk(0, 0);
    load_chunk(1, 1);
    load_chunk(2, 2);
    asm volatile("cp.async.wait_group 2;" ::: "memory");
    __syncthreads();

    Frag Fa, Fb;
    ldfr(Fa, sb, 0);

    for (int i = 0; i < NCHUNK; i++) {
        uint32_t stg = sb + (i % NSTAGE) * STGB;
        ldfr(Fb, stg, 32);
        mmab(Fa);
        if (i < NCHUNK - 1) {
            if (i < NCHUNK - 2) asm volatile("cp.async.wait_group 1;" ::: "memory");
            else                asm volatile("cp.async.wait_group 0;" ::: "memory");
            __syncthreads();
            uint32_t stg2 = sb + ((i + 1) % NSTAGE) * STGB;
            ldfr(Fa, stg2, 0);
            if (i + 3 < NCHUNK) load_chunk(i % NSTAGE, i + 3);
        }
        mmab(Fb);
    }
}

// fused q/k/v projection: blockIdx.z selects weight + epilogue
__global__ __launch_bounds__(256, 1) void proj_mma(
    const __half* __restrict__ xh,
    const __half* __restrict__ Wq, const __half* __restrict__ Wk,
    const __half* __restrict__ Wv,
    __half* __restrict__ qh, __half* __restrict__ kh, __half* __restrict__ vh,
    const float* __restrict__ ve, const float* __restrict__ gate,
    const float* __restrict__ cosp, const float* __restrict__ sinp) {
    extern __shared__ char smc[];
    const uint32_t sb = smem_u32(smc);
    const int tid = threadIdx.x;
    const int wid = tid >> 5, lane = tid & 31;
    const int warp_m = wid & 3, warp_n = wid >> 2;
    const int arow0 = blockIdx.y * 128, brow0 = blockIdx.x * 128;
    const int z = blockIdx.z;
    const __half* Bh = (z == 0) ? Wq : (z == 1) ? Wk : Wv;

    float acc[2][8][4];
#pragma unroll
    for (int mi = 0; mi < 2; mi++)
#pragma unroll
        for (int nf = 0; nf < 8; nf++)
#pragma unroll
            for (int q = 0; q < 4; q++) acc[mi][nf][q] = 0.f;

    gemm_core(sb, tid, wid, lane, xh, Bh, arow0, brow0, acc);

    if (z < 2) {
        // rope + rms epilogue -> single fp16 [b][h][t][d]
        __half* Oh = (z == 0) ? qh : kh;
        __syncthreads();
        float* S = (float*)smc;
        const int rbase = warp_m * 32 + (lane >> 2);
        const int cbase = warp_n * 64 + (lane & 3) * 2;
#pragma unroll
        for (int mi = 0; mi < 2; mi++)
#pragma unroll
            for (int nf = 0; nf < 8; nf++) {
                int r = rbase + mi * 16, c = cbase + nf * 8;
                S[r * 132 + c] = acc[mi][nf][0];
                S[r * 132 + c + 1] = acc[mi][nf][1];
                S[(r + 8) * 132 + c] = acc[mi][nf][2];
                S[(r + 8) * 132 + c + 1] = acc[mi][nf][3];
            }
        __syncthreads();
        const int hh = brow0 >> 7;
        const int d0 = lane * 2;
#pragma unroll 4
        for (int rr = wid * 16; rr < wid * 16 + 16; rr++) {
            int m = arow0 + rr, b = m >> 11, t = m & 2047;
            float xa0 = S[rr * 132 + d0],      xa1 = S[rr * 132 + d0 + 1];
            float xb0 = S[rr * 132 + d0 + 64], xb1 = S[rr * 132 + d0 + 65];
            float2 cc = *(const float2*)(cosp + t * 64 + d0);
            float2 sn = *(const float2*)(sinp + t * 64 + d0);
            float y1a = xa0 * cc.x + xb0 * sn.x;
            float y1b = xa1 * cc.y + xb1 * sn.y;
            float y2a = xb0 * cc.x - xa0 * sn.x;
            float y2b = xb1 * cc.y - xa1 * sn.y;
            float ss = y1a * y1a + y1b * y1b + y2a * y2a + y2b * y2b;
#pragma unroll
            for (int off = 16; off; off >>= 1) ss += __shfl_xor_sync(0xffffffffu, ss, off);
            float r = rsqrtf(ss * (1.f / 128.f) + 1e-6f) * 1.2f;
            size_t ob = ((size_t)(b * H_ + hh) * T_ + t) * D_;
            *reinterpret_cast<__half2*>(Oh + ob + d0) = __floats2half2_rn(y1a * r, y1b * r);
            *reinterpret_cast<__half2*>(Oh + ob + d0 + 64) = __floats2half2_rn(y2a * r, y2b * r);
        }
        return;
    }

    // v epilogue: + gate*ve -> single fp16 [b][h][t][d]
    const int r0w = arow0 + warp_m * 32 + (lane >> 2);
    const int c0w = brow0 + warp_n * 64 + (lane & 3) * 2;
#pragma unroll
    for (int mi = 0; mi < 2; mi++) {
#pragma unroll
        for (int nf = 0; nf < 8; nf++) {
            int n = c0w + nf * 8;
            int m0 = r0w + mi * 16;
            int m1 = m0 + 8;
            float v0 = acc[mi][nf][0], v1 = acc[mi][nf][1];
            float v2 = acc[mi][nf][2], v3 = acc[mi][nf][3];
            float g0 = gate[m0 * H_ + (n >> 7)];
            float g1 = gate[m1 * H_ + (n >> 7)];
            const float* ve0 = ve + (size_t)m0 * C_ + n;
            const float* ve1 = ve + (size_t)m1 * C_ + n;
            v0 += g0 * ve0[0]; v1 += g0 * ve0[1];
            v2 += g1 * ve1[0]; v3 += g1 * ve1[1];
            int hh = n >> 7, dd = n & 127;
            size_t o0 = ((size_t)((m0 >> 11) * H_ + hh) * T_ + (m0 & 2047)) * D_ + dd;
            size_t o1 = ((size_t)((m1 >> 11) * H_ + hh) * T_ + (m1 & 2047)) * D_ + dd;
            *reinterpret_cast<__half2*>(vh + o0) = __floats2half2_rn(v0, v1);
            *reinterpret_cast<__half2*>(vh + o1) = __floats2half2_rn(v2, v3);
        }
    }
}

// output projection: 1-product, fp32 out
__global__ __launch_bounds__(256, 1) void outproj_mma(
    const __half* __restrict__ yh, const __half* __restrict__ Wp,
    float* __restrict__ out) {
    extern __shared__ char smc[];
    const uint32_t sb = smem_u32(smc);
    const int tid = threadIdx.x;
    const int wid = tid >> 5, lane = tid & 31;
    const int warp_m = wid & 3, warp_n = wid >> 2;
    const int arow0 = blockIdx.y * 128, brow0 = blockIdx.x * 128;

    float acc[2][8][4];
#pragma unroll
    for (int mi = 0; mi < 2; mi++)
#pragma unroll
        for (int nf = 0; nf < 8; nf++)
#pragma unroll
            for (int q = 0; q < 4; q++) acc[mi][nf][q] = 0.f;

    gemm_core(sb, tid, wid, lane, yh, Wp, arow0, brow0, acc);

    const int r0w = arow0 + warp_m * 32 + (lane >> 2);
    const int c0w = brow0 + warp_n * 64 + (lane & 3) * 2;
#pragma unroll
    for (int mi = 0; mi < 2; mi++) {
#pragma unroll
        for (int nf = 0; nf < 8; nf++) {
            int n = c0w + nf * 8;
            int m0 = r0w + mi * 16;
            int m1 = m0 + 8;
            *(float2*)(out + (size_t)m0 * C_ + n) = make_float2(acc[mi][nf][0], acc[mi][nf][1]);
            *(float2*)(out + (size_t)m1 * C_ + n) = make_float2(acc[mi][nf][2], acc[mi][nf][3]);
        }
    }
}

// ---------------- tensor-core flash attention (single fp16) -------------------
// 128 threads (4 warps), q-tile 64 rows, KV tile 64, 2 stages (Kh|Vh).
// 2 CTAs/SM for cross-CTA MMA/softmax overlap. Fast-path softmax on full tiles.
#define QTB (64 * 272)               // 17408
#define KTB (64 * 272)               // 17408
#define KV_OFF QTB                   // 17408
#define STG (2 * KTB)                // 34816
#define ATT_SMEM (QTB + 2 * STG)     // 87040

__global__ __launch_bounds__(128, 2) void attn_mma(
    const __half* __restrict__ qh, const __half* __restrict__ kh,
    const __half* __restrict__ vh,
    __half* __restrict__ yh,
    const int* __restrict__ winp) {
    extern __shared__ char smc[];
    const uint32_t sb = smem_u32(smc);
    const int tid = threadIdx.x, w = tid >> 5, l = tid & 31;
    const int t0 = blockIdx.x * 64, h = blockIdx.y, b = blockIdx.z;
    int win = *winp;
    if (win <= 0 || win >= T_) win = T_;
    const size_t hb = (size_t)(b * H_ + h) * ((size_t)T_ * D_);

    // Q tile (64 rows)
#pragma unroll
    for (int j = 0; j < 8; j++) {
        int u = tid + j * 128;
        int r = u >> 4, c = u & 15;
        uint32_t so = (uint32_t)(r * 272 + c * 16);
        cpasync16(sb + so, qh + hb + (size_t)(t0 + r) * D_ + c * 8);
    }
    asm volatile("cp.async.commit_group;" ::: "memory");

    int start = t0 - win;
    if (start < 0) start = 0;
    start &= ~63;
    const int ntile = ((t0 - start) >> 6) + 1;

    auto loadKV = [&](int stg, int k0) {
        uint32_t bs = sb + KV_OFF + stg * STG;
#pragma unroll
        for (int j = 0; j < 16; j++) {
            int u = tid + j * 128;          // 0..2047
            int arr = u >> 10;
            int rc = u & 1023;
            int r = rc >> 4, c = rc & 15;
            uint32_t so = (uint32_t)(arr * KTB + r * 272 + c * 16);
            const __half* src = arr ? vh : kh;
            cpasync16(bs + so, src + hb + (size_t)(k0 + r) * D_ + c * 8);
        }
        asm volatile("cp.async.commit_group;" ::: "memory");
    };
    loadKV(0, start);
    if (ntile > 1) loadKV(1, start + 64);

    float o[16][4];
#pragma unroll
    for (int f = 0; f < 16; f++)
#pragma unroll
        for (int q = 0; q < 4; q++) o[f][q] = 0.f;
    float rm0 = -1e4f, rm1 = -1e4f, rl0 = 0.f, rl1 = 0.f;
    const float SC2 = 0.1275187989f;   // 1/sqrt(128) * log2(e)

    const uint32_t aoff = (uint32_t)((w * 16 + (l & 15)) * 272 + (l >> 4) * 16);
    const uint32_t boff = (uint32_t)((l & 15) * 272 + (l >> 4) * 16);
    const int r0 = t0 + w * 16 + (l >> 2), r1 = r0 + 8;
    const int wr_min = t0 + w * 16, wr_max = t0 + w * 16 + 15;

    for (int i = 0; i < ntile; i++) {
        int k0 = start + i * 64;
        if (i + 1 < ntile) asm volatile("cp.async.wait_group 1;" ::: "memory");
        else               asm volatile("cp.async.wait_group 0;" ::: "memory");
        __syncthreads();
        uint32_t bs = sb + KV_OFF + (i & 1) * STG;

        bool active = (k0 <= wr_max) && (k0 + 63 >= wr_min - win);
        if (active) {
            // ---- S = Q K^T (1-product) ----
            float s[8][4];
#pragma unroll
            for (int f = 0; f < 8; f++)
#pragma unroll
                for (int q = 0; q < 4; q++) s[f][q] = 0.f;
#pragma unroll
            for (int ks = 0; ks < 8; ks++) {
                uint32_t aq[4];
                uint32_t tk[4][4];
                ldsm4(sb + aoff + ks * 32, aq);
#pragma unroll
                for (int ng = 0; ng < 4; ng++)
                    ldsm4(bs + boff + ng * 16 * 272 + ks * 32, tk[ng]);
#pragma unroll
                for (int ng = 0; ng < 4; ng++) {
                    MMA_F16(s[ng * 2], aq, tk[ng][0], tk[ng][2]);
                    MMA_F16(s[ng * 2 + 1], aq, tk[ng][1], tk[ng][3]);
                }
            }

            // ---- online softmax (exp2 domain); fast path skips masking ----
            bool full = (k0 + 63 <= wr_min) && (k0 >= wr_max - win);
            float mx0 = -1e30f, mx1 = -1e30f;
            if (full) {
#pragma unroll
                for (int nf = 0; nf < 8; nf++) {
                    float x0 = s[nf][0] * SC2, x1 = s[nf][1] * SC2;
                    float x2 = s[nf][2] * SC2, x3 = s[nf][3] * SC2;
                    s[nf][0] = x0; s[nf][1] = x1; s[nf][2] = x2; s[nf][3] = x3;
                    mx0 = fmaxf(mx0, fmaxf(x0, x1));
                    mx1 = fmaxf(mx1, fmaxf(x2, x3));
                }
            } else {
#pragma unroll
                for (int nf = 0; nf < 8; nf++) {
                    int c0 = k0 + nf * 8 + (l & 3) * 2, c1 = c0 + 1;
                    float x0 = (c0 <= r0 && r0 - c0 <= win) ? s[nf][0] * SC2 : -1e30f;
                    float x1 = (c1 <= r0 && r0 - c1 <= win) ? s[nf][1] * SC2 : -1e30f;
                    float x2 = (c0 <= r1 && r1 - c0 <= win) ? s[nf][2] * SC2 : -1e30f;
                    float x3 = (c1 <= r1 && r1 - c1 <= win) ? s[nf][3] * SC2 : -1e30f;
                    s[nf][0] = x0; s[nf][1] = x1; s[nf][2] = x2; s[nf][3] = x3;
                    mx0 = fmaxf(mx0, fmaxf(x0, x1));
                    mx1 = fmaxf(mx1, fmaxf(x2, x3));
                }
            }
            mx0 = fmaxf(mx0, __shfl_xor_sync(0xffffffffu, mx0, 1));
            mx0 = fmaxf(mx0, __shfl_xor_sync(0xffffffffu, mx0, 2));
            mx1 = fmaxf(mx1, __shfl_xor_sync(0xffffffffu, mx1, 1));
            mx1 = fmaxf(mx1, __shfl_xor_sync(0xffffffffu, mx1, 2));
            float mn0 = fmaxf(rm0, fmaxf(mx0, -1e4f));
            float mn1 = fmaxf(rm1, fmaxf(mx1, -1e4f));
            float corr0 = ex2f(rm0 - mn0), corr1 = ex2f(rm1 - mn1);
            float ls0 = 0.f, ls1 = 0.f;
#pragma unroll
            for (int nf = 0; nf < 8; nf++) {
                float p0 = ex2f(s[nf][0] - mn0);
                float p1 = ex2f(s[nf][1] - mn0);
                float p2 = ex2f(s[nf][2] - mn1);
                float p3 = ex2f(s[nf][3] - mn1);
                s[nf][0] = p0; s[nf][1] = p1; s[nf][2] = p2; s[nf][3] = p3;
                ls0 += p0 + p1; ls1 += p2 + p3;
            }
            ls0 += __shfl_xor_sync(0xffffffffu, ls0, 1);
            ls0 += __shfl_xor_sync(0xffffffffu, ls0, 2);
            ls1 += __shfl_xor_sync(0xffffffffu, ls1, 1);
            ls1 += __shfl_xor_sync(0xffffffffu, ls1, 2);
            rl0 = rl0 * corr0 + ls0;
            rl1 = rl1 * corr1 + ls1;
            rm0 = mn0; rm1 = mn1;
#pragma unroll
            for (int f = 0; f < 16; f++) {
                o[f][0] *= corr0; o[f][1] *= corr0;
                o[f][2] *= corr1; o[f][3] *= corr1;
            }

            // ---- O += P V (1-product) ----
#pragma unroll
            for (int ks = 0; ks < 4; ks++) {
                uint32_t ph[4];
                ph[0] = packh(s[2 * ks][0], s[2 * ks][1]);
                ph[1] = packh(s[2 * ks][2], s[2 * ks][3]);
                ph[2] = packh(s[2 * ks + 1][0], s[2 * ks + 1][1]);
                ph[3] = packh(s[2 * ks + 1][2], s[2 * ks + 1][3]);
                uint32_t voff = (uint32_t)((ks * 16 + (l & 15)) * 272 + (l >> 4) * 16);
                uint32_t tv[8][4];
#pragma unroll
                for (int dg = 0; dg < 8; dg++)
                    ldsm4t(bs + KTB + voff + dg * 32, tv[dg]);
#pragma unroll
                for (int dg = 0; dg < 8; dg++) {
                    MMA_F16(o[dg * 2], ph, tv[dg][0], tv[dg][1]);
                    MMA_F16(o[dg * 2 + 1], ph, tv[dg][2], tv[dg][3]);
                }
            }
        }
        __syncthreads();
        if (i + 2 < ntile) loadKV(i & 1, k0 + 128);
    }

    float i0 = 1.f / rl0, i1 = 1.f / rl1;
    int m0r = t0 + w * 16 + (l >> 2);
#pragma unroll
    for (int f = 0; f < 16; f++) {
        int col = h * 128 + (f >> 1) * 16 + (f & 1) * 8 + (l & 3) * 2;
        size_t a0 = ((size_t)(b * T_ + m0r)) * C_ + col;
        size_t a1 = a0 + (size_t)8 * C_;
        *reinterpret_cast<__half2*>(yh + a0) = __floats2half2_rn(o[f][0] * i0, o[f][1] * i0);
        *reinterpret_cast<__half2*>(yh + a1) = __floats2half2_rn(o[f][2] * i1, o[f][3] * i1);
    }
}

// ---------------- launch ------------------------------------------------------
extern "C" void kernel_launch(void* const* d_in, const int* in_sizes, int n_in,
                              void* d_out, int out_size) {
    const float* x     = (const float*)d_in[0];
    const float* ve    = (const float*)d_in[1];
    const float* Wq    = (const float*)d_in[2];
    const float* Wk    = (const float*)d_in[3];
    const float* Wv    = (const float*)d_in[4];
    const float* Wproj = (const float*)d_in[5];
    const float* Wg    = (const float*)d_in[6];
    const float* cosp  = (const float*)d_in[7];
    const float* sinp  = (const float*)d_in[8];
    const int*   winp  = (const int*)d_in[9];
    float* out = (float*)d_out;

    void *pg, *pxh, *pyh, *pqh, *pkh, *pvh;
    void *pwqh, *pwkh, *pwvh, *pwph;
    cudaGetSymbolAddress(&pg,  g_gate);
    cudaGetSymbolAddress(&pxh, g_xh);
    cudaGetSymbolAddress(&pyh, g_yh);
    cudaGetSymbolAddress(&pqh, g_qh);
    cudaGetSymbolAddress(&pkh, g_kh);
    cudaGetSymbolAddress(&pvh, g_vh);
    cudaGetSymbolAddress(&pwqh, g_wqh); cudaGetSymbolAddress(&pwkh, g_wkh);
    cudaGetSymbolAddress(&pwvh, g_wvh); cudaGetSymbolAddress(&pwph, g_wph);

    cudaFuncSetAttribute(proj_mma, cudaFuncAttributeMaxDynamicSharedMemorySize, PROJ_SMEM);
    cudaFuncSetAttribute(outproj_mma, cudaFuncAttributeMaxDynamicSharedMemorySize, GEMM_SMEM);
    cudaFuncSetAttribute(attn_mma, cudaFuncAttributeMaxDynamicSharedMemorySize, ATT_SMEM);

    // 0) fp16 conversions (x + 4 weights, one launch)
    conv_kernel<<<dim3(M_*C_/1024, 5), 256>>>(
        x, Wq, Wk, Wv, Wproj,
        (__half*)pxh, (__half*)pwqh, (__half*)pwkh, (__half*)pwvh, (__half*)pwph);

    // 1) gate
    gate_kernel<<<(M_ * H_ + 255) / 256, 256>>>(x, Wg, (float*)pg);

    // 2) fused q/k/v projections (1-product each)
    proj_mma<<<dim3(C_ / 128, M_ / 128, 3), 256, PROJ_SMEM>>>(
        (const __half*)pxh,
        (const __half*)pwqh, (const __half*)pwkh, (const __half*)pwvh,
        (__half*)pqh, (__half*)pkh, (__half*)pvh,
        ve, (const float*)pg, cosp, sinp);

    // 3) tensor-core attention (q-tile 64, 2 CTA/SM) -> fp16 y
    attn_mma<<<dim3(T_ / 64, H_, B_), 128, ATT_SMEM>>>(
        (const __half*)pqh, (const __half*)pkh, (const __half*)pvh,
        (__half*)pyh, winp);

    // 4) output projection (1-product)
    outproj_mma<<<dim3(C_ / 128, M_ / 128), 256, GEMM_SMEM>>>(
        (const __half*)pyh, (const __half*)pwph, out);
}

// round 16
// speedup vs baseline: 2.4661x; 1.0000x over previous
#include <cuda_runtime.h>
#include <cuda_fp16.h>
#include <math.h>
#include <stdint.h>

#define B_ 2
#define T_ 2048
#define C_ 2048
#define H_ 16
#define D_ 128
#define M_ (B_*T_)   // 4096 rows

// ---------------- scratch (device globals; no allocation allowed) -------------
__device__ float g_gate[M_*H_];
__device__ __half g_xh[M_*C_];
__device__ __half g_yh[M_*C_];
__device__ __half g_qh[M_*C_];     // [b][h][t][d] single fp16
__device__ __half g_kh[M_*C_];     // [b][h][t][d] single fp16
__device__ __half g_vh[M_*C_];     // [b][h][t][d] single fp16
__device__ __half g_wqh[C_*C_];
__device__ __half g_wkh[C_*C_];
__device__ __half g_wvh[C_*C_];
__device__ __half g_wph[C_*C_];

// ================= PTX helpers =================
__device__ __forceinline__ uint32_t smem_u32(const void* p) {
    uint32_t a;
    asm("{ .reg .u64 t; cvta.to.shared.u64 t, %1; cvt.u32.u64 %0, t; }" : "=r"(a) : "l"(p));
    return a;
}
__device__ __forceinline__ void cpasync16(uint32_t saddr, const void* gaddr) {
    asm volatile("cp.async.cg.shared.global [%0], [%1], 16;" :: "r"(saddr), "l"(gaddr) : "memory");
}
__device__ __forceinline__ void ldsm4(uint32_t addr, uint32_t* r) {
    asm volatile("ldmatrix.sync.aligned.m8n8.x4.shared.b16 {%0,%1,%2,%3}, [%4];"
                 : "=r"(r[0]), "=r"(r[1]), "=r"(r[2]), "=r"(r[3]) : "r"(addr));
}
__device__ __forceinline__ void ldsm4t(uint32_t addr, uint32_t* r) {
    asm volatile("ldmatrix.sync.aligned.m8n8.x4.trans.shared.b16 {%0,%1,%2,%3}, [%4];"
                 : "=r"(r[0]), "=r"(r[1]), "=r"(r[2]), "=r"(r[3]) : "r"(addr));
}
__device__ __forceinline__ float ex2f(float x) {
    float y; asm("ex2.approx.f32 %0, %1;" : "=f"(y) : "f"(x)); return y;
}
#define MMA_F16(Cf, Af, B0, B1)                                               \
    asm volatile("mma.sync.aligned.m16n8k16.row.col.f32.f16.f16.f32 "          \
        "{%0,%1,%2,%3},{%4,%5,%6,%7},{%8,%9},{%0,%1,%2,%3};"                   \
        : "+f"((Cf)[0]), "+f"((Cf)[1]), "+f"((Cf)[2]), "+f"((Cf)[3])           \
        : "r"((Af)[0]), "r"((Af)[1]), "r"((Af)[2]), "r"((Af)[3]),              \
          "r"(B0), "r"(B1))

__device__ __forceinline__ uint32_t packh(float a, float b) {
    __half2 h = __floats2half2_rn(a, b);
    return *reinterpret_cast<uint32_t*>(&h);
}

// ---------------- fp32 -> fp16 conversions + gate (one launch) -----------------
// blockIdx.y: 0 -> x (M*C), 1..4 -> weights (C*C each), 5 -> gate
__global__ void conv_kernel(const float* __restrict__ x,
                            const float* __restrict__ w0, const float* __restrict__ w1,
                            const float* __restrict__ w2, const float* __restrict__ w3,
                            const float* __restrict__ Wg,
                            __half* __restrict__ xh,
                            __half* __restrict__ h0, __half* __restrict__ h1,
                            __half* __restrict__ h2, __half* __restrict__ h3,
                            float* __restrict__ gate) {
    int which = blockIdx.y;
    if (which == 5) {
        int idx = blockIdx.x * blockDim.x + threadIdx.x;
        if (idx >= M_ * H_) return;
        int m = idx >> 4, h = idx & 15;
        float s = 0.f;
#pragma unroll
        for (int j = 0; j < 12; j++) s += x[(size_t)m * C_ + j] * Wg[h * 12 + j];
        gate[idx] = 3.f / (1.f + __expf(-s));
        return;
    }
    const float* src; __half* dst; int n;
    switch (which) {
        case 0: src = x;  dst = xh; n = M_*C_; break;
        case 1: src = w0; dst = h0; n = C_*C_; break;
        case 2: src = w1; dst = h1; n = C_*C_; break;
        case 3: src = w2; dst = h2; n = C_*C_; break;
        default: src = w3; dst = h3; n = C_*C_; break;
    }
    int i = (blockIdx.x * blockDim.x + threadIdx.x) * 4;
    if (i >= n) return;
    float4 v = *(const float4*)(src + i);
    ((__half2*)(dst + i))[0] = __floats2half2_rn(v.x, v.y);
    ((__half2*)(dst + i))[1] = __floats2half2_rn(v.z, v.w);
}

// ---------------- 1-product fp16 GEMM core (shared by proj + out) --------------
#define RS_B 80
#define ARR_B (128 * RS_B)
#define NSTAGE 3
#define NCHUNK 64
#define STGB (2 * ARR_B)                 // Ah | Bh
#define GEMM_SMEM (NSTAGE * STGB)        // 61440
#define PROJ_SMEM (128 * 132 * 4)        // 67584 — rope epilogue staging

struct Frag {
    uint32_t a_h[2][4];
    uint32_t b_h[8][2];
};

__device__ __forceinline__ void gemm_core(
    uint32_t sb, int tid, int wid, int lane,
    const __half* Ah, const __half* Bh, int arow0, int brow0,
    float (&acc)[2][8][4]) {
    const int warp_m = wid & 3, warp_n = wid >> 2;

    auto load_chunk = [&](int stage, int chunk) {
        const int k0 = chunk * 32;
        uint32_t stg = sb + stage * STGB;
#pragma unroll
        for (int j = 0; j < 4; j++) {
            int u = tid + j * 256;
            int arr = u >> 9;
            int rc = u & 511;
            int r = rc >> 2, c = rc & 3;
            uint32_t sa = stg + arr * ARR_B + r * RS_B + c * 16;
            const __half* src = arr ? Bh : Ah;
            int row = arr ? (brow0 + r) : (arow0 + r);
            cpasync16(sa, src + (size_t)row * C_ + k0 + c * 8);
        }
        asm volatile("cp.async.commit_group;" ::: "memory");
    };

    const uint32_t a_lane_off = (uint32_t)((warp_m * 32 + (lane & 15)) * RS_B + (lane >> 4) * 16);
    const uint32_t b_lane_off = (uint32_t)((warp_n * 64 + (lane & 15)) * RS_B + (lane >> 4) * 16);

    auto ldfr = [&](Frag& F, uint32_t stg, uint32_t koff) {
#pragma unroll
        for (int mi = 0; mi < 2; mi++)
            ldsm4(stg + a_lane_off + mi * 16 * RS_B + koff, F.a_h[mi]);
#pragma unroll
        for (int nf4 = 0; nf4 < 4; nf4++) {
            uint32_t t[4];
            ldsm4(stg + ARR_B + b_lane_off + nf4 * 16 * RS_B + koff, t);
            F.b_h[nf4 * 2][0] = t[0]; F.b_h[nf4 * 2][1] = t[2];
            F.b_h[nf4 * 2 + 1][0] = t[1]; F.b_h[nf4 * 2 + 1][1] = t[3];
        }
    };

    auto mmab = [&](Frag& F) {
#pragma unroll
        for (int mi = 0; mi < 2; mi++)
#pragma unroll
            for (int nf = 0; nf < 8; nf++) MMA_F16(acc[mi][nf], F.a_h[mi], F.b_h[nf][0], F.b_h[nf][1]);
    };

    load_chunk(0, 0);
    load_chunk(1, 1);
    load_chunk(2, 2);
    asm volatile("cp.async.wait_group 2;" ::: "memory");
    __syncthreads();

    Frag Fa, Fb;
    ldfr(Fa, sb, 0);

    for (int i = 0; i < NCHUNK; i++) {
        uint32_t stg = sb + (i % NSTAGE) * STGB;
        ldfr(Fb, stg, 32);
        mmab(Fa);
        if (i < NCHUNK - 1) {
            if (i < NCHUNK - 2) asm volatile("cp.async.wait_group 1;" ::: "memory");
            else                asm volatile("cp.async.wait_group 0;" ::: "memory");
            __syncthreads();
            uint32_t stg2 = sb + ((i + 1) % NSTAGE) * STGB;
            ldfr(Fa, stg2, 0);
            if (i + 3 < NCHUNK) load_chunk(i % NSTAGE, i + 3);
        }
        mmab(Fb);
    }
}

// fused q/k/v projection: blockIdx.z selects weight + epilogue
__global__ __launch_bounds__(256, 1) void proj_mma(
    const __half* __restrict__ xh,
    const __half* __restrict__ Wq, const __half* __restrict__ Wk,
    const __half* __restrict__ Wv,
    __half* __restrict__ qh, __half* __restrict__ kh, __half* __restrict__ vh,
    const float* __restrict__ ve, const float* __restrict__ gate,
    const float* __restrict__ cosp, const float* __restrict__ sinp) {
    extern __shared__ char smc[];
    const uint32_t sb = smem_u32(smc);
    const int tid = threadIdx.x;
    const int wid = tid >> 5, lane = tid & 31;
    const int warp_m = wid & 3, warp_n = wid >> 2;
    const int arow0 = blockIdx.y * 128, brow0 = blockIdx.x * 128;
    const int z = blockIdx.z;
    const __half* Bh = (z == 0) ? Wq : (z == 1) ? Wk : Wv;

    float acc[2][8][4];
#pragma unroll
    for (int mi = 0; mi < 2; mi++)
#pragma unroll
        for (int nf = 0; nf < 8; nf++)
#pragma unroll
            for (int q = 0; q < 4; q++) acc[mi][nf][q] = 0.f;

    gemm_core(sb, tid, wid, lane, xh, Bh, arow0, brow0, acc);

    if (z < 2) {
        // rope + rms epilogue -> single fp16 [b][h][t][d]
        __half* Oh = (z == 0) ? qh : kh;
        __syncthreads();
        float* S = (float*)smc;
        const int rbase = warp_m * 32 + (lane >> 2);
        const int cbase = warp_n * 64 + (lane & 3) * 2;
#pragma unroll
        for (int mi = 0; mi < 2; mi++)
#pragma unroll
            for (int nf = 0; nf < 8; nf++) {
                int r = rbase + mi * 16, c = cbase + nf * 8;
                S[r * 132 + c] = acc[mi][nf][0];
                S[r * 132 + c + 1] = acc[mi][nf][1];
                S[(r + 8) * 132 + c] = acc[mi][nf][2];
                S[(r + 8) * 132 + c + 1] = acc[mi][nf][3];
            }
        __syncthreads();
        const int hh = brow0 >> 7;
        const int d0 = lane * 2;
#pragma unroll 4
        for (int rr = wid * 16; rr < wid * 16 + 16; rr++) {
            int m = arow0 + rr, b = m >> 11, t = m & 2047;
            float xa0 = S[rr * 132 + d0],      xa1 = S[rr * 132 + d0 + 1];
            float xb0 = S[rr * 132 + d0 + 64], xb1 = S[rr * 132 + d0 + 65];
            float2 cc = *(const float2*)(cosp + t * 64 + d0);
            float2 sn = *(const float2*)(sinp + t * 64 + d0);
            float y1a = xa0 * cc.x + xb0 * sn.x;
            float y1b = xa1 * cc.y + xb1 * sn.y;
            float y2a = xb0 * cc.x - xa0 * sn.x;
            float y2b = xb1 * cc.y - xa1 * sn.y;
            float ss = y1a * y1a + y1b * y1b + y2a * y2a + y2b * y2b;
#pragma unroll
            for (int off = 16; off; off >>= 1) ss += __shfl_xor_sync(0xffffffffu, ss, off);
            float r = rsqrtf(ss * (1.f / 128.f) + 1e-6f) * 1.2f;
            size_t ob = ((size_t)(b * H_ + hh) * T_ + t) * D_;
            *reinterpret_cast<__half2*>(Oh + ob + d0) = __floats2half2_rn(y1a * r, y1b * r);
            *reinterpret_cast<__half2*>(Oh + ob + d0 + 64) = __floats2half2_rn(y2a * r, y2b * r);
        }
        return;
    }

    // v epilogue: + gate*ve -> single fp16 [b][h][t][d]
    const int r0w = arow0 + warp_m * 32 + (lane >> 2);
    const int c0w = brow0 + warp_n * 64 + (lane & 3) * 2;
#pragma unroll
    for (int mi = 0; mi < 2; mi++) {
#pragma unroll
        for (int nf = 0; nf < 8; nf++) {
            int n = c0w + nf * 8;
            int m0 = r0w + mi * 16;
            int m1 = m0 + 8;
            float v0 = acc[mi][nf][0], v1 = acc[mi][nf][1];
            float v2 = acc[mi][nf][2], v3 = acc[mi][nf][3];
            float g0 = gate[m0 * H_ + (n >> 7)];
            float g1 = gate[m1 * H_ + (n >> 7)];
            const float* ve0 = ve + (size_t)m0 * C_ + n;
            const float* ve1 = ve + (size_t)m1 * C_ + n;
            v0 += g0 * ve0[0]; v1 += g0 * ve0[1];
            v2 += g1 * ve1[0]; v3 += g1 * ve1[1];
            int hh = n >> 7, dd = n & 127;
            size_t o0 = ((size_t)((m0 >> 11) * H_ + hh) * T_ + (m0 & 2047)) * D_ + dd;
            size_t o1 = ((size_t)((m1 >> 11) * H_ + hh) * T_ + (m1 & 2047)) * D_ + dd;
            *reinterpret_cast<__half2*>(vh + o0) = __floats2half2_rn(v0, v1);
            *reinterpret_cast<__half2*>(vh + o1) = __floats2half2_rn(v2, v3);
        }
    }
}

// output projection: 1-product, fp32 out
__global__ __launch_bounds__(256, 1) void outproj_mma(
    const __half* __restrict__ yh, const __half* __restrict__ Wp,
    float* __restrict__ out) {
    extern __shared__ char smc[];
    const uint32_t sb = smem_u32(smc);
    const int tid = threadIdx.x;
    const int wid = tid >> 5, lane = tid & 31;
    const int warp_m = wid & 3, warp_n = wid >> 2;
    const int arow0 = blockIdx.y * 128, brow0 = blockIdx.x * 128;

    float acc[2][8][4];
#pragma unroll
    for (int mi = 0; mi < 2; mi++)
#pragma unroll
        for (int nf = 0; nf < 8; nf++)
#pragma unroll
            for (int q = 0; q < 4; q++) acc[mi][nf][q] = 0.f;

    gemm_core(sb, tid, wid, lane, yh, Wp, arow0, brow0, acc);

    const int r0w = arow0 + warp_m * 32 + (lane >> 2);
    const int c0w = brow0 + warp_n * 64 + (lane & 3) * 2;
#pragma unroll
    for (int mi = 0; mi < 2; mi++) {
#pragma unroll
        for (int nf = 0; nf < 8; nf++) {
            int n = c0w + nf * 8;
            int m0 = r0w + mi * 16;
            int m1 = m0 + 8;
            *(float2*)(out + (size_t)m0 * C_ + n) = make_float2(acc[mi][nf][0], acc[mi][nf][1]);
            *(float2*)(out + (size_t)m1 * C_ + n) = make_float2(acc[mi][nf][2], acc[mi][nf][3]);
        }
    }
}

// ---------------- tensor-core flash attention (single fp16) -------------------
// 128 threads (4 warps), q-tile 64 rows, KV tile 64, 2 stages (Kh|Vh).
// 2 CTAs/SM; Q fragments hoisted to registers; fast-path softmax on full tiles.
#define QTB (64 * 272)               // 17408
#define KTB (64 * 272)               // 17408
#define KV_OFF QTB                   // 17408
#define STG (2 * KTB)                // 34816
#define ATT_SMEM (QTB + 2 * STG)     // 87040

__global__ __launch_bounds__(128, 2) void attn_mma(
    const __half* __restrict__ qh, const __half* __restrict__ kh,
    const __half* __restrict__ vh,
    __half* __restrict__ yh,
    const int* __restrict__ winp) {
    extern __shared__ char smc[];
    const uint32_t sb = smem_u32(smc);
    const int tid = threadIdx.x, w = tid >> 5, l = tid & 31;
    const int t0 = blockIdx.x * 64, h = blockIdx.y, b = blockIdx.z;
    int win = *winp;
    if (win <= 0 || win >= T_) win = T_;
    const size_t hb = (size_t)(b * H_ + h) * ((size_t)T_ * D_);

    // Q tile (64 rows)
#pragma unroll
    for (int j = 0; j < 8; j++) {
        int u = tid + j * 128;
        int r = u >> 4, c = u & 15;
        uint32_t so = (uint32_t)(r * 272 + c * 16);
        cpasync16(sb + so, qh + hb + (size_t)(t0 + r) * D_ + c * 8);
    }
    asm volatile("cp.async.commit_group;" ::: "memory");

    int start = t0 - win;
    if (start < 0) start = 0;
    start &= ~63;
    const int ntile = ((t0 - start) >> 6) + 1;

    auto loadKV = [&](int stg, int k0) {
        uint32_t bs = sb + KV_OFF + stg * STG;
#pragma unroll
        for (int j = 0; j < 16; j++) {
            int u = tid + j * 128;          // 0..2047
            int arr = u >> 10;
            int rc = u & 1023;
            int r = rc >> 4, c = rc & 15;
            uint32_t so = (uint32_t)(arr * KTB + r * 272 + c * 16);
            const __half* src = arr ? vh : kh;
            cpasync16(bs + so, src + hb + (size_t)(k0 + r) * D_ + c * 8);
        }
        asm volatile("cp.async.commit_group;" ::: "memory");
    };
    loadKV(0, start);
    if (ntile > 1) loadKV(1, start + 64);

    float o[16][4];
#pragma unroll
    for (int f = 0; f < 16; f++)
#pragma unroll
        for (int q = 0; q < 4; q++) o[f][q] = 0.f;
    float rm0 = -1e4f, rm1 = -1e4f, rl0 = 0.f, rl1 = 0.f;
    const float SC2 = 0.1275187989f;   // 1/sqrt(128) * log2(e)

    const uint32_t aoff = (uint32_t)((w * 16 + (l & 15)) * 272 + (l >> 4) * 16);
    const uint32_t boff = (uint32_t)((l & 15) * 272 + (l >> 4) * 16);
    const int r0 = t0 + w * 16 + (l >> 2), r1 = r0 + 8;
    const int wr_min = t0 + w * 16, wr_max = t0 + w * 16 + 15;

    uint32_t aq_all[8][4];   // persistent Q fragments

    for (int i = 0; i < ntile; i++) {
        int k0 = start + i * 64;
        if (i + 1 < ntile) asm volatile("cp.async.wait_group 1;" ::: "memory");
        else               asm volatile("cp.async.wait_group 0;" ::: "memory");
        __syncthreads();
        uint32_t bs = sb + KV_OFF + (i & 1) * STG;

        if (i == 0) {
#pragma unroll
            for (int ks = 0; ks < 8; ks++) ldsm4(sb + aoff + ks * 32, aq_all[ks]);
        }

        bool active = (k0 <= wr_max) && (k0 + 63 >= wr_min - win);
        if (active) {
            // ---- S = Q K^T (1-product) ----
            float s[8][4];
#pragma unroll
            for (int f = 0; f < 8; f++)
#pragma unroll
                for (int q = 0; q < 4; q++) s[f][q] = 0.f;
#pragma unroll
            for (int ks = 0; ks < 8; ks++) {
                uint32_t tk[4][4];
#pragma unroll
                for (int ng = 0; ng < 4; ng++)
                    ldsm4(bs + boff + ng * 16 * 272 + ks * 32, tk[ng]);
#pragma unroll
                for (int ng = 0; ng < 4; ng++) {
                    MMA_F16(s[ng * 2], aq_all[ks], tk[ng][0], tk[ng][2]);
                    MMA_F16(s[ng * 2 + 1], aq_all[ks], tk[ng][1], tk[ng][3]);
                }
            }

            // ---- online softmax (exp2 domain); fast path skips masking ----
            bool full = (k0 + 63 <= wr_min) && (k0 >= wr_max - win);
            float mx0 = -1e30f, mx1 = -1e30f;
            if (full) {
#pragma unroll
                for (int nf = 0; nf < 8; nf++) {
                    float x0 = s[nf][0] * SC2, x1 = s[nf][1] * SC2;
                    float x2 = s[nf][2] * SC2, x3 = s[nf][3] * SC2;
                    s[nf][0] = x0; s[nf][1] = x1; s[nf][2] = x2; s[nf][3] = x3;
                    mx0 = fmaxf(mx0, fmaxf(x0, x1));
                    mx1 = fmaxf(mx1, fmaxf(x2, x3));
                }
            } else {
#pragma unroll
                for (int nf = 0; nf < 8; nf++) {
                    int c0 = k0 + nf * 8 + (l & 3) * 2, c1 = c0 + 1;
                    float x0 = (c0 <= r0 && r0 - c0 <= win) ? s[nf][0] * SC2 : -1e30f;
                    float x1 = (c1 <= r0 && r0 - c1 <= win) ? s[nf][1] * SC2 : -1e30f;
                    float x2 = (c0 <= r1 && r1 - c0 <= win) ? s[nf][2] * SC2 : -1e30f;
                    float x3 = (c1 <= r1 && r1 - c1 <= win) ? s[nf][3] * SC2 : -1e30f;
                    s[nf][0] = x0; s[nf][1] = x1; s[nf][2] = x2; s[nf][3] = x3;
                    mx0 = fmaxf(mx0, fmaxf(x0, x1));
                    mx1 = fmaxf(mx1, fmaxf(x2, x3));
                }
            }
            mx0 = fmaxf(mx0, __shfl_xor_sync(0xffffffffu, mx0, 1));
            mx0 = fmaxf(mx0, __shfl_xor_sync(0xffffffffu, mx0, 2));
            mx1 = fmaxf(mx1, __shfl_xor_sync(0xffffffffu, mx1, 1));
            mx1 = fmaxf(mx1, __shfl_xor_sync(0xffffffffu, mx1, 2));
            float mn0 = fmaxf(rm0, fmaxf(mx0, -1e4f));
            float mn1 = fmaxf(rm1, fmaxf(mx1, -1e4f));
            float corr0 = ex2f(rm0 - mn0), corr1 = ex2f(rm1 - mn1);
            float ls0 = 0.f, ls1 = 0.f;
#pragma unroll
            for (int nf = 0; nf < 8; nf++) {
                float p0 = ex2f(s[nf][0] - mn0);
                float p1 = ex2f(s[nf][1] - mn0);
                float p2 = ex2f(s[nf][2] - mn1);
                float p3 = ex2f(s[nf][3] - mn1);
                s[nf][0] = p0; s[nf][1] = p1; s[nf][2] = p2; s[nf][3] = p3;
                ls0 += p0 + p1; ls1 += p2 + p3;
            }
            ls0 += __shfl_xor_sync(0xffffffffu, ls0, 1);
            ls0 += __shfl_xor_sync(0xffffffffu, ls0, 2);
            ls1 += __shfl_xor_sync(0xffffffffu, ls1, 1);
            ls1 += __shfl_xor_sync(0xffffffffu, ls1, 2);
            rl0 = rl0 * corr0 + ls0;
            rl1 = rl1 * corr1 + ls1;
            rm0 = mn0; rm1 = mn1;
#pragma unroll
            for (int f = 0; f < 16; f++) {
                o[f][0] *= corr0; o[f][1] *= corr0;
                o[f][2] *= corr1; o[f][3] *= corr1;
            }

            // ---- O += P V (1-product) ----
#pragma unroll
            for (int ks = 0; ks < 4; ks++) {
                uint32_t ph[4];
                ph[0] = packh(s[2 * ks][0], s[2 * ks][1]);
                ph[1] = packh(s[2 * ks][2], s[2 * ks][3]);
                ph[2] = packh(s[2 * ks + 1][0], s[2 * ks + 1][1]);
                ph[3] = packh(s[2 * ks + 1][2], s[2 * ks + 1][3]);
                uint32_t voff = (uint32_t)((ks * 16 + (l & 15)) * 272 + (l >> 4) * 16);
                uint32_t tv[8][4];
#pragma unroll
                for (int dg = 0; dg < 8; dg++)
                    ldsm4t(bs + KTB + voff + dg * 32, tv[dg]);
#pragma unroll
                for (int dg = 0; dg < 8; dg++) {
                    MMA_F16(o[dg * 2], ph, tv[dg][0], tv[dg][1]);
                    MMA_F16(o[dg * 2 + 1], ph, tv[dg][2], tv[dg][3]);
                }
            }
        }
        __syncthreads();
        if (i + 2 < ntile) loadKV(i & 1, k0 + 128);
    }

    float i0 = 1.f / rl0, i1 = 1.f / rl1;
    int m0r = t0 + w * 16 + (l >> 2);
#pragma unroll
    for (int f = 0; f < 16; f++) {
        int col = h * 128 + (f >> 1) * 16 + (f & 1) * 8 + (l & 3) * 2;
        size_t a0 = ((size_t)(b * T_ + m0r)) * C_ + col;
        size_t a1 = a0 + (size_t)8 * C_;
        *reinterpret_cast<__half2*>(yh + a0) = __floats2half2_rn(o[f][0] * i0, o[f][1] * i0);
        *reinterpret_cast<__half2*>(yh + a1) = __floats2half2_rn(o[f][2] * i1, o[f][3] * i1);
    }
}

// ---------------- launch ------------------------------------------------------
extern "C" void kernel_launch(void* const* d_in, const int* in_sizes, int n_in,
                              void* d_out, int out_size) {
    const float* x     = (const float*)d_in[0];
    const float* ve    = (const float*)d_in[1];
    const float* Wq    = (const float*)d_in[2];
    const float* Wk    = (const float*)d_in[3];
    const float* Wv    = (const float*)d_in[4];
    const float* Wproj = (const float*)d_in[5];
    const float* Wg    = (const float*)d_in[6];
    const float* cosp  = (const float*)d_in[7];
    const float* sinp  = (const float*)d_in[8];
    const int*   winp  = (const int*)d_in[9];
    float* out = (float*)d_out;

    void *pg, *pxh, *pyh, *pqh, *pkh, *pvh;
    void *pwqh, *pwkh, *pwvh, *pwph;
    cudaGetSymbolAddress(&pg,  g_gate);
    cudaGetSymbolAddress(&pxh, g_xh);
    cudaGetSymbolAddress(&pyh, g_yh);
    cudaGetSymbolAddress(&pqh, g_qh);
    cudaGetSymbolAddress(&pkh, g_kh);
    cudaGetSymbolAddress(&pvh, g_vh);
    cudaGetSymbolAddress(&pwqh, g_wqh); cudaGetSymbolAddress(&pwkh, g_wkh);
    cudaGetSymbolAddress(&pwvh, g_wvh); cudaGetSymbolAddress(&pwph, g_wph);

    cudaFuncSetAttribute(proj_mma, cudaFuncAttributeMaxDynamicSharedMemorySize, PROJ_SMEM);
    cudaFuncSetAttribute(outproj_mma, cudaFuncAttributeMaxDynamicSharedMemorySize, GEMM_SMEM);
    cudaFuncSetAttribute(attn_mma, cudaFuncAttributeMaxDynamicSharedMemorySize, ATT_SMEM);

    // 0) fp16 conversions + gate, one launch
    conv_kernel<<<dim3(M_*C_/1024, 6), 256>>>(
        x, Wq, Wk, Wv, Wproj, Wg,
        (__half*)pxh, (__half*)pwqh, (__half*)pwkh, (__half*)pwvh, (__half*)pwph,
        (float*)pg);

    // 1) fused q/k/v projections (1-product each)
    proj_mma<<<dim3(C_ / 128, M_ / 128, 3), 256, PROJ_SMEM>>>(
        (const __half*)pxh,
        (const __half*)pwqh, (const __half*)pwkh, (const __half*)pwvh,
        (__half*)pqh, (__half*)pkh, (__half*)pvh,
        ve, (const float*)pg, cosp, sinp);

    // 2) tensor-core attention (q-tile 64, 2 CTA/SM, Q frags in regs) -> fp16 y
    attn_mma<<<dim3(T_ / 64, H_, B_), 128, ATT_SMEM>>>(
        (const __half*)pqh, (const __half*)pkh, (const __half*)pvh,
        (__half*)pyh, winp);

    // 3) output projection (1-product)
    outproj_mma<<<dim3(C_ / 128, M_ / 128), 256, GEMM_SMEM>>>(
        (const __half*)pyh, (const __half*)pwph, out);
}

// round 17
// speedup vs baseline: 2.7318x; 1.1077x over previous
#include <cuda_runtime.h>
#include <cuda_fp16.h>
#include <math.h>
#include <stdint.h>

#define B_ 2
#define T_ 2048
#define C_ 2048
#define H_ 16
#define D_ 128
#define M_ (B_*T_)   // 4096 rows

// ---------------- scratch (device globals; no allocation allowed) -------------
__device__ float g_gate[M_*H_];
__device__ __half g_xh[M_*C_];
__device__ __half g_yh[M_*C_];
__device__ __half g_qh[M_*C_];     // [b][h][t][d] single fp16
__device__ __half g_kh[M_*C_];     // [b][h][t][d] single fp16
__device__ __half g_vh[M_*C_];     // [b][h][t][d] single fp16
__device__ __half g_wqh[C_*C_];
__device__ __half g_wkh[C_*C_];
__device__ __half g_wvh[C_*C_];
__device__ __half g_wph[C_*C_];

// ================= PTX helpers =================
__device__ __forceinline__ uint32_t smem_u32(const void* p) {
    uint32_t a;
    asm("{ .reg .u64 t; cvta.to.shared.u64 t, %1; cvt.u32.u64 %0, t; }" : "=r"(a) : "l"(p));
    return a;
}
__device__ __forceinline__ void cpasync16(uint32_t saddr, const void* gaddr) {
    asm volatile("cp.async.cg.shared.global [%0], [%1], 16;" :: "r"(saddr), "l"(gaddr) : "memory");
}
__device__ __forceinline__ void ldsm4(uint32_t addr, uint32_t* r) {
    asm volatile("ldmatrix.sync.aligned.m8n8.x4.shared.b16 {%0,%1,%2,%3}, [%4];"
                 : "=r"(r[0]), "=r"(r[1]), "=r"(r[2]), "=r"(r[3]) : "r"(addr));
}
__device__ __forceinline__ void ldsm4t(uint32_t addr, uint32_t* r) {
    asm volatile("ldmatrix.sync.aligned.m8n8.x4.trans.shared.b16 {%0,%1,%2,%3}, [%4];"
                 : "=r"(r[0]), "=r"(r[1]), "=r"(r[2]), "=r"(r[3]) : "r"(addr));
}
__device__ __forceinline__ float ex2f(float x) {
    float y; asm("ex2.approx.f32 %0, %1;" : "=f"(y) : "f"(x)); return y;
}
#define MMA_F16(Cf, Af, B0, B1)                                               \
    asm volatile("mma.sync.aligned.m16n8k16.row.col.f32.f16.f16.f32 "          \
        "{%0,%1,%2,%3},{%4,%5,%6,%7},{%8,%9},{%0,%1,%2,%3};"                   \
        : "+f"((Cf)[0]), "+f"((Cf)[1]), "+f"((Cf)[2]), "+f"((Cf)[3])           \
        : "r"((Af)[0]), "r"((Af)[1]), "r"((Af)[2]), "r"((Af)[3]),              \
          "r"(B0), "r"(B1))

__device__ __forceinline__ uint32_t packh(float a, float b) {
    __half2 h = __floats2half2_rn(a, b);
    return *reinterpret_cast<uint32_t*>(&h);
}

// ---------------- fp32 -> fp16 conversions + gate (one launch) -----------------
__global__ void conv_kernel(const float* __restrict__ x,
                            const float* __restrict__ w0, const float* __restrict__ w1,
                            const float* __restrict__ w2, const float* __restrict__ w3,
                            const float* __restrict__ Wg,
                            __half* __restrict__ xh,
                            __half* __restrict__ h0, __half* __restrict__ h1,
                            __half* __restrict__ h2, __half* __restrict__ h3,
                            float* __restrict__ gate) {
    int which = blockIdx.y;
    if (which == 5) {
        int idx = blockIdx.x * blockDim.x + threadIdx.x;
        if (idx >= M_ * H_) return;
        int m = idx >> 4, h = idx & 15;
        float s = 0.f;
#pragma unroll
        for (int j = 0; j < 12; j++) s += x[(size_t)m * C_ + j] * Wg[h * 12 + j];
        gate[idx] = 3.f / (1.f + __expf(-s));
        return;
    }
    const float* src; __half* dst; int n;
    switch (which) {
        case 0: src = x;  dst = xh; n = M_*C_; break;
        case 1: src = w0; dst = h0; n = C_*C_; break;
        case 2: src = w1; dst = h1; n = C_*C_; break;
        case 3: src = w2; dst = h2; n = C_*C_; break;
        default: src = w3; dst = h3; n = C_*C_; break;
    }
    int i = (blockIdx.x * blockDim.x + threadIdx.x) * 4;
    if (i >= n) return;
    float4 v = *(const float4*)(src + i);
    ((__half2*)(dst + i))[0] = __floats2half2_rn(v.x, v.y);
    ((__half2*)(dst + i))[1] = __floats2half2_rn(v.z, v.w);
}

// ---------------- 1-product fp16 GEMM cores ------------------------------------
#define RS_B 80
#define ARR_B (128 * RS_B)               // 10240
#define BRR_B (64 * RS_B)                // 5120
#define NSTAGE 3
#define NCHUNK 64
#define STGB (2 * ARR_B)                 // BN=128 stage: Ah | Bh
#define GEMM_SMEM (NSTAGE * STGB)        // 61440
#define PROJ_SMEM (128 * 132 * 4)        // 67584 — rope epilogue staging
#define STGB64 (ARR_B + BRR_B)           // 15360
#define GEMM64_SMEM (NSTAGE * STGB64)    // 46080

struct Frag {
    uint32_t a_h[2][4];
    uint32_t b_h[8][2];
};
struct Frag64 {
    uint32_t a_h[2][4];
    uint32_t b_h[4][2];
};

// ---- BN=128 core (q/k proj) ----
__device__ __forceinline__ void gemm_core(
    uint32_t sb, int tid, int wid, int lane,
    const __half* Ah, const __half* Bh, int arow0, int brow0,
    float (&acc)[2][8][4]) {
    const int warp_m = wid & 3, warp_n = wid >> 2;

    auto load_chunk = [&](int stage, int chunk) {
        const int k0 = chunk * 32;
        uint32_t stg = sb + stage * STGB;
#pragma unroll
        for (int j = 0; j < 4; j++) {
            int u = tid + j * 256;
            int arr = u >> 9;
            int rc = u & 511;
            int r = rc >> 2, c = rc & 3;
            uint32_t sa = stg + arr * ARR_B + r * RS_B + c * 16;
            const __half* src = arr ? Bh : Ah;
            int row = arr ? (brow0 + r) : (arow0 + r);
            cpasync16(sa, src + (size_t)row * C_ + k0 + c * 8);
        }
        asm volatile("cp.async.commit_group;" ::: "memory");
    };

    const uint32_t a_lane_off = (uint32_t)((warp_m * 32 + (lane & 15)) * RS_B + (lane >> 4) * 16);
    const uint32_t b_lane_off = (uint32_t)((warp_n * 64 + (lane & 15)) * RS_B + (lane >> 4) * 16);

    auto ldfr = [&](Frag& F, uint32_t stg, uint32_t koff) {
#pragma unroll
        for (int mi = 0; mi < 2; mi++)
            ldsm4(stg + a_lane_off + mi * 16 * RS_B + koff, F.a_h[mi]);
#pragma unroll
        for (int nf4 = 0; nf4 < 4; nf4++) {
            uint32_t t[4];
            ldsm4(stg + ARR_B + b_lane_off + nf4 * 16 * RS_B + koff, t);
            F.b_h[nf4 * 2][0] = t[0]; F.b_h[nf4 * 2][1] = t[2];
            F.b_h[nf4 * 2 + 1][0] = t[1]; F.b_h[nf4 * 2 + 1][1] = t[3];
        }
    };

    auto mmab = [&](Frag& F) {
#pragma unroll
        for (int mi = 0; mi < 2; mi++)
#pragma unroll
            for (int nf = 0; nf < 8; nf++) MMA_F16(acc[mi][nf], F.a_h[mi], F.b_h[nf][0], F.b_h[nf][1]);
    };

    load_chunk(0, 0);
    load_chunk(1, 1);
    load_chunk(2, 2);
    asm volatile("cp.async.wait_group 2;" ::: "memory");
    __syncthreads();

    Frag Fa, Fb;
    ldfr(Fa, sb, 0);

    for (int i = 0; i < NCHUNK; i++) {
        uint32_t stg = sb + (i % NSTAGE) * STGB;
        ldfr(Fb, stg, 32);
        mmab(Fa);
        if (i < NCHUNK - 1) {
            if (i < NCHUNK - 2) asm volatile("cp.async.wait_group 1;" ::: "memory");
            else                asm volatile("cp.async.wait_group 0;" ::: "memory");
            __syncthreads();
            uint32_t stg2 = sb + ((i + 1) % NSTAGE) * STGB;
            ldfr(Fa, stg2, 0);
            if (i + 3 < NCHUNK) load_chunk(i % NSTAGE, i + 3);
        }
        mmab(Fb);
    }
}

// ---- BN=64 core (v proj + out proj), occ 2 ----
__device__ __forceinline__ void gemm_core64(
    uint32_t sb, int tid, int wid, int lane,
    const __half* Ah, const __half* Bh, int arow0, int brow0,
    float (&acc)[2][4][4]) {
    const int warp_m = wid & 3, warp_n = wid >> 2;

    auto load_chunk = [&](int stage, int chunk) {
        const int k0 = chunk * 32;
        uint32_t stg = sb + stage * STGB64;
#pragma unroll
        for (int j = 0; j < 3; j++) {
            int u = tid + j * 256;           // 0..767
            if (u < 512) {
                int r = u >> 2, c = u & 3;
                cpasync16(stg + r * RS_B + c * 16,
                          Ah + (size_t)(arow0 + r) * C_ + k0 + c * 8);
            } else {
                int v = u - 512;
                int r = v >> 2, c = v & 3;
                cpasync16(stg + ARR_B + r * RS_B + c * 16,
                          Bh + (size_t)(brow0 + r) * C_ + k0 + c * 8);
            }
        }
        asm volatile("cp.async.commit_group;" ::: "memory");
    };

    const uint32_t a_lane_off = (uint32_t)((warp_m * 32 + (lane & 15)) * RS_B + (lane >> 4) * 16);
    const uint32_t b_lane_off = (uint32_t)((warp_n * 32 + (lane & 15)) * RS_B + (lane >> 4) * 16);

    auto ldfr = [&](Frag64& F, uint32_t stg, uint32_t koff) {
#pragma unroll
        for (int mi = 0; mi < 2; mi++)
            ldsm4(stg + a_lane_off + mi * 16 * RS_B + koff, F.a_h[mi]);
#pragma unroll
        for (int nf4 = 0; nf4 < 2; nf4++) {
            uint32_t t[4];
            ldsm4(stg + ARR_B + b_lane_off + nf4 * 16 * RS_B + koff, t);
            F.b_h[nf4 * 2][0] = t[0]; F.b_h[nf4 * 2][1] = t[2];
            F.b_h[nf4 * 2 + 1][0] = t[1]; F.b_h[nf4 * 2 + 1][1] = t[3];
        }
    };

    auto mmab = [&](Frag64& F) {
#pragma unroll
        for (int mi = 0; mi < 2; mi++)
#pragma unroll
            for (int nf = 0; nf < 4; nf++) MMA_F16(acc[mi][nf], F.a_h[mi], F.b_h[nf][0], F.b_h[nf][1]);
    };

    load_chunk(0, 0);
    load_chunk(1, 1);
    load_chunk(2, 2);
    asm volatile("cp.async.wait_group 2;" ::: "memory");
    __syncthreads();

    Frag64 Fa, Fb;
    ldfr(Fa, sb, 0);

    for (int i = 0; i < NCHUNK; i++) {
        uint32_t stg = sb + (i % NSTAGE) * STGB64;
        ldfr(Fb, stg, 32);
        mmab(Fa);
        if (i < NCHUNK - 1) {
            if (i < NCHUNK - 2) asm volatile("cp.async.wait_group 1;" ::: "memory");
            else                asm volatile("cp.async.wait_group 0;" ::: "memory");
            __syncthreads();
            uint32_t stg2 = sb + ((i + 1) % NSTAGE) * STGB64;
            ldfr(Fa, stg2, 0);
            if (i + 3 < NCHUNK) load_chunk(i % NSTAGE, i + 3);
        }
        mmab(Fb);
    }
}

// fused q/k projection: blockIdx.z in {0,1}, rope+rms epilogue
__global__ __launch_bounds__(256, 1) void proj_mma(
    const __half* __restrict__ xh,
    const __half* __restrict__ Wq, const __half* __restrict__ Wk,
    __half* __restrict__ qh, __half* __restrict__ kh,
    const float* __restrict__ cosp, const float* __restrict__ sinp) {
    extern __shared__ char smc[];
    const uint32_t sb = smem_u32(smc);
    const int tid = threadIdx.x;
    const int wid = tid >> 5, lane = tid & 31;
    const int warp_m = wid & 3, warp_n = wid >> 2;
    const int arow0 = blockIdx.y * 128, brow0 = blockIdx.x * 128;
    const int z = blockIdx.z;
    const __half* Bh = (z == 0) ? Wq : Wk;

    float acc[2][8][4];
#pragma unroll
    for (int mi = 0; mi < 2; mi++)
#pragma unroll
        for (int nf = 0; nf < 8; nf++)
#pragma unroll
            for (int q = 0; q < 4; q++) acc[mi][nf][q] = 0.f;

    gemm_core(sb, tid, wid, lane, xh, Bh, arow0, brow0, acc);

    __half* Oh = (z == 0) ? qh : kh;
    __syncthreads();
    float* S = (float*)smc;
    const int rbase = warp_m * 32 + (lane >> 2);
    const int cbase = warp_n * 64 + (lane & 3) * 2;
#pragma unroll
    for (int mi = 0; mi < 2; mi++)
#pragma unroll
        for (int nf = 0; nf < 8; nf++) {
            int r = rbase + mi * 16, c = cbase + nf * 8;
            S[r * 132 + c] = acc[mi][nf][0];
            S[r * 132 + c + 1] = acc[mi][nf][1];
            S[(r + 8) * 132 + c] = acc[mi][nf][2];
            S[(r + 8) * 132 + c + 1] = acc[mi][nf][3];
        }
    __syncthreads();
    const int hh = brow0 >> 7;
    const int d0 = lane * 2;
#pragma unroll 4
    for (int rr = wid * 16; rr < wid * 16 + 16; rr++) {
        int m = arow0 + rr, b = m >> 11, t = m & 2047;
        float xa0 = S[rr * 132 + d0],      xa1 = S[rr * 132 + d0 + 1];
        float xb0 = S[rr * 132 + d0 + 64], xb1 = S[rr * 132 + d0 + 65];
        float2 cc = *(const float2*)(cosp + t * 64 + d0);
        float2 sn = *(const float2*)(sinp + t * 64 + d0);
        float y1a = xa0 * cc.x + xb0 * sn.x;
        float y1b = xa1 * cc.y + xb1 * sn.y;
        float y2a = xb0 * cc.x - xa0 * sn.x;
        float y2b = xb1 * cc.y - xa1 * sn.y;
        float ss = y1a * y1a + y1b * y1b + y2a * y2a + y2b * y2b;
#pragma unroll
        for (int off = 16; off; off >>= 1) ss += __shfl_xor_sync(0xffffffffu, ss, off);
        float r = rsqrtf(ss * (1.f / 128.f) + 1e-6f) * 1.2f;
        size_t ob = ((size_t)(b * H_ + hh) * T_ + t) * D_;
        *reinterpret_cast<__half2*>(Oh + ob + d0) = __floats2half2_rn(y1a * r, y1b * r);
        *reinterpret_cast<__half2*>(Oh + ob + d0 + 64) = __floats2half2_rn(y2a * r, y2b * r);
    }
}

// v projection: BN=64, occ 2, gate+ve epilogue -> fp16 [b][h][t][d]
__global__ __launch_bounds__(256, 2) void vproj_mma(
    const __half* __restrict__ xh, const __half* __restrict__ Wv,
    __half* __restrict__ vh,
    const float* __restrict__ ve, const float* __restrict__ gate) {
    extern __shared__ char smc[];
    const uint32_t sb = smem_u32(smc);
    const int tid = threadIdx.x;
    const int wid = tid >> 5, lane = tid & 31;
    const int warp_m = wid & 3, warp_n = wid >> 2;
    const int arow0 = blockIdx.y * 128, brow0 = blockIdx.x * 64;

    float acc[2][4][4];
#pragma unroll
    for (int mi = 0; mi < 2; mi++)
#pragma unroll
        for (int nf = 0; nf < 4; nf++)
#pragma unroll
            for (int q = 0; q < 4; q++) acc[mi][nf][q] = 0.f;

    gemm_core64(sb, tid, wid, lane, xh, Wv, arow0, brow0, acc);

    const int r0w = arow0 + warp_m * 32 + (lane >> 2);
    const int c0w = brow0 + warp_n * 32 + (lane & 3) * 2;
#pragma unroll
    for (int mi = 0; mi < 2; mi++) {
#pragma unroll
        for (int nf = 0; nf < 4; nf++) {
            int n = c0w + nf * 8;
            int m0 = r0w + mi * 16;
            int m1 = m0 + 8;
            float v0 = acc[mi][nf][0], v1 = acc[mi][nf][1];
            float v2 = acc[mi][nf][2], v3 = acc[mi][nf][3];
            float g0 = gate[m0 * H_ + (n >> 7)];
            float g1 = gate[m1 * H_ + (n >> 7)];
            const float* ve0 = ve + (size_t)m0 * C_ + n;
            const float* ve1 = ve + (size_t)m1 * C_ + n;
            v0 += g0 * ve0[0]; v1 += g0 * ve0[1];
            v2 += g1 * ve1[0]; v3 += g1 * ve1[1];
            int hh = n >> 7, dd = n & 127;
            size_t o0 = ((size_t)((m0 >> 11) * H_ + hh) * T_ + (m0 & 2047)) * D_ + dd;
            size_t o1 = ((size_t)((m1 >> 11) * H_ + hh) * T_ + (m1 & 2047)) * D_ + dd;
            *reinterpret_cast<__half2*>(vh + o0) = __floats2half2_rn(v0, v1);
            *reinterpret_cast<__half2*>(vh + o1) = __floats2half2_rn(v2, v3);
        }
    }
}

// output projection: BN=64, occ 2, fp32 out
__global__ __launch_bounds__(256, 2) void outproj_mma(
    const __half* __restrict__ yh, const __half* __restrict__ Wp,
    float* __restrict__ out) {
    extern __shared__ char smc[];
    const uint32_t sb = smem_u32(smc);
    const int tid = threadIdx.x;
    const int wid = tid >> 5, lane = tid & 31;
    const int warp_m = wid & 3, warp_n = wid >> 2;
    const int arow0 = blockIdx.y * 128, brow0 = blockIdx.x * 64;

    float acc[2][4][4];
#pragma unroll
    for (int mi = 0; mi < 2; mi++)
#pragma unroll
        for (int nf = 0; nf < 4; nf++)
#pragma unroll
            for (int q = 0; q < 4; q++) acc[mi][nf][q] = 0.f;

    gemm_core64(sb, tid, wid, lane, yh, Wp, arow0, brow0, acc);

    const int r0w = arow0 + warp_m * 32 + (lane >> 2);
    const int c0w = brow0 + warp_n * 32 + (lane & 3) * 2;
#pragma unroll
    for (int mi = 0; mi < 2; mi++) {
#pragma unroll
        for (int nf = 0; nf < 4; nf++) {
            int n = c0w + nf * 8;
            int m0 = r0w + mi * 16;
            int m1 = m0 + 8;
            *(float2*)(out + (size_t)m0 * C_ + n) = make_float2(acc[mi][nf][0], acc[mi][nf][1]);
            *(float2*)(out + (size_t)m1 * C_ + n) = make_float2(acc[mi][nf][2], acc[mi][nf][3]);
        }
    }
}

// ---------------- tensor-core flash attention (single fp16) -------------------
// 128 threads (4 warps), q-tile 64 rows, KV tile 64, 2 stages (Kh|Vh).
// 2 CTAs/SM; Q fragments hoisted; fast-path softmax on full tiles.
#define QTB (64 * 272)               // 17408
#define KTB (64 * 272)               // 17408
#define KV_OFF QTB                   // 17408
#define STG (2 * KTB)                // 34816
#define ATT_SMEM (QTB + 2 * STG)     // 87040

__global__ __launch_bounds__(128, 2) void attn_mma(
    const __half* __restrict__ qh, const __half* __restrict__ kh,
    const __half* __restrict__ vh,
    __half* __restrict__ yh,
    const int* __restrict__ winp) {
    extern __shared__ char smc[];
    const uint32_t sb = smem_u32(smc);
    const int tid = threadIdx.x, w = tid >> 5, l = tid & 31;
    const int t0 = blockIdx.x * 64, h = blockIdx.y, b = blockIdx.z;
    int win = *winp;
    if (win <= 0 || win >= T_) win = T_;
    const size_t hb = (size_t)(b * H_ + h) * ((size_t)T_ * D_);

#pragma unroll
    for (int j = 0; j < 8; j++) {
        int u = tid + j * 128;
        int r = u >> 4, c = u & 15;
        uint32_t so = (uint32_t)(r * 272 + c * 16);
        cpasync16(sb + so, qh + hb + (size_t)(t0 + r) * D_ + c * 8);
    }
    asm volatile("cp.async.commit_group;" ::: "memory");

    int start = t0 - win;
    if (start < 0) start = 0;
    start &= ~63;
    const int ntile = ((t0 - start) >> 6) + 1;

    auto loadKV = [&](int stg, int k0) {
        uint32_t bs = sb + KV_OFF + stg * STG;
#pragma unroll
        for (int j = 0; j < 16; j++) {
            int u = tid + j * 128;
            int arr = u >> 10;
            int rc = u & 1023;
            int r = rc >> 4, c = rc & 15;
            uint32_t so = (uint32_t)(arr * KTB + r * 272 + c * 16);
            const __half* src = arr ? vh : kh;
            cpasync16(bs + so, src + hb + (size_t)(k0 + r) * D_ + c * 8);
        }
        asm volatile("cp.async.commit_group;" ::: "memory");
    };
    loadKV(0, start);
    if (ntile > 1) loadKV(1, start + 64);

    float o[16][4];
#pragma unroll
    for (int f = 0; f < 16; f++)
#pragma unroll
        for (int q = 0; q < 4; q++) o[f][q] = 0.f;
    float rm0 = -1e4f, rm1 = -1e4f, rl0 = 0.f, rl1 = 0.f;
    const float SC2 = 0.1275187989f;   // 1/sqrt(128) * log2(e)

    const uint32_t aoff = (uint32_t)((w * 16 + (l & 15)) * 272 + (l >> 4) * 16);
    const uint32_t boff = (uint32_t)((l & 15) * 272 + (l >> 4) * 16);
    const int r0 = t0 + w * 16 + (l >> 2), r1 = r0 + 8;
    const int wr_min = t0 + w * 16, wr_max = t0 + w * 16 + 15;

    uint32_t aq_all[8][4];

    for (int i = 0; i < ntile; i++) {
        int k0 = start + i * 64;
        if (i + 1 < ntile) asm volatile("cp.async.wait_group 1;" ::: "memory");
        else               asm volatile("cp.async.wait_group 0;" ::: "memory");
        __syncthreads();
        uint32_t bs = sb + KV_OFF + (i & 1) * STG;

        if (i == 0) {
#pragma unroll
            for (int ks = 0; ks < 8; ks++) ldsm4(sb + aoff + ks * 32, aq_all[ks]);
        }

        bool active = (k0 <= wr_max) && (k0 + 63 >= wr_min - win);
        if (active) {
            float s[8][4];
#pragma unroll
            for (int f = 0; f < 8; f++)
#pragma unroll
                for (int q = 0; q < 4; q++) s[f][q] = 0.f;
#pragma unroll
            for (int ks = 0; ks < 8; ks++) {
                uint32_t tk[4][4];
#pragma unroll
                for (int ng = 0; ng < 4; ng++)
                    ldsm4(bs + boff + ng * 16 * 272 + ks * 32, tk[ng]);
#pragma unroll
                for (int ng = 0; ng < 4; ng++) {
                    MMA_F16(s[ng * 2], aq_all[ks], tk[ng][0], tk[ng][2]);
                    MMA_F16(s[ng * 2 + 1], aq_all[ks], tk[ng][1], tk[ng][3]);
                }
            }

            bool full = (k0 + 63 <= wr_min) && (k0 >= wr_max - win);
            float mx0 = -1e30f, mx1 = -1e30f;
            if (full) {
#pragma unroll
                for (int nf = 0; nf < 8; nf++) {
                    float x0 = s[nf][0] * SC2, x1 = s[nf][1] * SC2;
                    float x2 = s[nf][2] * SC2, x3 = s[nf][3] * SC2;
                    s[nf][0] = x0; s[nf][1] = x1; s[nf][2] = x2; s[nf][3] = x3;
                    mx0 = fmaxf(mx0, fmaxf(x0, x1));
                    mx1 = fmaxf(mx1, fmaxf(x2, x3));
                }
            } else {
#pragma unroll
                for (int nf = 0; nf < 8; nf++) {
                    int c0 = k0 + nf * 8 + (l & 3) * 2, c1 = c0 + 1;
                    float x0 = (c0 <= r0 && r0 - c0 <= win) ? s[nf][0] * SC2 : -1e30f;
                    float x1 = (c1 <= r0 && r0 - c1 <= win) ? s[nf][1] * SC2 : -1e30f;
                    float x2 = (c0 <= r1 && r1 - c0 <= win) ? s[nf][2] * SC2 : -1e30f;
                    float x3 = (c1 <= r1 && r1 - c1 <= win) ? s[nf][3] * SC2 : -1e30f;
                    s[nf][0] = x0; s[nf][1] = x1; s[nf][2] = x2; s[nf][3] = x3;
                    mx0 = fmaxf(mx0, fmaxf(x0, x1));
                    mx1 = fmaxf(mx1, fmaxf(x2, x3));
                }
            }
            mx0 = fmaxf(mx0, __shfl_xor_sync(0xffffffffu, mx0, 1));
            mx0 = fmaxf(mx0, __shfl_xor_sync(0xffffffffu, mx0, 2));
            mx1 = fmaxf(mx1, __shfl_xor_sync(0xffffffffu, mx1, 1));
            mx1 = fmaxf(mx1, __shfl_xor_sync(0xffffffffu, mx1, 2));
            float mn0 = fmaxf(rm0, fmaxf(mx0, -1e4f));
            float mn1 = fmaxf(rm1, fmaxf(mx1, -1e4f));
            float corr0 = ex2f(rm0 - mn0), corr1 = ex2f(rm1 - mn1);
            float ls0 = 0.f, ls1 = 0.f;
#pragma unroll
            for (int nf = 0; nf < 8; nf++) {
                float p0 = ex2f(s[nf][0] - mn0);
                float p1 = ex2f(s[nf][1] - mn0);
                float p2 = ex2f(s[nf][2] - mn1);
                float p3 = ex2f(s[nf][3] - mn1);
                s[nf][0] = p0; s[nf][1] = p1; s[nf][2] = p2; s[nf][3] = p3;
                ls0 += p0 + p1; ls1 += p2 + p3;
            }
            ls0 += __shfl_xor_sync(0xffffffffu, ls0, 1);
            ls0 += __shfl_xor_sync(0xffffffffu, ls0, 2);
            ls1 += __shfl_xor_sync(0xffffffffu, ls1, 1);
            ls1 += __shfl_xor_sync(0xffffffffu, ls1, 2);
            rl0 = rl0 * corr0 + ls0;
            rl1 = rl1 * corr1 + ls1;
            rm0 = mn0; rm1 = mn1;
#pragma unroll
            for (int f = 0; f < 16; f++) {
                o[f][0] *= corr0; o[f][1] *= corr0;
                o[f][2] *= corr1; o[f][3] *= corr1;
            }

#pragma unroll
            for (int ks = 0; ks < 4; ks++) {
                uint32_t ph[4];
                ph[0] = packh(s[2 * ks][0], s[2 * ks][1]);
                ph[1] = packh(s[2 * ks][2], s[2 * ks][3]);
                ph[2] = packh(s[2 * ks + 1][0], s[2 * ks + 1][1]);
                ph[3] = packh(s[2 * ks + 1][2], s[2 * ks + 1][3]);
                uint32_t voff = (uint32_t)((ks * 16 + (l & 15)) * 272 + (l >> 4) * 16);
                uint32_t tv[8][4];
#pragma unroll
                for (int dg = 0; dg < 8; dg++)
                    ldsm4t(bs + KTB + voff + dg * 32, tv[dg]);
#pragma unroll
                for (int dg = 0; dg < 8; dg++) {
                    MMA_F16(o[dg * 2], ph, tv[dg][0], tv[dg][1]);
                    MMA_F16(o[dg * 2 + 1], ph, tv[dg][2], tv[dg][3]);
                }
            }
        }
        __syncthreads();
        if (i + 2 < ntile) loadKV(i & 1, k0 + 128);
    }

    float i0 = 1.f / rl0, i1 = 1.f / rl1;
    int m0r = t0 + w * 16 + (l >> 2);
#pragma unroll
    for (int f = 0; f < 16; f++) {
        int col = h * 128 + (f >> 1) * 16 + (f & 1) * 8 + (l & 3) * 2;
        size_t a0 = ((size_t)(b * T_ + m0r)) * C_ + col;
        size_t a1 = a0 + (size_t)8 * C_;
        *reinterpret_cast<__half2*>(yh + a0) = __floats2half2_rn(o[f][0] * i0, o[f][1] * i0);
        *reinterpret_cast<__half2*>(yh + a1) = __floats2half2_rn(o[f][2] * i1, o[f][3] * i1);
    }
}

// ---------------- launch ------------------------------------------------------
extern "C" void kernel_launch(void* const* d_in, const int* in_sizes, int n_in,
                              void* d_out, int out_size) {
    const float* x     = (const float*)d_in[0];
    const float* ve    = (const float*)d_in[1];
    const float* Wq    = (const float*)d_in[2];
    const float* Wk    = (const float*)d_in[3];
    const float* Wv    = (const float*)d_in[4];
    const float* Wproj = (const float*)d_in[5];
    const float* Wg    = (const float*)d_in[6];
    const float* cosp  = (const float*)d_in[7];
    const float* sinp  = (const float*)d_in[8];
    const int*   winp  = (const int*)d_in[9];
    float* out = (float*)d_out;

    void *pg, *pxh, *pyh, *pqh, *pkh, *pvh;
    void *pwqh, *pwkh, *pwvh, *pwph;
    cudaGetSymbolAddress(&pg,  g_gate);
    cudaGetSymbolAddress(&pxh, g_xh);
    cudaGetSymbolAddress(&pyh, g_yh);
    cudaGetSymbolAddress(&pqh, g_qh);
    cudaGetSymbolAddress(&pkh, g_kh);
    cudaGetSymbolAddress(&pvh, g_vh);
    cudaGetSymbolAddress(&pwqh, g_wqh); cudaGetSymbolAddress(&pwkh, g_wkh);
    cudaGetSymbolAddress(&pwvh, g_wvh); cudaGetSymbolAddress(&pwph, g_wph);

    cudaFuncSetAttribute(proj_mma, cudaFuncAttributeMaxDynamicSharedMemorySize, PROJ_SMEM);
    cudaFuncSetAttribute(vproj_mma, cudaFuncAttributeMaxDynamicSharedMemorySize, GEMM64_SMEM);
    cudaFuncSetAttribute(outproj_mma, cudaFuncAttributeMaxDynamicSharedMemorySize, GEMM64_SMEM);
    cudaFuncSetAttribute(attn_mma, cudaFuncAttributeMaxDynamicSharedMemorySize, ATT_SMEM);

    // 0) fp16 conversions + gate, one launch
    conv_kernel<<<dim3(M_*C_/1024, 6), 256>>>(
        x, Wq, Wk, Wv, Wproj, Wg,
        (__half*)pxh, (__half*)pwqh, (__half*)pwkh, (__half*)pwvh, (__half*)pwph,
        (float*)pg);

    // 1) q/k projections (BN=128, rope fused) + v projection (BN=64, occ 2)
    proj_mma<<<dim3(C_ / 128, M_ / 128, 2), 256, PROJ_SMEM>>>(
        (const __half*)pxh, (const __half*)pwqh, (const __half*)pwkh,
        (__half*)pqh, (__half*)pkh, cosp, sinp);
    vproj_mma<<<dim3(C_ / 64, M_ / 128), 256, GEMM64_SMEM>>>(
        (const __half*)pxh, (const __half*)pwvh, (__half*)pvh,
        ve, (const float*)pg);

    // 2) tensor-core attention -> fp16 y
    attn_mma<<<dim3(T_ / 64, H_, B_), 128, ATT_SMEM>>>(
        (const __half*)pqh, (const __half*)pkh, (const __half*)pvh,
        (__half*)pyh, winp);

    // 3) output projection (BN=64, occ 2)
    outproj_mma<<<dim3(C_ / 64, M_ / 128), 256, GEMM64_SMEM>>>(
        (const __half*)pyh, (const __half*)pwph, out);
}